// round 1
// baseline (speedup 1.0000x reference)
#include <cuda_runtime.h>
#include <math.h>

#define BB   2
#define SS   768
#define DDIM 1024
#define HH   16
#define HDIM 64
#define NQh  8
#define NF   16          // 2*NQ feature width
#define BHn  (BB*HH)     // 32
#define MM   (BB*SS)     // 1536

// ---------------- scratch (static device globals: no allocs) ----------------
__device__ float g_Q[BHn*SS*HDIM];      // [B,H,S,HD]
__device__ float g_K[BHn*SS*HDIM];
__device__ float g_V[BHn*SS*HDIM];
__device__ float g_fQ[BHn*SS*NF];       // quantum features for Q side
__device__ float g_fK[BHn*SS*NF];       // quantum features for K side
__device__ float g_sc[(size_t)BHn*SS*SS]; // scores -> attn (in place), 75.5MB
__device__ float g_att[MM*DDIM];        // attended, [B,S,D]

// ---------------- fused QKV projection: X @ W + b, scatter to [B,H,S,HD] ----
__global__ void proj_kernel(const float* __restrict__ q,
                            const float* __restrict__ k,
                            const float* __restrict__ v,
                            const float* __restrict__ Wq, const float* __restrict__ bq,
                            const float* __restrict__ Wk, const float* __restrict__ bk,
                            const float* __restrict__ Wv, const float* __restrict__ bv) {
    int which = blockIdx.z;
    const float* A    = (which == 0) ? q  : (which == 1) ? k  : v;
    const float* W    = (which == 0) ? Wq : (which == 1) ? Wk : Wv;
    const float* bias = (which == 0) ? bq : (which == 1) ? bk : bv;
    float*       out  = (which == 0) ? g_Q : (which == 1) ? g_K : g_V;

    __shared__ float As[64][16];
    __shared__ float Bs[16][65];
    int tx = threadIdx.x, ty = threadIdx.y;
    int t  = ty * 16 + tx;
    int row0 = blockIdx.y * 64, col0 = blockIdx.x * 64;
    float acc[4][4] = {};

    for (int k0 = 0; k0 < DDIM; k0 += 16) {
        #pragma unroll
        for (int u = 0; u < 4; u++) {
            int f = t + 256 * u;
            As[f >> 4][f & 15] = A[(row0 + (f >> 4)) * DDIM + k0 + (f & 15)];
        }
        #pragma unroll
        for (int u = 0; u < 4; u++) {
            int f = t + 256 * u;
            Bs[f >> 6][f & 63] = W[(k0 + (f >> 6)) * DDIM + col0 + (f & 63)];
        }
        __syncthreads();
        #pragma unroll
        for (int kk = 0; kk < 16; kk++) {
            float a[4], b[4];
            #pragma unroll
            for (int i = 0; i < 4; i++) a[i] = As[ty * 4 + i][kk];
            #pragma unroll
            for (int j = 0; j < 4; j++) b[j] = Bs[kk][tx * 4 + j];
            #pragma unroll
            for (int i = 0; i < 4; i++)
                #pragma unroll
                for (int j = 0; j < 4; j++)
                    acc[i][j] += a[i] * b[j];
        }
        __syncthreads();
    }
    #pragma unroll
    for (int i = 0; i < 4; i++) {
        int m = row0 + ty * 4 + i;
        int b = m / SS, s = m % SS;
        #pragma unroll
        for (int j = 0; j < 4; j++) {
            int n = col0 + tx * 4 + j;
            int h = n >> 6, d = n & 63;
            out[((b * HH + h) * SS + s) * HDIM + d] = acc[i][j] + bias[n];
        }
    }
}

// ---------------- quantum features ------------------------------------------
// side 0 (Q): Fq[n]    = sig(qw)/NQ * cos(tanh(Q.qmapW+b)+phase)
//             Fq[NQ+n] = sig(qw)/NQ * sin(tanh(Q.qmapW+b)+phase)
// side 1 (K): Fk[n]    = cos(tanh(K.qmapW+b)),  Fk[NQ+n] = sin(...)
__global__ void qfeat_kernel(const float* __restrict__ qmapW,
                             const float* __restrict__ qmapb,
                             const float* __restrict__ qw,
                             const float* __restrict__ ph) {
    int idx = blockIdx.x * blockDim.x + threadIdx.x;
    if (idx >= 2 * BHn * SS) return;
    int side = idx / (BHn * SS);
    int r    = idx % (BHn * SS);
    int h    = (r / SS) % HH;
    const float* row  = ((side == 0) ? g_Q : g_K) + r * HDIM;
    float*       feat = ((side == 0) ? g_fQ : g_fK) + r * NF;

    float rv[HDIM];
    #pragma unroll
    for (int d = 0; d < HDIM; d++) rv[d] = row[d];

    #pragma unroll
    for (int n = 0; n < NQh; n++) {
        float acc = qmapb[n];
        #pragma unroll
        for (int d = 0; d < HDIM; d++) acc += rv[d] * qmapW[d * NQh + n];
        float a = tanhf(acc);
        float s, c;
        if (side == 0) {
            float w = (1.0f / (1.0f + expf(-qw[h * NQh + n]))) * (1.0f / NQh);
            sincosf(a + ph[h * NQh + n], &s, &c);
            feat[n]       = w * c;
            feat[NQh + n] = w * s;
        } else {
            sincosf(a, &s, &c);
            feat[n]       = c;
            feat[NQh + n] = s;
        }
    }
}

// ---------------- scores: (1-mix)*QK^T/8 + mix*ent*(Fq Fk^T) ----------------
__global__ void scores_kernel(const float* __restrict__ es_ptr) {
    int bh = blockIdx.z;
    const float* Qp = g_Q  + bh * SS * HDIM;
    const float* Kp = g_K  + bh * SS * HDIM;
    const float* Fq = g_fQ + bh * SS * NF;
    const float* Fk = g_fK + bh * SS * NF;
    float* out = g_sc + (size_t)bh * SS * SS;

    __shared__ float As[64][17];
    __shared__ float Bs[64][17];
    int tx = threadIdx.x, ty = threadIdx.y;
    int t  = ty * 16 + tx;
    int i0 = blockIdx.y * 64, j0 = blockIdx.x * 64;
    float acc1[4][4] = {}, acc2[4][4] = {};

    for (int k0 = 0; k0 < HDIM; k0 += 16) {             // classical, 64-dim
        #pragma unroll
        for (int u = 0; u < 4; u++) {
            int f = t + 256 * u; int r = f >> 4, c = f & 15;
            As[r][c] = Qp[(i0 + r) * HDIM + k0 + c];
            Bs[r][c] = Kp[(j0 + r) * HDIM + k0 + c];
        }
        __syncthreads();
        #pragma unroll
        for (int kk = 0; kk < 16; kk++) {
            float a[4], b[4];
            #pragma unroll
            for (int i = 0; i < 4; i++) a[i] = As[ty * 4 + i][kk];
            #pragma unroll
            for (int j = 0; j < 4; j++) b[j] = Bs[tx * 4 + j][kk];
            #pragma unroll
            for (int i = 0; i < 4; i++)
                #pragma unroll
                for (int j = 0; j < 4; j++)
                    acc1[i][j] += a[i] * b[j];
        }
        __syncthreads();
    }
    {                                                    // quantum, 16-dim
        #pragma unroll
        for (int u = 0; u < 4; u++) {
            int f = t + 256 * u; int r = f >> 4, c = f & 15;
            As[r][c] = Fq[(i0 + r) * NF + c];
            Bs[r][c] = Fk[(j0 + r) * NF + c];
        }
        __syncthreads();
        #pragma unroll
        for (int kk = 0; kk < 16; kk++) {
            float a[4], b[4];
            #pragma unroll
            for (int i = 0; i < 4; i++) a[i] = As[ty * 4 + i][kk];
            #pragma unroll
            for (int j = 0; j < 4; j++) b[j] = Bs[tx * 4 + j][kk];
            #pragma unroll
            for (int i = 0; i < 4; i++)
                #pragma unroll
                for (int j = 0; j < 4; j++)
                    acc2[i][j] += a[i] * b[j];
        }
        __syncthreads();
    }
    float es  = *es_ptr;
    float mix = 1.0f / (1.0f + expf(-es));
    float ca  = (1.0f - mix) * 0.125f;                   // 1/sqrt(64)
    #pragma unroll
    for (int i = 0; i < 4; i++) {
        int gi = i0 + ty * 4 + i;
        #pragma unroll
        for (int j = 0; j < 4; j++) {
            int gj = j0 + tx * 4 + j;
            float ent = expf(-0.1f * fabsf((float)(gi - gj)));
            out[gi * SS + gj] = ca * acc1[i][j] + mix * ent * acc2[i][j];
        }
    }
}

// ---------------- row softmax (in place) ------------------------------------
__global__ void softmax_kernel() {
    int row = blockIdx.x;
    float* p = g_sc + (size_t)row * SS;
    __shared__ float red[256];
    int t = threadIdx.x;
    float v[3];
    float m = -1e30f;
    #pragma unroll
    for (int u = 0; u < 3; u++) { v[u] = p[t + 256 * u]; m = fmaxf(m, v[u]); }
    red[t] = m; __syncthreads();
    for (int s = 128; s > 0; s >>= 1) { if (t < s) red[t] = fmaxf(red[t], red[t + s]); __syncthreads(); }
    m = red[0]; __syncthreads();
    float sum = 0.f;
    #pragma unroll
    for (int u = 0; u < 3; u++) { v[u] = expf(v[u] - m); sum += v[u]; }
    red[t] = sum; __syncthreads();
    for (int s = 128; s > 0; s >>= 1) { if (t < s) red[t] += red[t + s]; __syncthreads(); }
    float inv = 1.0f / red[0];
    #pragma unroll
    for (int u = 0; u < 3; u++) p[t + 256 * u] = v[u] * inv;
}

// ---------------- head-mean of attn -> second output ------------------------
__global__ void amean_kernel(float* __restrict__ out2) {
    int idx = blockIdx.x * blockDim.x + threadIdx.x;
    if (idx >= BB * SS * SS) return;
    int b  = idx / (SS * SS);
    int qk = idx % (SS * SS);
    float s = 0.f;
    #pragma unroll
    for (int h = 0; h < HH; h++)
        s += g_sc[(size_t)(b * HH + h) * SS * SS + qk];
    out2[idx] = s * (1.0f / HH);
}

// ---------------- attended = attn @ V, to [B,S,D] ---------------------------
__global__ void av_kernel() {
    int bh = blockIdx.z;
    int b = bh / HH, h = bh % HH;
    const float* A  = g_sc + (size_t)bh * SS * SS;   // [S,S]
    const float* Bm = g_V  + bh * SS * HDIM;         // [S,64]
    __shared__ float As[64][17];
    __shared__ float Bs[16][65];
    int tx = threadIdx.x, ty = threadIdx.y;
    int t  = ty * 16 + tx;
    int i0 = blockIdx.y * 64;
    float acc[4][4] = {};
    for (int k0 = 0; k0 < SS; k0 += 16) {
        #pragma unroll
        for (int u = 0; u < 4; u++) {
            int f = t + 256 * u;
            As[f >> 4][f & 15] = A[(i0 + (f >> 4)) * SS + k0 + (f & 15)];
        }
        {   // Bs: 16x64 = 1024 elems
            #pragma unroll
            for (int u = 0; u < 4; u++) {
                int f = t + 256 * u;
                Bs[f >> 6][f & 63] = Bm[(k0 + (f >> 6)) * HDIM + (f & 63)];
            }
        }
        __syncthreads();
        #pragma unroll
        for (int kk = 0; kk < 16; kk++) {
            float a[4], bb[4];
            #pragma unroll
            for (int i = 0; i < 4; i++) a[i] = As[ty * 4 + i][kk];
            #pragma unroll
            for (int j = 0; j < 4; j++) bb[j] = Bs[kk][tx * 4 + j];
            #pragma unroll
            for (int i = 0; i < 4; i++)
                #pragma unroll
                for (int j = 0; j < 4; j++)
                    acc[i][j] += a[i] * bb[j];
        }
        __syncthreads();
    }
    #pragma unroll
    for (int i = 0; i < 4; i++) {
        int s = i0 + ty * 4 + i;
        #pragma unroll
        for (int j = 0; j < 4; j++) {
            int d = tx * 4 + j;
            g_att[(b * SS + s) * DDIM + h * HDIM + d] = acc[i][j];
        }
    }
}

// ---------------- out = attended @ Wo + bo ----------------------------------
__global__ void outproj_kernel(const float* __restrict__ Wo,
                               const float* __restrict__ bo,
                               float* __restrict__ out) {
    __shared__ float As[64][16];
    __shared__ float Bs[16][65];
    int tx = threadIdx.x, ty = threadIdx.y;
    int t  = ty * 16 + tx;
    int row0 = blockIdx.y * 64, col0 = blockIdx.x * 64;
    float acc[4][4] = {};
    for (int k0 = 0; k0 < DDIM; k0 += 16) {
        #pragma unroll
        for (int u = 0; u < 4; u++) {
            int f = t + 256 * u;
            As[f >> 4][f & 15] = g_att[(row0 + (f >> 4)) * DDIM + k0 + (f & 15)];
        }
        #pragma unroll
        for (int u = 0; u < 4; u++) {
            int f = t + 256 * u;
            Bs[f >> 6][f & 63] = Wo[(k0 + (f >> 6)) * DDIM + col0 + (f & 63)];
        }
        __syncthreads();
        #pragma unroll
        for (int kk = 0; kk < 16; kk++) {
            float a[4], b[4];
            #pragma unroll
            for (int i = 0; i < 4; i++) a[i] = As[ty * 4 + i][kk];
            #pragma unroll
            for (int j = 0; j < 4; j++) b[j] = Bs[kk][tx * 4 + j];
            #pragma unroll
            for (int i = 0; i < 4; i++)
                #pragma unroll
                for (int j = 0; j < 4; j++)
                    acc[i][j] += a[i] * b[j];
        }
        __syncthreads();
    }
    #pragma unroll
    for (int i = 0; i < 4; i++) {
        int m = row0 + ty * 4 + i;
        #pragma unroll
        for (int j = 0; j < 4; j++) {
            int n = col0 + tx * 4 + j;
            out[m * DDIM + n] = acc[i][j] + bo[n];
        }
    }
}

// ---------------- launch -----------------------------------------------------
extern "C" void kernel_launch(void* const* d_in, const int* in_sizes, int n_in,
                              void* d_out, int out_size) {
    const float* query = (const float*)d_in[0];
    const float* key   = (const float*)d_in[1];
    const float* value = (const float*)d_in[2];
    const float* Wq = (const float*)d_in[3];
    const float* bq = (const float*)d_in[4];
    const float* Wk = (const float*)d_in[5];
    const float* bk = (const float*)d_in[6];
    const float* Wv = (const float*)d_in[7];
    const float* bv = (const float*)d_in[8];
    const float* Wo = (const float*)d_in[9];
    const float* bo = (const float*)d_in[10];
    const float* qmapW = (const float*)d_in[11];
    const float* qmapb = (const float*)d_in[12];
    const float* qw    = (const float*)d_in[13];
    const float* ph    = (const float*)d_in[14];
    const float* es    = (const float*)d_in[15];

    float* out  = (float*)d_out;                 // [B,S,D]
    float* out2 = out + MM * DDIM;               // [B,S,S]

    dim3 blk(16, 16);
    // 1. QKV projections
    proj_kernel<<<dim3(DDIM / 64, MM / 64, 3), blk>>>(query, key, value,
                                                      Wq, bq, Wk, bk, Wv, bv);
    // 2. quantum features
    {
        int n = 2 * BHn * SS;
        qfeat_kernel<<<(n + 127) / 128, 128>>>(qmapW, qmapb, qw, ph);
    }
    // 3. mixed scores
    scores_kernel<<<dim3(SS / 64, SS / 64, BHn), blk>>>(es);
    // 4. softmax in place
    softmax_kernel<<<BHn * SS, 256>>>();
    // 5. head-mean output
    {
        int n = BB * SS * SS;
        amean_kernel<<<(n + 255) / 256, 256>>>(out2);
    }
    // 6. attn @ V
    av_kernel<<<dim3(1, SS / 64, BHn), blk>>>();
    // 7. output projection
    outproj_kernel<<<dim3(DDIM / 64, MM / 64), blk>>>(Wo, bo, out);
}

// round 2
// speedup vs baseline: 1.9051x; 1.9051x over previous
#include <cuda_runtime.h>
#include <math.h>

#define BB   2
#define SS   768
#define DDIM 1024
#define HH   16
#define HDIM 64
#define NQh  8
#define NF   16
#define BHn  (BB*HH)     // 32
#define MM   (BB*SS)     // 1536

// ---------------- scratch ----------------------------------------------------
__device__ float g_Q[BHn*SS*HDIM];
__device__ float g_K[BHn*SS*HDIM];
__device__ float g_V[BHn*SS*HDIM];
__device__ float g_fQ[BHn*SS*NF];
__device__ float g_fK[BHn*SS*NF];
__device__ float g_sc[(size_t)BHn*SS*SS];
__device__ float g_att[MM*DDIM];

// ---------------- helpers ----------------------------------------------------
__device__ __forceinline__ unsigned f2tf32(float f) {
    unsigned u;
    asm("cvt.rna.tf32.f32 %0, %1;" : "=r"(u) : "f"(f));
    return u;
}

__device__ __forceinline__ void mma_tf32(float& c0, float& c1, float& c2, float& c3,
                                         unsigned a0, unsigned a1, unsigned a2, unsigned a3,
                                         unsigned b0, unsigned b1) {
    asm volatile("mma.sync.aligned.m16n8k8.row.col.f32.tf32.tf32.f32 "
                 "{%0,%1,%2,%3}, {%4,%5,%6,%7}, {%8,%9}, {%0,%1,%2,%3};\n"
                 : "+f"(c0), "+f"(c1), "+f"(c2), "+f"(c3)
                 : "r"(a0), "r"(a1), "r"(a2), "r"(a3), "r"(b0), "r"(b1));
}

// Warp-tile compute over one K-chunk of 16 (two k8 steps).
// As: [128][17] tf32, Bs: [64][17] tf32. Warp wm in 0..3 (m*32), wn in 0..1 (n*32).
// acc[mt 2][nt 4][4]
#define WARP_MMA_STEP(As, Bs, acc)                                              \
    {                                                                           \
        _Pragma("unroll")                                                       \
        for (int kk = 0; kk < 16; kk += 8) {                                    \
            unsigned afr[2][4];                                                 \
            _Pragma("unroll")                                                   \
            for (int mt = 0; mt < 2; mt++) {                                    \
                int r = wm * 32 + mt * 16 + g;                                  \
                afr[mt][0] = As[r][kk + tg];                                    \
                afr[mt][1] = As[r + 8][kk + tg];                                \
                afr[mt][2] = As[r][kk + tg + 4];                                \
                afr[mt][3] = As[r + 8][kk + tg + 4];                            \
            }                                                                   \
            unsigned bfr[4][2];                                                 \
            _Pragma("unroll")                                                   \
            for (int nt = 0; nt < 4; nt++) {                                    \
                int c = wn * 32 + nt * 8 + g;                                   \
                bfr[nt][0] = Bs[c][kk + tg];                                    \
                bfr[nt][1] = Bs[c][kk + tg + 4];                                \
            }                                                                   \
            _Pragma("unroll")                                                   \
            for (int mt = 0; mt < 2; mt++)                                      \
                _Pragma("unroll")                                               \
                for (int nt = 0; nt < 4; nt++)                                  \
                    mma_tf32(acc[mt][nt][0], acc[mt][nt][1],                    \
                             acc[mt][nt][2], acc[mt][nt][3],                    \
                             afr[mt][0], afr[mt][1], afr[mt][2], afr[mt][3],    \
                             bfr[nt][0], bfr[nt][1]);                           \
        }                                                                       \
    }

// ---------------- fused QKV projection (tf32 MMA) ---------------------------
__global__ __launch_bounds__(256) void proj_kernel(
        const float* __restrict__ q, const float* __restrict__ k,
        const float* __restrict__ v,
        const float* __restrict__ Wq, const float* __restrict__ bq,
        const float* __restrict__ Wk, const float* __restrict__ bk,
        const float* __restrict__ Wv, const float* __restrict__ bv) {
    int which = blockIdx.z;
    const float* A    = (which == 0) ? q  : (which == 1) ? k  : v;
    const float* W    = (which == 0) ? Wq : (which == 1) ? Wk : Wv;
    const float* bias = (which == 0) ? bq : (which == 1) ? bk : bv;
    float*       out  = (which == 0) ? g_Q : (which == 1) ? g_K : g_V;

    __shared__ unsigned As[128][17];
    __shared__ unsigned Bs[64][17];
    int tid  = threadIdx.x;
    int wid  = tid >> 5, lane = tid & 31;
    int wm   = wid & 3, wn = wid >> 2;
    int g    = lane >> 2, tg = lane & 3;
    int row0 = blockIdx.y * 128, col0 = blockIdx.x * 64;

    float acc[2][4][4] = {};
    int ar = tid >> 2, ac = (tid & 3) * 4;          // A: 64 rows/pass, 4 floats
    int bk2 = tid >> 4, bn = (tid & 15) * 4;        // B: 16 k-rows, 4 n each

    for (int k0 = 0; k0 < DDIM; k0 += 16) {
        #pragma unroll
        for (int p = 0; p < 2; p++) {
            int m = p * 64 + ar;
            float4 f = *(const float4*)&A[(size_t)(row0 + m) * DDIM + k0 + ac];
            As[m][ac]     = f2tf32(f.x);
            As[m][ac + 1] = f2tf32(f.y);
            As[m][ac + 2] = f2tf32(f.z);
            As[m][ac + 3] = f2tf32(f.w);
        }
        {
            float4 f = *(const float4*)&W[(size_t)(k0 + bk2) * DDIM + col0 + bn];
            Bs[bn][bk2]     = f2tf32(f.x);
            Bs[bn + 1][bk2] = f2tf32(f.y);
            Bs[bn + 2][bk2] = f2tf32(f.z);
            Bs[bn + 3][bk2] = f2tf32(f.w);
        }
        __syncthreads();
        WARP_MMA_STEP(As, Bs, acc)
        __syncthreads();
    }
    #pragma unroll
    for (int mt = 0; mt < 2; mt++) {
        #pragma unroll
        for (int nt = 0; nt < 4; nt++) {
            int gm = row0 + wm * 32 + mt * 16 + g;
            int gn = col0 + wn * 32 + nt * 8 + tg * 2;
            #pragma unroll
            for (int hrow = 0; hrow < 2; hrow++) {
                int m = gm + hrow * 8;
                int b = m / SS, s = m % SS;
                #pragma unroll
                for (int j = 0; j < 2; j++) {
                    int n = gn + j;
                    int h = n >> 6, d = n & 63;
                    out[(((size_t)(b * HH + h) * SS + s)) * HDIM + d] =
                        acc[mt][nt][hrow * 2 + j] + bias[n];
                }
            }
        }
    }
}

// ---------------- quantum features ------------------------------------------
__global__ void qfeat_kernel(const float* __restrict__ qmapW,
                             const float* __restrict__ qmapb,
                             const float* __restrict__ qw,
                             const float* __restrict__ ph) {
    int idx = blockIdx.x * blockDim.x + threadIdx.x;
    if (idx >= 2 * BHn * SS) return;
    int side = idx / (BHn * SS);
    int r    = idx % (BHn * SS);
    int h    = (r / SS) % HH;
    const float* row  = ((side == 0) ? g_Q : g_K) + (size_t)r * HDIM;
    float*       feat = ((side == 0) ? g_fQ : g_fK) + (size_t)r * NF;

    float rv[HDIM];
    #pragma unroll
    for (int d = 0; d < HDIM; d++) rv[d] = row[d];

    #pragma unroll
    for (int n = 0; n < NQh; n++) {
        float acc = qmapb[n];
        #pragma unroll
        for (int d = 0; d < HDIM; d++) acc += rv[d] * qmapW[d * NQh + n];
        float a = tanhf(acc);
        float s, c;
        if (side == 0) {
            float w = (1.0f / (1.0f + expf(-qw[h * NQh + n]))) * (1.0f / NQh);
            sincosf(a + ph[h * NQh + n], &s, &c);
            feat[n]       = w * c;
            feat[NQh + n] = w * s;
        } else {
            sincosf(a, &s, &c);
            feat[n]       = c;
            feat[NQh + n] = s;
        }
    }
}

// ---------------- scores (tf32 MMA): classical + quantum --------------------
__global__ __launch_bounds__(256) void scores_kernel(const float* __restrict__ es_ptr) {
    int bh = blockIdx.z;
    const float* Qp = g_Q  + (size_t)bh * SS * HDIM;
    const float* Kp = g_K  + (size_t)bh * SS * HDIM;
    const float* Fq = g_fQ + (size_t)bh * SS * NF;
    const float* Fk = g_fK + (size_t)bh * SS * NF;
    float* out = g_sc + (size_t)bh * SS * SS;

    __shared__ unsigned As[128][17];
    __shared__ unsigned Bs[64][17];
    int tid  = threadIdx.x;
    int wid  = tid >> 5, lane = tid & 31;
    int wm   = wid & 3, wn = wid >> 2;
    int g    = lane >> 2, tg = lane & 3;
    int i0   = blockIdx.y * 128, j0 = blockIdx.x * 64;

    float acc1[2][4][4] = {};
    float acc2[2][4][4] = {};
    int ar = tid >> 2, ac = (tid & 3) * 4;
    int br = tid >> 2, bc = (tid & 3) * 4;

    for (int k0 = 0; k0 < HDIM; k0 += 16) {            // classical
        #pragma unroll
        for (int p = 0; p < 2; p++) {
            int m = p * 64 + ar;
            float4 f = *(const float4*)&Qp[(size_t)(i0 + m) * HDIM + k0 + ac];
            As[m][ac]     = f2tf32(f.x);
            As[m][ac + 1] = f2tf32(f.y);
            As[m][ac + 2] = f2tf32(f.z);
            As[m][ac + 3] = f2tf32(f.w);
        }
        {
            float4 f = *(const float4*)&Kp[(size_t)(j0 + br) * HDIM + k0 + bc];
            Bs[br][bc]     = f2tf32(f.x);
            Bs[br][bc + 1] = f2tf32(f.y);
            Bs[br][bc + 2] = f2tf32(f.z);
            Bs[br][bc + 3] = f2tf32(f.w);
        }
        __syncthreads();
        WARP_MMA_STEP(As, Bs, acc1)
        __syncthreads();
    }
    {                                                   // quantum, K=16
        #pragma unroll
        for (int p = 0; p < 2; p++) {
            int m = p * 64 + ar;
            float4 f = *(const float4*)&Fq[(size_t)(i0 + m) * NF + ac];
            As[m][ac]     = f2tf32(f.x);
            As[m][ac + 1] = f2tf32(f.y);
            As[m][ac + 2] = f2tf32(f.z);
            As[m][ac + 3] = f2tf32(f.w);
        }
        {
            float4 f = *(const float4*)&Fk[(size_t)(j0 + br) * NF + bc];
            Bs[br][bc]     = f2tf32(f.x);
            Bs[br][bc + 1] = f2tf32(f.y);
            Bs[br][bc + 2] = f2tf32(f.z);
            Bs[br][bc + 3] = f2tf32(f.w);
        }
        __syncthreads();
        WARP_MMA_STEP(As, Bs, acc2)
        __syncthreads();
    }
    float es  = *es_ptr;
    float mix = 1.0f / (1.0f + expf(-es));
    float ca  = (1.0f - mix) * 0.125f;
    #pragma unroll
    for (int mt = 0; mt < 2; mt++) {
        #pragma unroll
        for (int nt = 0; nt < 4; nt++) {
            int gm = i0 + wm * 32 + mt * 16 + g;
            int gn = j0 + wn * 32 + nt * 8 + tg * 2;
            #pragma unroll
            for (int hrow = 0; hrow < 2; hrow++) {
                int gi = gm + hrow * 8;
                #pragma unroll
                for (int j = 0; j < 2; j++) {
                    int gj = gn + j;
                    float ent = __expf(-0.1f * fabsf((float)(gi - gj)));
                    out[(size_t)gi * SS + gj] =
                        ca * acc1[mt][nt][hrow * 2 + j] +
                        mix * ent * acc2[mt][nt][hrow * 2 + j];
                }
            }
        }
    }
}

// ---------------- row softmax (warp-shuffle) --------------------------------
__global__ void softmax_kernel() {
    int row = blockIdx.x;
    float* p = g_sc + (size_t)row * SS;
    int t = threadIdx.x;
    int wid = t >> 5, lane = t & 31;
    __shared__ float redm[8], reds[8];

    float v0 = p[t], v1 = p[t + 256], v2 = p[t + 512];
    float m = fmaxf(v0, fmaxf(v1, v2));
    #pragma unroll
    for (int o = 16; o; o >>= 1) m = fmaxf(m, __shfl_xor_sync(0xffffffffu, m, o));
    if (lane == 0) redm[wid] = m;
    __syncthreads();
    float bm = redm[0];
    #pragma unroll
    for (int w = 1; w < 8; w++) bm = fmaxf(bm, redm[w]);

    v0 = __expf(v0 - bm); v1 = __expf(v1 - bm); v2 = __expf(v2 - bm);
    float s = v0 + v1 + v2;
    #pragma unroll
    for (int o = 16; o; o >>= 1) s += __shfl_xor_sync(0xffffffffu, s, o);
    if (lane == 0) reds[wid] = s;
    __syncthreads();
    float bs = reds[0];
    #pragma unroll
    for (int w = 1; w < 8; w++) bs += reds[w];
    float inv = __frcp_rn(bs);
    p[t] = v0 * inv; p[t + 256] = v1 * inv; p[t + 512] = v2 * inv;
}

// ---------------- head-mean of attn -> second output ------------------------
__global__ void amean_kernel(float* __restrict__ out2) {
    int idx = blockIdx.x * blockDim.x + threadIdx.x;
    if (idx >= BB * SS * SS / 4) return;
    int b  = idx / (SS * SS / 4);
    int qk = idx % (SS * SS / 4);
    float4 s = make_float4(0.f, 0.f, 0.f, 0.f);
    #pragma unroll
    for (int h = 0; h < HH; h++) {
        const float4* src = (const float4*)(g_sc + (size_t)(b * HH + h) * SS * SS);
        float4 v = src[qk];
        s.x += v.x; s.y += v.y; s.z += v.z; s.w += v.w;
    }
    float4* dst = (float4*)out2;
    s.x *= (1.0f / HH); s.y *= (1.0f / HH); s.z *= (1.0f / HH); s.w *= (1.0f / HH);
    dst[idx] = s;
}

// ---------------- attended = attn @ V (tf32 MMA) ----------------------------
__global__ __launch_bounds__(256) void av_kernel() {
    int bh = blockIdx.z;
    int b = bh / HH, h = bh % HH;
    const float* A  = g_sc + (size_t)bh * SS * SS;
    const float* Vp = g_V  + (size_t)bh * SS * HDIM;

    __shared__ unsigned As[128][17];
    __shared__ unsigned Bs[64][17];
    int tid  = threadIdx.x;
    int wid  = tid >> 5, lane = tid & 31;
    int wm   = wid & 3, wn = wid >> 2;
    int g    = lane >> 2, tg = lane & 3;
    int i0   = blockIdx.y * 128;

    float acc[2][4][4] = {};
    int ar = tid >> 2, ac = (tid & 3) * 4;
    int vk = tid >> 4, vn = (tid & 15) * 4;

    for (int k0 = 0; k0 < SS; k0 += 16) {
        #pragma unroll
        for (int p = 0; p < 2; p++) {
            int m = p * 64 + ar;
            float4 f = *(const float4*)&A[(size_t)(i0 + m) * SS + k0 + ac];
            As[m][ac]     = f2tf32(f.x);
            As[m][ac + 1] = f2tf32(f.y);
            As[m][ac + 2] = f2tf32(f.z);
            As[m][ac + 3] = f2tf32(f.w);
        }
        {
            float4 f = *(const float4*)&Vp[(size_t)(k0 + vk) * HDIM + vn];
            Bs[vn][vk]     = f2tf32(f.x);
            Bs[vn + 1][vk] = f2tf32(f.y);
            Bs[vn + 2][vk] = f2tf32(f.z);
            Bs[vn + 3][vk] = f2tf32(f.w);
        }
        __syncthreads();
        WARP_MMA_STEP(As, Bs, acc)
        __syncthreads();
    }
    #pragma unroll
    for (int mt = 0; mt < 2; mt++) {
        #pragma unroll
        for (int nt = 0; nt < 4; nt++) {
            int gm = i0 + wm * 32 + mt * 16 + g;
            int gn = wn * 32 + nt * 8 + tg * 2;
            #pragma unroll
            for (int hrow = 0; hrow < 2; hrow++) {
                int s = gm + hrow * 8;
                #pragma unroll
                for (int j = 0; j < 2; j++) {
                    int d = gn + j;
                    g_att[(size_t)(b * SS + s) * DDIM + h * HDIM + d] =
                        acc[mt][nt][hrow * 2 + j];
                }
            }
        }
    }
}

// ---------------- out = attended @ Wo + bo (tf32 MMA) -----------------------
__global__ __launch_bounds__(256) void outproj_kernel(const float* __restrict__ Wo,
                                                      const float* __restrict__ bo,
                                                      float* __restrict__ out) {
    __shared__ unsigned As[128][17];
    __shared__ unsigned Bs[64][17];
    int tid  = threadIdx.x;
    int wid  = tid >> 5, lane = tid & 31;
    int wm   = wid & 3, wn = wid >> 2;
    int g    = lane >> 2, tg = lane & 3;
    int row0 = blockIdx.y * 128, col0 = blockIdx.x * 64;

    float acc[2][4][4] = {};
    int ar = tid >> 2, ac = (tid & 3) * 4;
    int bk2 = tid >> 4, bn = (tid & 15) * 4;

    for (int k0 = 0; k0 < DDIM; k0 += 16) {
        #pragma unroll
        for (int p = 0; p < 2; p++) {
            int m = p * 64 + ar;
            float4 f = *(const float4*)&g_att[(size_t)(row0 + m) * DDIM + k0 + ac];
            As[m][ac]     = f2tf32(f.x);
            As[m][ac + 1] = f2tf32(f.y);
            As[m][ac + 2] = f2tf32(f.z);
            As[m][ac + 3] = f2tf32(f.w);
        }
        {
            float4 f = *(const float4*)&Wo[(size_t)(k0 + bk2) * DDIM + col0 + bn];
            Bs[bn][bk2]     = f2tf32(f.x);
            Bs[bn + 1][bk2] = f2tf32(f.y);
            Bs[bn + 2][bk2] = f2tf32(f.z);
            Bs[bn + 3][bk2] = f2tf32(f.w);
        }
        __syncthreads();
        WARP_MMA_STEP(As, Bs, acc)
        __syncthreads();
    }
    #pragma unroll
    for (int mt = 0; mt < 2; mt++) {
        #pragma unroll
        for (int nt = 0; nt < 4; nt++) {
            int gm = row0 + wm * 32 + mt * 16 + g;
            int gn = col0 + wn * 32 + nt * 8 + tg * 2;
            #pragma unroll
            for (int hrow = 0; hrow < 2; hrow++) {
                int m = gm + hrow * 8;
                #pragma unroll
                for (int j = 0; j < 2; j++) {
                    int n = gn + j;
                    out[(size_t)m * DDIM + n] = acc[mt][nt][hrow * 2 + j] + bo[n];
                }
            }
        }
    }
}

// ---------------- launch -----------------------------------------------------
extern "C" void kernel_launch(void* const* d_in, const int* in_sizes, int n_in,
                              void* d_out, int out_size) {
    const float* query = (const float*)d_in[0];
    const float* key   = (const float*)d_in[1];
    const float* value = (const float*)d_in[2];
    const float* Wq = (const float*)d_in[3];
    const float* bq = (const float*)d_in[4];
    const float* Wk = (const float*)d_in[5];
    const float* bk = (const float*)d_in[6];
    const float* Wv = (const float*)d_in[7];
    const float* bv = (const float*)d_in[8];
    const float* Wo = (const float*)d_in[9];
    const float* bo = (const float*)d_in[10];
    const float* qmapW = (const float*)d_in[11];
    const float* qmapb = (const float*)d_in[12];
    const float* qw    = (const float*)d_in[13];
    const float* ph    = (const float*)d_in[14];
    const float* es    = (const float*)d_in[15];

    float* out  = (float*)d_out;
    float* out2 = out + (size_t)MM * DDIM;

    proj_kernel<<<dim3(DDIM / 64, MM / 128, 3), 256>>>(query, key, value,
                                                       Wq, bq, Wk, bk, Wv, bv);
    {
        int n = 2 * BHn * SS;
        qfeat_kernel<<<(n + 127) / 128, 128>>>(qmapW, qmapb, qw, ph);
    }
    scores_kernel<<<dim3(SS / 64, SS / 128, BHn), 256>>>(es);
    softmax_kernel<<<BHn * SS, 256>>>();
    {
        int n = BB * SS * SS / 4;
        amean_kernel<<<(n + 255) / 256, 256>>>(out2);
    }
    av_kernel<<<dim3(1, SS / 128, BHn), 256>>>();
    outproj_kernel<<<dim3(DDIM / 64, MM / 128), 256>>>(Wo, bo, out);
}

// round 3
// speedup vs baseline: 1.9793x; 1.0389x over previous
#include <cuda_runtime.h>
#include <math.h>

#define BB   2
#define SS   768
#define DDIM 1024
#define HH   16
#define HDIM 64
#define NQh  8
#define NF   16
#define BHn  (BB*HH)     // 32
#define MM   (BB*SS)     // 1536
#define PROW 772         // 768 + 4 pad (float), conflict-free MMA frag loads

// ---------------- scratch ----------------------------------------------------
__device__ float g_Q[BHn*SS*HDIM];
__device__ float g_K[BHn*SS*HDIM];
__device__ float g_V[BHn*SS*HDIM];
__device__ float g_fQ[BHn*SS*NF];
__device__ float g_fK[BHn*SS*NF];
__device__ float g_sc[(size_t)BHn*SS*SS];
__device__ float g_att[MM*DDIM];

// ---------------- helpers ----------------------------------------------------
__device__ __forceinline__ unsigned f2tf32(float f) {
    unsigned u;
    asm("cvt.rna.tf32.f32 %0, %1;" : "=r"(u) : "f"(f));
    return u;
}

__device__ __forceinline__ void mma_tf32(float& c0, float& c1, float& c2, float& c3,
                                         unsigned a0, unsigned a1, unsigned a2, unsigned a3,
                                         unsigned b0, unsigned b1) {
    asm volatile("mma.sync.aligned.m16n8k8.row.col.f32.tf32.tf32.f32 "
                 "{%0,%1,%2,%3}, {%4,%5,%6,%7}, {%8,%9}, {%0,%1,%2,%3};\n"
                 : "+f"(c0), "+f"(c1), "+f"(c2), "+f"(c3)
                 : "r"(a0), "r"(a1), "r"(a2), "r"(a3), "r"(b0), "r"(b1));
}

// warp-tile (128x64 block, 8 warps as 4m x 2n, warp tile 32x16-per-mt... acc[2][4][4])
#define WARP_MMA_STEP(AsX, BsX, acc)                                            \
    {                                                                           \
        _Pragma("unroll")                                                       \
        for (int kk = 0; kk < 16; kk += 8) {                                    \
            unsigned afr[2][4];                                                 \
            _Pragma("unroll")                                                   \
            for (int mt = 0; mt < 2; mt++) {                                    \
                int r = wm * 32 + mt * 16 + g;                                  \
                afr[mt][0] = AsX[r][kk + tg];                                   \
                afr[mt][1] = AsX[r + 8][kk + tg];                               \
                afr[mt][2] = AsX[r][kk + tg + 4];                               \
                afr[mt][3] = AsX[r + 8][kk + tg + 4];                           \
            }                                                                   \
            unsigned bfr[4][2];                                                 \
            _Pragma("unroll")                                                   \
            for (int nt = 0; nt < 4; nt++) {                                    \
                int c = wn * 32 + nt * 8 + g;                                   \
                bfr[nt][0] = BsX[c][kk + tg];                                   \
                bfr[nt][1] = BsX[c][kk + tg + 4];                               \
            }                                                                   \
            _Pragma("unroll")                                                   \
            for (int mt = 0; mt < 2; mt++)                                      \
                _Pragma("unroll")                                               \
                for (int nt = 0; nt < 4; nt++)                                  \
                    mma_tf32(acc[mt][nt][0], acc[mt][nt][1],                    \
                             acc[mt][nt][2], acc[mt][nt][3],                    \
                             afr[mt][0], afr[mt][1], afr[mt][2], afr[mt][3],    \
                             bfr[nt][0], bfr[nt][1]);                           \
        }                                                                       \
    }

// ---------------- fused QKV projection (tf32 MMA, ping-pong pipeline) -------
__global__ __launch_bounds__(256) void proj_kernel(
        const float* __restrict__ q, const float* __restrict__ k,
        const float* __restrict__ v,
        const float* __restrict__ Wq, const float* __restrict__ bq,
        const float* __restrict__ Wk, const float* __restrict__ bk,
        const float* __restrict__ Wv, const float* __restrict__ bv) {
    int which = blockIdx.z;
    const float* A    = (which == 0) ? q  : (which == 1) ? k  : v;
    const float* W    = (which == 0) ? Wq : (which == 1) ? Wk : Wv;
    const float* bias = (which == 0) ? bq : (which == 1) ? bk : bv;
    float*       out  = (which == 0) ? g_Q : (which == 1) ? g_K : g_V;

    __shared__ unsigned As[2][128][17];
    __shared__ unsigned Bs[2][64][17];
    int tid  = threadIdx.x;
    int wid  = tid >> 5, lane = tid & 31;
    int wm   = wid & 3, wn = wid >> 2;
    int g    = lane >> 2, tg = lane & 3;
    int row0 = blockIdx.y * 128, col0 = blockIdx.x * 64;

    float acc[2][4][4] = {};
    int ar  = tid >> 2, ac = (tid & 3) * 4;
    int bkr = tid >> 4, bn = (tid & 15) * 4;

    float4 ra0, ra1, rb;
    // prologue: chunk 0
    ra0 = *(const float4*)&A[(size_t)(row0 + ar) * DDIM + ac];
    ra1 = *(const float4*)&A[(size_t)(row0 + 64 + ar) * DDIM + ac];
    rb  = *(const float4*)&W[(size_t)bkr * DDIM + col0 + bn];
    As[0][ar][ac]        = f2tf32(ra0.x); As[0][ar][ac + 1]      = f2tf32(ra0.y);
    As[0][ar][ac + 2]    = f2tf32(ra0.z); As[0][ar][ac + 3]      = f2tf32(ra0.w);
    As[0][64 + ar][ac]   = f2tf32(ra1.x); As[0][64 + ar][ac + 1] = f2tf32(ra1.y);
    As[0][64 + ar][ac + 2] = f2tf32(ra1.z); As[0][64 + ar][ac + 3] = f2tf32(ra1.w);
    Bs[0][bn][bkr] = f2tf32(rb.x); Bs[0][bn + 1][bkr] = f2tf32(rb.y);
    Bs[0][bn + 2][bkr] = f2tf32(rb.z); Bs[0][bn + 3][bkr] = f2tf32(rb.w);
    __syncthreads();

    for (int i = 0; i < DDIM / 16; i++) {
        int buf = i & 1;
        int k1 = (i + 1) * 16;
        if (k1 < DDIM) {
            ra0 = *(const float4*)&A[(size_t)(row0 + ar) * DDIM + k1 + ac];
            ra1 = *(const float4*)&A[(size_t)(row0 + 64 + ar) * DDIM + k1 + ac];
            rb  = *(const float4*)&W[(size_t)(k1 + bkr) * DDIM + col0 + bn];
        }
        WARP_MMA_STEP(As[buf], Bs[buf], acc)
        if (k1 < DDIM) {
            int nb = buf ^ 1;
            As[nb][ar][ac]          = f2tf32(ra0.x); As[nb][ar][ac + 1]      = f2tf32(ra0.y);
            As[nb][ar][ac + 2]      = f2tf32(ra0.z); As[nb][ar][ac + 3]      = f2tf32(ra0.w);
            As[nb][64 + ar][ac]     = f2tf32(ra1.x); As[nb][64 + ar][ac + 1] = f2tf32(ra1.y);
            As[nb][64 + ar][ac + 2] = f2tf32(ra1.z); As[nb][64 + ar][ac + 3] = f2tf32(ra1.w);
            Bs[nb][bn][bkr] = f2tf32(rb.x); Bs[nb][bn + 1][bkr] = f2tf32(rb.y);
            Bs[nb][bn + 2][bkr] = f2tf32(rb.z); Bs[nb][bn + 3][bkr] = f2tf32(rb.w);
        }
        __syncthreads();
    }
    #pragma unroll
    for (int mt = 0; mt < 2; mt++)
        #pragma unroll
        for (int nt = 0; nt < 4; nt++) {
            int gm = row0 + wm * 32 + mt * 16 + g;
            int gn = col0 + wn * 32 + nt * 8 + tg * 2;
            #pragma unroll
            for (int hrow = 0; hrow < 2; hrow++) {
                int m = gm + hrow * 8;
                int b = m / SS, s = m % SS;
                #pragma unroll
                for (int j = 0; j < 2; j++) {
                    int n = gn + j;
                    int h = n >> 6, d = n & 63;
                    out[((size_t)(b * HH + h) * SS + s) * HDIM + d] =
                        acc[mt][nt][hrow * 2 + j] + bias[n];
                }
            }
        }
}

// ---------------- quantum features (warp-per-row) ---------------------------
// side0 (Q): fQ = mix*sig(qw)/NQ * {cos,sin}(tanh(.)+phase)
// side1 (K): fK = {cos,sin}(tanh(.))
__global__ __launch_bounds__(256) void qfeat_kernel(
        const float* __restrict__ qmapW, const float* __restrict__ qmapb,
        const float* __restrict__ qw, const float* __restrict__ ph,
        const float* __restrict__ es_ptr) {
    int gw   = (blockIdx.x * blockDim.x + threadIdx.x) >> 5;
    int lane = threadIdx.x & 31;
    if (gw >= 2 * BHn * SS) return;
    int side = gw / (BHn * SS);
    int r    = gw % (BHn * SS);
    int h    = (r / SS) % HH;
    const float* row = ((side == 0) ? g_Q : g_K) + (size_t)r * HDIM;
    float rv0 = row[lane], rv1 = row[lane + 32];

    float mydot = 0.f;
    #pragma unroll
    for (int n = 0; n < NQh; n++) {
        float p = rv0 * qmapW[lane * NQh + n] + rv1 * qmapW[(lane + 32) * NQh + n];
        #pragma unroll
        for (int o = 16; o; o >>= 1) p += __shfl_xor_sync(0xffffffffu, p, o);
        if (lane == n) mydot = p;
    }
    if (lane < NQh) {
        float a = tanhf(mydot + qmapb[lane]);
        float s, c;
        if (side == 0) {
            float mix = 1.f / (1.f + __expf(-*es_ptr));
            float w = (1.f / (1.f + __expf(-qw[h * NQh + lane]))) * (1.0f / NQh) * mix;
            sincosf(a + ph[h * NQh + lane], &s, &c);
            g_fQ[(size_t)r * NF + lane]       = w * c;
            g_fQ[(size_t)r * NF + NQh + lane] = w * s;
        } else {
            sincosf(a, &s, &c);
            g_fK[(size_t)r * NF + lane]       = c;
            g_fK[(size_t)r * NF + NQh + lane] = s;
        }
    }
}

// ---------------- fused attention: scores + softmax + AV --------------------
// block: (qtile=64 rows) x (bh). smem: P[64][772] fp32 + Ks[64][81] tf32.
__global__ __launch_bounds__(256) void attn_kernel(const float* __restrict__ es_ptr) {
    extern __shared__ float P[];                      // [64][PROW]
    unsigned* Ks = (unsigned*)(P + 64 * PROW);        // [64][81]

    int bh = blockIdx.y;
    int b = bh >> 4, h = bh & 15;
    int i0 = blockIdx.x * 64;
    const float* Qp  = g_Q  + (size_t)bh * SS * HDIM;
    const float* Kp  = g_K  + (size_t)bh * SS * HDIM;
    const float* Vp  = g_V  + (size_t)bh * SS * HDIM;
    const float* Fqp = g_fQ + (size_t)bh * SS * NF;
    const float* Fkp = g_fK + (size_t)bh * SS * NF;
    float* scp = g_sc + (size_t)bh * SS * SS;

    int tid = threadIdx.x;
    int wid = tid >> 5, lane = tid & 31;
    int wm = wid & 3, wn = wid >> 2;
    int g = lane >> 2, tg = lane & 3;

    float es  = *es_ptr;
    float mix = 1.f / (1.f + __expf(-es));
    float ca  = (1.f - mix) * 0.125f;

    // ---- stage Q(*ca)+Fq into Ks, build persistent a-fragments -------------
    {
        #pragma unroll
        for (int it = 0; it < 4; it++) {
            int fid = tid + 256 * it;
            int r = fid >> 4, c4 = (fid & 15) * 4;
            float4 f = *(const float4*)&Qp[(size_t)(i0 + r) * HDIM + c4];
            Ks[r * 81 + c4]     = f2tf32(ca * f.x);
            Ks[r * 81 + c4 + 1] = f2tf32(ca * f.y);
            Ks[r * 81 + c4 + 2] = f2tf32(ca * f.z);
            Ks[r * 81 + c4 + 3] = f2tf32(ca * f.w);
        }
        int r = tid >> 2, c4 = (tid & 3) * 4;
        float4 f = *(const float4*)&Fqp[(size_t)(i0 + r) * NF + c4];
        Ks[r * 81 + 64 + c4]     = f2tf32(f.x);
        Ks[r * 81 + 64 + c4 + 1] = f2tf32(f.y);
        Ks[r * 81 + 64 + c4 + 2] = f2tf32(f.z);
        Ks[r * 81 + 64 + c4 + 3] = f2tf32(f.w);
    }
    __syncthreads();
    unsigned afr[10][4];
    #pragma unroll
    for (int s = 0; s < 10; s++) {
        int r = wm * 16 + g, c = s * 8 + tg;
        afr[s][0] = Ks[r * 81 + c];
        afr[s][1] = Ks[(r + 8) * 81 + c];
        afr[s][2] = Ks[r * 81 + c + 4];
        afr[s][3] = Ks[(r + 8) * 81 + c + 4];
    }

    // ---- phase 1: scores over 12 K-chunks ----------------------------------
    for (int jc = 0; jc < 12; jc++) {
        int j0 = jc * 64;
        // load K+Fk chunk into regs (overlaps previous compute drain)
        float4 rc[4], rq;
        #pragma unroll
        for (int it = 0; it < 4; it++) {
            int fid = tid + 256 * it;
            int r = fid >> 4, c4 = (fid & 15) * 4;
            rc[it] = *(const float4*)&Kp[(size_t)(j0 + r) * HDIM + c4];
        }
        {
            int r = tid >> 2, c4 = (tid & 3) * 4;
            rq = *(const float4*)&Fkp[(size_t)(j0 + r) * NF + c4];
        }
        __syncthreads();   // previous chunk's readers done
        #pragma unroll
        for (int it = 0; it < 4; it++) {
            int fid = tid + 256 * it;
            int r = fid >> 4, c4 = (fid & 15) * 4;
            Ks[r * 81 + c4]     = f2tf32(rc[it].x);
            Ks[r * 81 + c4 + 1] = f2tf32(rc[it].y);
            Ks[r * 81 + c4 + 2] = f2tf32(rc[it].z);
            Ks[r * 81 + c4 + 3] = f2tf32(rc[it].w);
        }
        {
            int r = tid >> 2, c4 = (tid & 3) * 4;
            Ks[r * 81 + 64 + c4]     = f2tf32(rq.x);
            Ks[r * 81 + 64 + c4 + 1] = f2tf32(rq.y);
            Ks[r * 81 + 64 + c4 + 2] = f2tf32(rq.z);
            Ks[r * 81 + 64 + c4 + 3] = f2tf32(rq.w);
        }
        __syncthreads();

        float accC[4][4] = {}, accQ[4][4] = {};
        #pragma unroll
        for (int s = 0; s < 10; s++) {
            unsigned bfr[4][2];
            #pragma unroll
            for (int nt = 0; nt < 4; nt++) {
                int c = wn * 32 + nt * 8 + g;
                bfr[nt][0] = Ks[c * 81 + s * 8 + tg];
                bfr[nt][1] = Ks[c * 81 + s * 8 + tg + 4];
            }
            #pragma unroll
            for (int nt = 0; nt < 4; nt++) {
                if (s < 8)
                    mma_tf32(accC[nt][0], accC[nt][1], accC[nt][2], accC[nt][3],
                             afr[s][0], afr[s][1], afr[s][2], afr[s][3],
                             bfr[nt][0], bfr[nt][1]);
                else
                    mma_tf32(accQ[nt][0], accQ[nt][1], accQ[nt][2], accQ[nt][3],
                             afr[s][0], afr[s][1], afr[s][2], afr[s][3],
                             bfr[nt][0], bfr[nt][1]);
            }
        }
        // epilogue into P
        #pragma unroll
        for (int nt = 0; nt < 4; nt++) {
            int r  = wm * 16 + g;
            int cl = wn * 32 + nt * 8 + tg * 2;
            #pragma unroll
            for (int hrow = 0; hrow < 2; hrow++) {
                int rr = r + hrow * 8;
                #pragma unroll
                for (int j = 0; j < 2; j++) {
                    int cc = cl + j;
                    float ent = __expf(-0.1f * fabsf((float)((i0 + rr) - (j0 + cc))));
                    P[rr * PROW + j0 + cc] =
                        accC[nt][hrow * 2 + j] + ent * accQ[nt][hrow * 2 + j];
                }
            }
        }
        __syncthreads();
    }

    // ---- phase 2: softmax over rows in smem --------------------------------
    for (int rr = wid; rr < 64; rr += 8) {
        float* row = P + rr * PROW;
        float v[24];
        float m = -1e30f;
        #pragma unroll
        for (int u = 0; u < 24; u++) { v[u] = row[lane + u * 32]; m = fmaxf(m, v[u]); }
        #pragma unroll
        for (int o = 16; o; o >>= 1) m = fmaxf(m, __shfl_xor_sync(0xffffffffu, m, o));
        float ssum = 0.f;
        #pragma unroll
        for (int u = 0; u < 24; u++) { v[u] = __expf(v[u] - m); ssum += v[u]; }
        #pragma unroll
        for (int o = 16; o; o >>= 1) ssum += __shfl_xor_sync(0xffffffffu, ssum, o);
        float inv = __frcp_rn(ssum);
        #pragma unroll
        for (int u = 0; u < 24; u++) row[lane + u * 32] = v[u] * inv;
    }
    __syncthreads();

    // ---- phase 2.5: write attn to g_sc (fire-and-forget) -------------------
    for (int fid = tid; fid < 64 * 192; fid += 256) {
        int r = fid / 192, c4 = fid % 192;
        *(float4*)&scp[(size_t)(i0 + r) * SS + c4 * 4] = *(float4*)&P[r * PROW + c4 * 4];
    }

    // ---- phase 3: AV from smem probs (ping-pong V staging) -----------------
    unsigned* Vs0 = Ks;              // [64][33]
    unsigned* Vs1 = Ks + 64 * 33;
    float acc[4][4] = {};
    float4 vreg[2];
    // prologue: chunk 0
    #pragma unroll
    for (int it = 0; it < 2; it++) {
        int fid = tid + it * 256;
        int kk = fid >> 4, c4 = (fid & 15) * 4;
        vreg[it] = *(const float4*)&Vp[(size_t)kk * HDIM + c4];
    }
    __syncthreads();  // attn writes (phase 2.5 reads P; Ks reuse needs phase1/afr done — already)
    #pragma unroll
    for (int it = 0; it < 2; it++) {
        int fid = tid + it * 256;
        int kk = fid >> 4, c4 = (fid & 15) * 4;
        Vs0[(c4)     * 33 + kk] = f2tf32(vreg[it].x);
        Vs0[(c4 + 1) * 33 + kk] = f2tf32(vreg[it].y);
        Vs0[(c4 + 2) * 33 + kk] = f2tf32(vreg[it].z);
        Vs0[(c4 + 3) * 33 + kk] = f2tf32(vreg[it].w);
    }
    __syncthreads();
    for (int cidx = 0; cidx < SS / 32; cidx++) {
        unsigned* Vc = (cidx & 1) ? Vs1 : Vs0;
        unsigned* Vn = (cidx & 1) ? Vs0 : Vs1;
        int k1 = (cidx + 1) * 32;
        if (k1 < SS) {
            #pragma unroll
            for (int it = 0; it < 2; it++) {
                int fid = tid + it * 256;
                int kk = fid >> 4, c4 = (fid & 15) * 4;
                vreg[it] = *(const float4*)&Vp[(size_t)(k1 + kk) * HDIM + c4];
            }
        }
        int k0 = cidx * 32;
        #pragma unroll
        for (int s = 0; s < 4; s++) {
            int kk = s * 8;
            int r = wm * 16 + g;
            unsigned a0 = f2tf32(P[r * PROW + k0 + kk + tg]);
            unsigned a1 = f2tf32(P[(r + 8) * PROW + k0 + kk + tg]);
            unsigned a2 = f2tf32(P[r * PROW + k0 + kk + tg + 4]);
            unsigned a3 = f2tf32(P[(r + 8) * PROW + k0 + kk + tg + 4]);
            #pragma unroll
            for (int nt = 0; nt < 4; nt++) {
                unsigned b0 = Vc[(wn * 32 + nt * 8 + g) * 33 + kk + tg];
                unsigned b1 = Vc[(wn * 32 + nt * 8 + g) * 33 + kk + tg + 4];
                mma_tf32(acc[nt][0], acc[nt][1], acc[nt][2], acc[nt][3],
                         a0, a1, a2, a3, b0, b1);
            }
        }
        if (k1 < SS) {
            #pragma unroll
            for (int it = 0; it < 2; it++) {
                int fid = tid + it * 256;
                int kk = fid >> 4, c4 = (fid & 15) * 4;
                Vn[(c4)     * 33 + kk] = f2tf32(vreg[it].x);
                Vn[(c4 + 1) * 33 + kk] = f2tf32(vreg[it].y);
                Vn[(c4 + 2) * 33 + kk] = f2tf32(vreg[it].z);
                Vn[(c4 + 3) * 33 + kk] = f2tf32(vreg[it].w);
            }
        }
        __syncthreads();
    }
    // epilogue -> g_att
    #pragma unroll
    for (int nt = 0; nt < 4; nt++) {
        int r = wm * 16 + g;
        int d0 = wn * 32 + nt * 8 + tg * 2;
        #pragma unroll
        for (int hrow = 0; hrow < 2; hrow++) {
            int s_ = i0 + r + hrow * 8;
            #pragma unroll
            for (int j = 0; j < 2; j++) {
                g_att[(size_t)(b * SS + s_) * DDIM + h * HDIM + d0 + j] =
                    acc[nt][hrow * 2 + j];
            }
        }
    }
}

// ---------------- head-mean of attn -> second output ------------------------
__global__ void amean_kernel(float* __restrict__ out2) {
    int idx = blockIdx.x * blockDim.x + threadIdx.x;
    if (idx >= BB * SS * SS / 4) return;
    int b  = idx / (SS * SS / 4);
    int qk = idx % (SS * SS / 4);
    float4 s = make_float4(0.f, 0.f, 0.f, 0.f);
    #pragma unroll
    for (int h = 0; h < HH; h++) {
        const float4* src = (const float4*)(g_sc + (size_t)(b * HH + h) * SS * SS);
        float4 v = src[qk];
        s.x += v.x; s.y += v.y; s.z += v.z; s.w += v.w;
    }
    s.x *= (1.0f / HH); s.y *= (1.0f / HH); s.z *= (1.0f / HH); s.w *= (1.0f / HH);
    ((float4*)out2)[idx] = s;
}

// ---------------- out = attended @ Wo + bo (tf32 MMA, ping-pong) ------------
__global__ __launch_bounds__(256) void outproj_kernel(const float* __restrict__ Wo,
                                                      const float* __restrict__ bo,
                                                      float* __restrict__ out) {
    __shared__ unsigned As[2][128][17];
    __shared__ unsigned Bs[2][64][17];
    int tid  = threadIdx.x;
    int wid  = tid >> 5, lane = tid & 31;
    int wm   = wid & 3, wn = wid >> 2;
    int g    = lane >> 2, tg = lane & 3;
    int row0 = blockIdx.y * 128, col0 = blockIdx.x * 64;

    float acc[2][4][4] = {};
    int ar  = tid >> 2, ac = (tid & 3) * 4;
    int bkr = tid >> 4, bn = (tid & 15) * 4;

    float4 ra0, ra1, rb;
    ra0 = *(const float4*)&g_att[(size_t)(row0 + ar) * DDIM + ac];
    ra1 = *(const float4*)&g_att[(size_t)(row0 + 64 + ar) * DDIM + ac];
    rb  = *(const float4*)&Wo[(size_t)bkr * DDIM + col0 + bn];
    As[0][ar][ac]          = f2tf32(ra0.x); As[0][ar][ac + 1]      = f2tf32(ra0.y);
    As[0][ar][ac + 2]      = f2tf32(ra0.z); As[0][ar][ac + 3]      = f2tf32(ra0.w);
    As[0][64 + ar][ac]     = f2tf32(ra1.x); As[0][64 + ar][ac + 1] = f2tf32(ra1.y);
    As[0][64 + ar][ac + 2] = f2tf32(ra1.z); As[0][64 + ar][ac + 3] = f2tf32(ra1.w);
    Bs[0][bn][bkr] = f2tf32(rb.x); Bs[0][bn + 1][bkr] = f2tf32(rb.y);
    Bs[0][bn + 2][bkr] = f2tf32(rb.z); Bs[0][bn + 3][bkr] = f2tf32(rb.w);
    __syncthreads();

    for (int i = 0; i < DDIM / 16; i++) {
        int buf = i & 1;
        int k1 = (i + 1) * 16;
        if (k1 < DDIM) {
            ra0 = *(const float4*)&g_att[(size_t)(row0 + ar) * DDIM + k1 + ac];
            ra1 = *(const float4*)&g_att[(size_t)(row0 + 64 + ar) * DDIM + k1 + ac];
            rb  = *(const float4*)&Wo[(size_t)(k1 + bkr) * DDIM + col0 + bn];
        }
        WARP_MMA_STEP(As[buf], Bs[buf], acc)
        if (k1 < DDIM) {
            int nb = buf ^ 1;
            As[nb][ar][ac]          = f2tf32(ra0.x); As[nb][ar][ac + 1]      = f2tf32(ra0.y);
            As[nb][ar][ac + 2]      = f2tf32(ra0.z); As[nb][ar][ac + 3]      = f2tf32(ra0.w);
            As[nb][64 + ar][ac]     = f2tf32(ra1.x); As[nb][64 + ar][ac + 1] = f2tf32(ra1.y);
            As[nb][64 + ar][ac + 2] = f2tf32(ra1.z); As[nb][64 + ar][ac + 3] = f2tf32(ra1.w);
            Bs[nb][bn][bkr] = f2tf32(rb.x); Bs[nb][bn + 1][bkr] = f2tf32(rb.y);
            Bs[nb][bn + 2][bkr] = f2tf32(rb.z); Bs[nb][bn + 3][bkr] = f2tf32(rb.w);
        }
        __syncthreads();
    }
    #pragma unroll
    for (int mt = 0; mt < 2; mt++)
        #pragma unroll
        for (int nt = 0; nt < 4; nt++) {
            int gm = row0 + wm * 32 + mt * 16 + g;
            int gn = col0 + wn * 32 + nt * 8 + tg * 2;
            #pragma unroll
            for (int hrow = 0; hrow < 2; hrow++) {
                int m = gm + hrow * 8;
                #pragma unroll
                for (int j = 0; j < 2; j++)
                    out[(size_t)m * DDIM + gn + j] = acc[mt][nt][hrow * 2 + j] + bo[gn + j];
            }
        }
}

// ---------------- launch -----------------------------------------------------
extern "C" void kernel_launch(void* const* d_in, const int* in_sizes, int n_in,
                              void* d_out, int out_size) {
    const float* query = (const float*)d_in[0];
    const float* key   = (const float*)d_in[1];
    const float* value = (const float*)d_in[2];
    const float* Wq = (const float*)d_in[3];
    const float* bq = (const float*)d_in[4];
    const float* Wk = (const float*)d_in[5];
    const float* bk = (const float*)d_in[6];
    const float* Wv = (const float*)d_in[7];
    const float* bv = (const float*)d_in[8];
    const float* Wo = (const float*)d_in[9];
    const float* bo = (const float*)d_in[10];
    const float* qmapW = (const float*)d_in[11];
    const float* qmapb = (const float*)d_in[12];
    const float* qw    = (const float*)d_in[13];
    const float* ph    = (const float*)d_in[14];
    const float* es    = (const float*)d_in[15];

    float* out  = (float*)d_out;
    float* out2 = out + (size_t)MM * DDIM;

    proj_kernel<<<dim3(DDIM / 64, MM / 128, 3), 256>>>(query, key, value,
                                                       Wq, bq, Wk, bk, Wv, bv);
    {
        int nrows = 2 * BHn * SS;               // one warp per row
        qfeat_kernel<<<nrows / 8, 256>>>(qmapW, qmapb, qw, ph, es);
    }
    {
        size_t smem = (size_t)64 * PROW * 4 + (size_t)64 * 81 * 4;   // 218368 B
        cudaFuncSetAttribute(attn_kernel,
                             cudaFuncAttributeMaxDynamicSharedMemorySize, (int)smem);
        attn_kernel<<<dim3(SS / 64, BHn), 256, smem>>>(es);
    }
    {
        int n = BB * SS * SS / 4;
        amean_kernel<<<(n + 255) / 256, 256>>>(out2);
    }
    outproj_kernel<<<dim3(DDIM / 64, MM / 128), 256>>>(Wo, bo, out);
}

// round 4
// speedup vs baseline: 2.4934x; 1.2598x over previous
#include <cuda_runtime.h>
#include <math.h>

#define BB   2
#define SS   768
#define DDIM 1024
#define HH   16
#define HDIM 64
#define NQh  8
#define NF   16
#define BHn  (BB*HH)     // 32
#define MM   (BB*SS)     // 1536
#define PROW 772
#define SPITCH 20        // smem row pitch (floats) for ldmatrix tiles

// ---------------- scratch ----------------------------------------------------
__device__ float g_Q[BHn*SS*HDIM];
__device__ float g_K[BHn*SS*HDIM];
__device__ float g_V[BHn*SS*HDIM];
__device__ float g_fQ[BHn*SS*NF];
__device__ float g_fK[BHn*SS*NF];
__device__ float g_sc[(size_t)BHn*SS*SS];
__device__ float g_att[MM*DDIM];

// ---------------- helpers ----------------------------------------------------
__device__ __forceinline__ unsigned f2tf32(float f) {
    unsigned u;
    asm("cvt.rna.tf32.f32 %0, %1;" : "=r"(u) : "f"(f));
    return u;
}

__device__ __forceinline__ void mma_tf32(float& c0, float& c1, float& c2, float& c3,
                                         unsigned a0, unsigned a1, unsigned a2, unsigned a3,
                                         unsigned b0, unsigned b1) {
    asm volatile("mma.sync.aligned.m16n8k8.row.col.f32.tf32.tf32.f32 "
                 "{%0,%1,%2,%3}, {%4,%5,%6,%7}, {%8,%9}, {%0,%1,%2,%3};\n"
                 : "+f"(c0), "+f"(c1), "+f"(c2), "+f"(c3)
                 : "r"(a0), "r"(a1), "r"(a2), "r"(a3), "r"(b0), "r"(b1));
}

__device__ __forceinline__ void ldsm_x4(unsigned& r0, unsigned& r1,
                                        unsigned& r2, unsigned& r3, unsigned addr) {
    asm volatile("ldmatrix.sync.aligned.m8n8.x4.shared.b16 {%0,%1,%2,%3}, [%4];"
                 : "=r"(r0), "=r"(r1), "=r"(r2), "=r"(r3) : "r"(addr));
}

// ============================================================================
// High-throughput tf32 GEMM core: 128x128 block, 8 warps (2m x 4n), warp 64x32.
// A[m][k] and B[n][k] staged in smem (pitch 20), fragments via ldmatrix.b16.
// ============================================================================
struct GemmCore {
    unsigned* As0; unsigned* As1; unsigned* Bs0; unsigned* Bs1;
};

#define GEMM_BODY(LOAD_A0, LOAD_A1, LOAD_B, NCHUNK)                              \
    float acc[4][4][4] = {};                                                     \
    int tid = threadIdx.x;                                                       \
    int wid = tid >> 5, lane = tid & 31;                                         \
    int wm = wid & 1, wnw = wid >> 1;                                            \
    int ar = tid >> 2, ac = (tid & 3) * 4;                                       \
    int bn = tid & 127, bk0 = (tid >> 7) * 8;                                    \
    int a_row = lane & 15, a_koff = (lane >> 4) * 4;                             \
    int b_nr  = (lane & 7) + ((lane >> 4) << 3);                                 \
    int b_koff = ((lane >> 3) & 1) * 4;                                          \
    unsigned aBase0 = (unsigned)__cvta_generic_to_shared(As0);                   \
    unsigned aBase1 = (unsigned)__cvta_generic_to_shared(As1);                   \
    unsigned bBase0 = (unsigned)__cvta_generic_to_shared(Bs0);                   \
    unsigned bBase1 = (unsigned)__cvta_generic_to_shared(Bs1);                   \
    float4 pa0, pa1; float pb[8];                                                \
    { int kg = 0;                                                                \
      pa0 = LOAD_A0(kg); pa1 = LOAD_A1(kg);                                      \
      _Pragma("unroll") for (int j = 0; j < 8; j++) pb[j] = LOAD_B(kg, j); }     \
    { unsigned* As = As0; unsigned* Bs = Bs0;                                    \
      *(uint4*)&As[ar * SPITCH + ac] =                                           \
          make_uint4(f2tf32(pa0.x), f2tf32(pa0.y), f2tf32(pa0.z), f2tf32(pa0.w));\
      *(uint4*)&As[(ar + 64) * SPITCH + ac] =                                    \
          make_uint4(f2tf32(pa1.x), f2tf32(pa1.y), f2tf32(pa1.z), f2tf32(pa1.w));\
      *(uint4*)&Bs[bn * SPITCH + bk0] =                                          \
          make_uint4(f2tf32(pb[0]), f2tf32(pb[1]), f2tf32(pb[2]), f2tf32(pb[3]));\
      *(uint4*)&Bs[bn * SPITCH + bk0 + 4] =                                      \
          make_uint4(f2tf32(pb[4]), f2tf32(pb[5]), f2tf32(pb[6]), f2tf32(pb[7]));}\
    __syncthreads();                                                             \
    for (int ch = 0; ch < (NCHUNK); ch++) {                                      \
        int buf = ch & 1;                                                        \
        if (ch + 1 < (NCHUNK)) {                                                 \
            int kg = (ch + 1) * 16;                                              \
            pa0 = LOAD_A0(kg); pa1 = LOAD_A1(kg);                                \
            _Pragma("unroll") for (int j = 0; j < 8; j++) pb[j] = LOAD_B(kg, j); \
        }                                                                        \
        unsigned aB = buf ? aBase1 : aBase0;                                     \
        unsigned bB = buf ? bBase1 : bBase0;                                     \
        _Pragma("unroll")                                                        \
        for (int ks = 0; ks < 2; ks++) {                                         \
            int kc = ks * 8;                                                     \
            unsigned af[4][4];                                                   \
            _Pragma("unroll")                                                    \
            for (int mt = 0; mt < 4; mt++)                                       \
                ldsm_x4(af[mt][0], af[mt][1], af[mt][2], af[mt][3],              \
                    aB + ((wm * 64 + mt * 16 + a_row) * SPITCH + kc + a_koff) * 4);\
            unsigned bf[4][2];                                                   \
            _Pragma("unroll")                                                    \
            for (int p = 0; p < 2; p++)                                          \
                ldsm_x4(bf[2 * p][0], bf[2 * p][1], bf[2 * p + 1][0],            \
                        bf[2 * p + 1][1],                                        \
                    bB + ((wnw * 32 + p * 16 + b_nr) * SPITCH + kc + b_koff) * 4);\
            _Pragma("unroll")                                                    \
            for (int mt = 0; mt < 4; mt++)                                       \
                _Pragma("unroll")                                                \
                for (int nt = 0; nt < 4; nt++)                                   \
                    mma_tf32(acc[mt][nt][0], acc[mt][nt][1],                     \
                             acc[mt][nt][2], acc[mt][nt][3],                     \
                             af[mt][0], af[mt][1], af[mt][2], af[mt][3],         \
                             bf[nt][0], bf[nt][1]);                              \
        }                                                                        \
        if (ch + 1 < (NCHUNK)) {                                                 \
            unsigned* As = buf ? As0 : As1;                                      \
            unsigned* Bs = buf ? Bs0 : Bs1;                                      \
            *(uint4*)&As[ar * SPITCH + ac] =                                     \
                make_uint4(f2tf32(pa0.x), f2tf32(pa0.y), f2tf32(pa0.z), f2tf32(pa0.w));\
            *(uint4*)&As[(ar + 64) * SPITCH + ac] =                              \
                make_uint4(f2tf32(pa1.x), f2tf32(pa1.y), f2tf32(pa1.z), f2tf32(pa1.w));\
            *(uint4*)&Bs[bn * SPITCH + bk0] =                                    \
                make_uint4(f2tf32(pb[0]), f2tf32(pb[1]), f2tf32(pb[2]), f2tf32(pb[3]));\
            *(uint4*)&Bs[bn * SPITCH + bk0 + 4] =                                \
                make_uint4(f2tf32(pb[4]), f2tf32(pb[5]), f2tf32(pb[6]), f2tf32(pb[7]));\
        }                                                                        \
        __syncthreads();                                                         \
    }

// ---------------- fused QKV projection ---------------------------------------
__global__ __launch_bounds__(256) void proj_kernel(
        const float* __restrict__ q, const float* __restrict__ k,
        const float* __restrict__ v,
        const float* __restrict__ Wq, const float* __restrict__ bq,
        const float* __restrict__ Wk, const float* __restrict__ bk,
        const float* __restrict__ Wv, const float* __restrict__ bv) {
    int which = blockIdx.z;
    const float* A    = (which == 0) ? q  : (which == 1) ? k  : v;
    const float* W    = (which == 0) ? Wq : (which == 1) ? Wk : Wv;
    const float* bias = (which == 0) ? bq : (which == 1) ? bk : bv;
    float*       out  = (which == 0) ? g_Q : (which == 1) ? g_K : g_V;

    __shared__ unsigned As0[128 * SPITCH], As1[128 * SPITCH];
    __shared__ unsigned Bs0[128 * SPITCH], Bs1[128 * SPITCH];
    int row0 = blockIdx.y * 128, col0 = blockIdx.x * 128;

#define LA0(kg) (*(const float4*)&A[(size_t)(row0 + ar) * DDIM + (kg) + ac])
#define LA1(kg) (*(const float4*)&A[(size_t)(row0 + 64 + ar) * DDIM + (kg) + ac])
#define LB(kg, j) (W[(size_t)((kg) + bk0 + (j)) * DDIM + col0 + bn])
    GEMM_BODY(LA0, LA1, LB, DDIM / 16)
#undef LA0
#undef LA1
#undef LB

    int g = lane >> 2, tg = lane & 3;
    #pragma unroll
    for (int mt = 0; mt < 4; mt++)
        #pragma unroll
        for (int nt = 0; nt < 4; nt++) {
            int gm = row0 + wm * 64 + mt * 16 + g;
            int gn = col0 + wnw * 32 + nt * 8 + tg * 2;
            #pragma unroll
            for (int hrow = 0; hrow < 2; hrow++) {
                int m = gm + hrow * 8;
                int b = m / SS, s = m % SS;
                #pragma unroll
                for (int j = 0; j < 2; j++) {
                    int n = gn + j;
                    int h = n >> 6, d = n & 63;
                    out[((size_t)(b * HH + h) * SS + s) * HDIM + d] =
                        acc[mt][nt][hrow * 2 + j] + bias[n];
                }
            }
        }
}

// ---------------- out = attended @ Wo + bo -----------------------------------
__global__ __launch_bounds__(256) void outproj_kernel(const float* __restrict__ Wo,
                                                      const float* __restrict__ bo,
                                                      float* __restrict__ out) {
    __shared__ unsigned As0[128 * SPITCH], As1[128 * SPITCH];
    __shared__ unsigned Bs0[128 * SPITCH], Bs1[128 * SPITCH];
    int row0 = blockIdx.y * 128, col0 = blockIdx.x * 128;

#define LA0(kg) (*(const float4*)&g_att[(size_t)(row0 + ar) * DDIM + (kg) + ac])
#define LA1(kg) (*(const float4*)&g_att[(size_t)(row0 + 64 + ar) * DDIM + (kg) + ac])
#define LB(kg, j) (Wo[(size_t)((kg) + bk0 + (j)) * DDIM + col0 + bn])
    GEMM_BODY(LA0, LA1, LB, DDIM / 16)
#undef LA0
#undef LA1
#undef LB

    int g = lane >> 2, tg = lane & 3;
    #pragma unroll
    for (int mt = 0; mt < 4; mt++)
        #pragma unroll
        for (int nt = 0; nt < 4; nt++) {
            int gm = row0 + wm * 64 + mt * 16 + g;
            int gn = col0 + wnw * 32 + nt * 8 + tg * 2;
            #pragma unroll
            for (int hrow = 0; hrow < 2; hrow++) {
                int m = gm + hrow * 8;
                #pragma unroll
                for (int j = 0; j < 2; j++)
                    out[(size_t)m * DDIM + gn + j] =
                        acc[mt][nt][hrow * 2 + j] + bo[gn + j];
            }
        }
}

// ---------------- quantum features (warp-per-row) ---------------------------
__global__ __launch_bounds__(256) void qfeat_kernel(
        const float* __restrict__ qmapW, const float* __restrict__ qmapb,
        const float* __restrict__ qw, const float* __restrict__ ph,
        const float* __restrict__ es_ptr) {
    int gw   = (blockIdx.x * blockDim.x + threadIdx.x) >> 5;
    int lane = threadIdx.x & 31;
    if (gw >= 2 * BHn * SS) return;
    int side = gw / (BHn * SS);
    int r    = gw % (BHn * SS);
    int h    = (r / SS) % HH;
    const float* row = ((side == 0) ? g_Q : g_K) + (size_t)r * HDIM;
    float rv0 = row[lane], rv1 = row[lane + 32];

    float mydot = 0.f;
    #pragma unroll
    for (int n = 0; n < NQh; n++) {
        float p = rv0 * qmapW[lane * NQh + n] + rv1 * qmapW[(lane + 32) * NQh + n];
        #pragma unroll
        for (int o = 16; o; o >>= 1) p += __shfl_xor_sync(0xffffffffu, p, o);
        if (lane == n) mydot = p;
    }
    if (lane < NQh) {
        float a = tanhf(mydot + qmapb[lane]);
        float s, c;
        if (side == 0) {
            float mix = 1.f / (1.f + __expf(-*es_ptr));
            float w = (1.f / (1.f + __expf(-qw[h * NQh + lane]))) * (1.0f / NQh) * mix;
            sincosf(a + ph[h * NQh + lane], &s, &c);
            g_fQ[(size_t)r * NF + lane]       = w * c;
            g_fQ[(size_t)r * NF + NQh + lane] = w * s;
        } else {
            sincosf(a, &s, &c);
            g_fK[(size_t)r * NF + lane]       = c;
            g_fK[(size_t)r * NF + NQh + lane] = s;
        }
    }
}

// ---------------- fused attention: scores + softmax + AV --------------------
__global__ __launch_bounds__(256) void attn_kernel(const float* __restrict__ es_ptr) {
    extern __shared__ float P[];                      // [64][PROW]
    unsigned* Ks = (unsigned*)(P + 64 * PROW);        // [64][81]

    int bh = blockIdx.y;
    int b = bh >> 4, h = bh & 15;
    int i0 = blockIdx.x * 64;
    const float* Qp  = g_Q  + (size_t)bh * SS * HDIM;
    const float* Kp  = g_K  + (size_t)bh * SS * HDIM;
    const float* Vp  = g_V  + (size_t)bh * SS * HDIM;
    const float* Fqp = g_fQ + (size_t)bh * SS * NF;
    const float* Fkp = g_fK + (size_t)bh * SS * NF;
    float* scp = g_sc + (size_t)bh * SS * SS;

    int tid = threadIdx.x;
    int wid = tid >> 5, lane = tid & 31;
    int wm = wid & 3, wn = wid >> 2;
    int g = lane >> 2, tg = lane & 3;

    float es  = *es_ptr;
    float mix = 1.f / (1.f + __expf(-es));
    float ca  = (1.f - mix) * 0.125f;

    {
        #pragma unroll
        for (int it = 0; it < 4; it++) {
            int fid = tid + 256 * it;
            int r = fid >> 4, c4 = (fid & 15) * 4;
            float4 f = *(const float4*)&Qp[(size_t)(i0 + r) * HDIM + c4];
            Ks[r * 81 + c4]     = f2tf32(ca * f.x);
            Ks[r * 81 + c4 + 1] = f2tf32(ca * f.y);
            Ks[r * 81 + c4 + 2] = f2tf32(ca * f.z);
            Ks[r * 81 + c4 + 3] = f2tf32(ca * f.w);
        }
        int r = tid >> 2, c4 = (tid & 3) * 4;
        float4 f = *(const float4*)&Fqp[(size_t)(i0 + r) * NF + c4];
        Ks[r * 81 + 64 + c4]     = f2tf32(f.x);
        Ks[r * 81 + 64 + c4 + 1] = f2tf32(f.y);
        Ks[r * 81 + 64 + c4 + 2] = f2tf32(f.z);
        Ks[r * 81 + 64 + c4 + 3] = f2tf32(f.w);
    }
    __syncthreads();
    unsigned afr[10][4];
    #pragma unroll
    for (int s = 0; s < 10; s++) {
        int r = wm * 16 + g, c = s * 8 + tg;
        afr[s][0] = Ks[r * 81 + c];
        afr[s][1] = Ks[(r + 8) * 81 + c];
        afr[s][2] = Ks[r * 81 + c + 4];
        afr[s][3] = Ks[(r + 8) * 81 + c + 4];
    }

    for (int jc = 0; jc < 12; jc++) {
        int j0 = jc * 64;
        float4 rc[4], rq;
        #pragma unroll
        for (int it = 0; it < 4; it++) {
            int fid = tid + 256 * it;
            int r = fid >> 4, c4 = (fid & 15) * 4;
            rc[it] = *(const float4*)&Kp[(size_t)(j0 + r) * HDIM + c4];
        }
        {
            int r = tid >> 2, c4 = (tid & 3) * 4;
            rq = *(const float4*)&Fkp[(size_t)(j0 + r) * NF + c4];
        }
        __syncthreads();
        #pragma unroll
        for (int it = 0; it < 4; it++) {
            int fid = tid + 256 * it;
            int r = fid >> 4, c4 = (fid & 15) * 4;
            Ks[r * 81 + c4]     = f2tf32(rc[it].x);
            Ks[r * 81 + c4 + 1] = f2tf32(rc[it].y);
            Ks[r * 81 + c4 + 2] = f2tf32(rc[it].z);
            Ks[r * 81 + c4 + 3] = f2tf32(rc[it].w);
        }
        {
            int r = tid >> 2, c4 = (tid & 3) * 4;
            Ks[r * 81 + 64 + c4]     = f2tf32(rq.x);
            Ks[r * 81 + 64 + c4 + 1] = f2tf32(rq.y);
            Ks[r * 81 + 64 + c4 + 2] = f2tf32(rq.z);
            Ks[r * 81 + 64 + c4 + 3] = f2tf32(rq.w);
        }
        __syncthreads();

        float accC[4][4] = {}, accQ[4][4] = {};
        #pragma unroll
        for (int s = 0; s < 10; s++) {
            unsigned bfr[4][2];
            #pragma unroll
            for (int nt = 0; nt < 4; nt++) {
                int c = wn * 32 + nt * 8 + g;
                bfr[nt][0] = Ks[c * 81 + s * 8 + tg];
                bfr[nt][1] = Ks[c * 81 + s * 8 + tg + 4];
            }
            #pragma unroll
            for (int nt = 0; nt < 4; nt++) {
                if (s < 8)
                    mma_tf32(accC[nt][0], accC[nt][1], accC[nt][2], accC[nt][3],
                             afr[s][0], afr[s][1], afr[s][2], afr[s][3],
                             bfr[nt][0], bfr[nt][1]);
                else
                    mma_tf32(accQ[nt][0], accQ[nt][1], accQ[nt][2], accQ[nt][3],
                             afr[s][0], afr[s][1], afr[s][2], afr[s][3],
                             bfr[nt][0], bfr[nt][1]);
            }
        }
        #pragma unroll
        for (int nt = 0; nt < 4; nt++) {
            int r  = wm * 16 + g;
            int cl = wn * 32 + nt * 8 + tg * 2;
            #pragma unroll
            for (int hrow = 0; hrow < 2; hrow++) {
                int rr = r + hrow * 8;
                #pragma unroll
                for (int j = 0; j < 2; j++) {
                    int cc = cl + j;
                    float ent = __expf(-0.1f * fabsf((float)((i0 + rr) - (j0 + cc))));
                    P[rr * PROW + j0 + cc] =
                        accC[nt][hrow * 2 + j] + ent * accQ[nt][hrow * 2 + j];
                }
            }
        }
        __syncthreads();
    }

    for (int rr = wid; rr < 64; rr += 8) {
        float* row = P + rr * PROW;
        float v[24];
        float m = -1e30f;
        #pragma unroll
        for (int u = 0; u < 24; u++) { v[u] = row[lane + u * 32]; m = fmaxf(m, v[u]); }
        #pragma unroll
        for (int o = 16; o; o >>= 1) m = fmaxf(m, __shfl_xor_sync(0xffffffffu, m, o));
        float ssum = 0.f;
        #pragma unroll
        for (int u = 0; u < 24; u++) { v[u] = __expf(v[u] - m); ssum += v[u]; }
        #pragma unroll
        for (int o = 16; o; o >>= 1) ssum += __shfl_xor_sync(0xffffffffu, ssum, o);
        float inv = __frcp_rn(ssum);
        #pragma unroll
        for (int u = 0; u < 24; u++) row[lane + u * 32] = v[u] * inv;
    }
    __syncthreads();

    for (int fid = tid; fid < 64 * 192; fid += 256) {
        int r = fid / 192, c4 = fid % 192;
        *(float4*)&scp[(size_t)(i0 + r) * SS + c4 * 4] = *(float4*)&P[r * PROW + c4 * 4];
    }

    unsigned* Vs0 = Ks;
    unsigned* Vs1 = Ks + 64 * 33;
    float acc[4][4] = {};
    float4 vreg[2];
    #pragma unroll
    for (int it = 0; it < 2; it++) {
        int fid = tid + it * 256;
        int kk = fid >> 4, c4 = (fid & 15) * 4;
        vreg[it] = *(const float4*)&Vp[(size_t)kk * HDIM + c4];
    }
    __syncthreads();
    #pragma unroll
    for (int it = 0; it < 2; it++) {
        int fid = tid + it * 256;
        int kk = fid >> 4, c4 = (fid & 15) * 4;
        Vs0[(c4)     * 33 + kk] = f2tf32(vreg[it].x);
        Vs0[(c4 + 1) * 33 + kk] = f2tf32(vreg[it].y);
        Vs0[(c4 + 2) * 33 + kk] = f2tf32(vreg[it].z);
        Vs0[(c4 + 3) * 33 + kk] = f2tf32(vreg[it].w);
    }
    __syncthreads();
    for (int cidx = 0; cidx < SS / 32; cidx++) {
        unsigned* Vc = (cidx & 1) ? Vs1 : Vs0;
        unsigned* Vn = (cidx & 1) ? Vs0 : Vs1;
        int k1 = (cidx + 1) * 32;
        if (k1 < SS) {
            #pragma unroll
            for (int it = 0; it < 2; it++) {
                int fid = tid + it * 256;
                int kk = fid >> 4, c4 = (fid & 15) * 4;
                vreg[it] = *(const float4*)&Vp[(size_t)(k1 + kk) * HDIM + c4];
            }
        }
        int k0 = cidx * 32;
        #pragma unroll
        for (int s = 0; s < 4; s++) {
            int kk = s * 8;
            int r = wm * 16 + g;
            unsigned a0 = f2tf32(P[r * PROW + k0 + kk + tg]);
            unsigned a1 = f2tf32(P[(r + 8) * PROW + k0 + kk + tg]);
            unsigned a2 = f2tf32(P[r * PROW + k0 + kk + tg + 4]);
            unsigned a3 = f2tf32(P[(r + 8) * PROW + k0 + kk + tg + 4]);
            #pragma unroll
            for (int nt = 0; nt < 4; nt++) {
                unsigned b0 = Vc[(wn * 32 + nt * 8 + g) * 33 + kk + tg];
                unsigned b1 = Vc[(wn * 32 + nt * 8 + g) * 33 + kk + tg + 4];
                mma_tf32(acc[nt][0], acc[nt][1], acc[nt][2], acc[nt][3],
                         a0, a1, a2, a3, b0, b1);
            }
        }
        if (k1 < SS) {
            #pragma unroll
            for (int it = 0; it < 2; it++) {
                int fid = tid + it * 256;
                int kk = fid >> 4, c4 = (fid & 15) * 4;
                Vn[(c4)     * 33 + kk] = f2tf32(vreg[it].x);
                Vn[(c4 + 1) * 33 + kk] = f2tf32(vreg[it].y);
                Vn[(c4 + 2) * 33 + kk] = f2tf32(vreg[it].z);
                Vn[(c4 + 3) * 33 + kk] = f2tf32(vreg[it].w);
            }
        }
        __syncthreads();
    }
    #pragma unroll
    for (int nt = 0; nt < 4; nt++) {
        int r = wm * 16 + g;
        int d0 = wn * 32 + nt * 8 + tg * 2;
        #pragma unroll
        for (int hrow = 0; hrow < 2; hrow++) {
            int s_ = i0 + r + hrow * 8;
            #pragma unroll
            for (int j = 0; j < 2; j++) {
                g_att[(size_t)(b * SS + s_) * DDIM + h * HDIM + d0 + j] =
                    acc[nt][hrow * 2 + j];
            }
        }
    }
}

// ---------------- head-mean of attn -> second output ------------------------
__global__ void amean_kernel(float* __restrict__ out2) {
    int idx = blockIdx.x * blockDim.x + threadIdx.x;
    if (idx >= BB * SS * SS / 4) return;
    int b  = idx / (SS * SS / 4);
    int qk = idx % (SS * SS / 4);
    float4 s = make_float4(0.f, 0.f, 0.f, 0.f);
    #pragma unroll
    for (int h = 0; h < HH; h++) {
        const float4* src = (const float4*)(g_sc + (size_t)(b * HH + h) * SS * SS);
        float4 v = src[qk];
        s.x += v.x; s.y += v.y; s.z += v.z; s.w += v.w;
    }
    s.x *= (1.0f / HH); s.y *= (1.0f / HH); s.z *= (1.0f / HH); s.w *= (1.0f / HH);
    ((float4*)out2)[idx] = s;
}

// ---------------- launch -----------------------------------------------------
extern "C" void kernel_launch(void* const* d_in, const int* in_sizes, int n_in,
                              void* d_out, int out_size) {
    const float* query = (const float*)d_in[0];
    const float* key   = (const float*)d_in[1];
    const float* value = (const float*)d_in[2];
    const float* Wq = (const float*)d_in[3];
    const float* bq = (const float*)d_in[4];
    const float* Wk = (const float*)d_in[5];
    const float* bk = (const float*)d_in[6];
    const float* Wv = (const float*)d_in[7];
    const float* bv = (const float*)d_in[8];
    const float* Wo = (const float*)d_in[9];
    const float* bo = (const float*)d_in[10];
    const float* qmapW = (const float*)d_in[11];
    const float* qmapb = (const float*)d_in[12];
    const float* qw    = (const float*)d_in[13];
    const float* ph    = (const float*)d_in[14];
    const float* es    = (const float*)d_in[15];

    float* out  = (float*)d_out;
    float* out2 = out + (size_t)MM * DDIM;

    proj_kernel<<<dim3(DDIM / 128, MM / 128, 3), 256>>>(query, key, value,
                                                        Wq, bq, Wk, bk, Wv, bv);
    {
        int nrows = 2 * BHn * SS;
        qfeat_kernel<<<nrows / 8, 256>>>(qmapW, qmapb, qw, ph, es);
    }
    {
        size_t smem = (size_t)64 * PROW * 4 + (size_t)64 * 81 * 4;
        cudaFuncSetAttribute(attn_kernel,
                             cudaFuncAttributeMaxDynamicSharedMemorySize, (int)smem);
        attn_kernel<<<dim3(SS / 64, BHn), 256, smem>>>(es);
    }
    {
        int n = BB * SS * SS / 4;
        amean_kernel<<<(n + 255) / 256, 256>>>(out2);
    }
    outproj_kernel<<<dim3(DDIM / 128, MM / 128), 256>>>(Wo, bo, out);
}

// round 5
// speedup vs baseline: 2.9628x; 1.1882x over previous
#include <cuda_runtime.h>
#include <math.h>

#define BB   2
#define SS   768
#define DDIM 1024
#define HH   16
#define HDIM 64
#define NQh  8
#define NF   16
#define BHn  (BB*HH)     // 32
#define MM   (BB*SS)     // 1536
#define PROW 772         // 768+4; 772 % 32 == 4 -> conflict-free ldmatrix rows
#define SPITCH 20
#define KPITCH 84        // 84 % 32 == 20 -> conflict-free ldmatrix rows
#define VPITCH 68        // 68 % 32 == 4  -> conflict-free ldmatrix rows

// ---------------- scratch ----------------------------------------------------
__device__ float g_Q[BHn*SS*HDIM];      // [bh][s][d]
__device__ float g_K[BHn*SS*HDIM];      // [bh][s][d]
__device__ float g_V[BHn*SS*HDIM];      // [bh][d][s]  (TRANSPOSED)
__device__ float g_fQ[BHn*SS*NF];
__device__ float g_fK[BHn*SS*NF];
__device__ float g_sc[(size_t)BHn*SS*SS];
__device__ float g_att[MM*DDIM];

// ---------------- helpers ----------------------------------------------------
__device__ __forceinline__ unsigned f2tf32(float f) {
    unsigned u;
    asm("cvt.rna.tf32.f32 %0, %1;" : "=r"(u) : "f"(f));
    return u;
}

__device__ __forceinline__ void mma_tf32(float& c0, float& c1, float& c2, float& c3,
                                         unsigned a0, unsigned a1, unsigned a2, unsigned a3,
                                         unsigned b0, unsigned b1) {
    asm volatile("mma.sync.aligned.m16n8k8.row.col.f32.tf32.tf32.f32 "
                 "{%0,%1,%2,%3}, {%4,%5,%6,%7}, {%8,%9}, {%0,%1,%2,%3};\n"
                 : "+f"(c0), "+f"(c1), "+f"(c2), "+f"(c3)
                 : "r"(a0), "r"(a1), "r"(a2), "r"(a3), "r"(b0), "r"(b1));
}

__device__ __forceinline__ void ldsm_x4(unsigned& r0, unsigned& r1,
                                        unsigned& r2, unsigned& r3, unsigned addr) {
    asm volatile("ldmatrix.sync.aligned.m8n8.x4.shared.b16 {%0,%1,%2,%3}, [%4];"
                 : "=r"(r0), "=r"(r1), "=r"(r2), "=r"(r3) : "r"(addr));
}

// ============================================================================
// tf32 GEMM core for proj/outproj (unchanged from R4)
// ============================================================================
#define GEMM_BODY(LOAD_A0, LOAD_A1, LOAD_B, NCHUNK)                              \
    float acc[4][4][4] = {};                                                     \
    int tid = threadIdx.x;                                                       \
    int wid = tid >> 5, lane = tid & 31;                                         \
    int wm = wid & 1, wnw = wid >> 1;                                            \
    int ar = tid >> 2, ac = (tid & 3) * 4;                                       \
    int bn = tid & 127, bk0 = (tid >> 7) * 8;                                    \
    int a_row = lane & 15, a_koff = (lane >> 4) * 4;                             \
    int b_nr  = (lane & 7) + ((lane >> 4) << 3);                                 \
    int b_koff = ((lane >> 3) & 1) * 4;                                          \
    unsigned aBase0 = (unsigned)__cvta_generic_to_shared(As0);                   \
    unsigned aBase1 = (unsigned)__cvta_generic_to_shared(As1);                   \
    unsigned bBase0 = (unsigned)__cvta_generic_to_shared(Bs0);                   \
    unsigned bBase1 = (unsigned)__cvta_generic_to_shared(Bs1);                   \
    float4 pa0, pa1; float pb[8];                                                \
    { int kg = 0;                                                                \
      pa0 = LOAD_A0(kg); pa1 = LOAD_A1(kg);                                      \
      _Pragma("unroll") for (int j = 0; j < 8; j++) pb[j] = LOAD_B(kg, j); }     \
    { unsigned* As = As0; unsigned* Bs = Bs0;                                    \
      *(uint4*)&As[ar * SPITCH + ac] =                                           \
          make_uint4(f2tf32(pa0.x), f2tf32(pa0.y), f2tf32(pa0.z), f2tf32(pa0.w));\
      *(uint4*)&As[(ar + 64) * SPITCH + ac] =                                    \
          make_uint4(f2tf32(pa1.x), f2tf32(pa1.y), f2tf32(pa1.z), f2tf32(pa1.w));\
      *(uint4*)&Bs[bn * SPITCH + bk0] =                                          \
          make_uint4(f2tf32(pb[0]), f2tf32(pb[1]), f2tf32(pb[2]), f2tf32(pb[3]));\
      *(uint4*)&Bs[bn * SPITCH + bk0 + 4] =                                      \
          make_uint4(f2tf32(pb[4]), f2tf32(pb[5]), f2tf32(pb[6]), f2tf32(pb[7]));}\
    __syncthreads();                                                             \
    for (int ch = 0; ch < (NCHUNK); ch++) {                                      \
        int buf = ch & 1;                                                        \
        if (ch + 1 < (NCHUNK)) {                                                 \
            int kg = (ch + 1) * 16;                                              \
            pa0 = LOAD_A0(kg); pa1 = LOAD_A1(kg);                                \
            _Pragma("unroll") for (int j = 0; j < 8; j++) pb[j] = LOAD_B(kg, j); \
        }                                                                        \
        unsigned aB = buf ? aBase1 : aBase0;                                     \
        unsigned bB = buf ? bBase1 : bBase0;                                     \
        _Pragma("unroll")                                                        \
        for (int ks = 0; ks < 2; ks++) {                                         \
            int kc = ks * 8;                                                     \
            unsigned af[4][4];                                                   \
            _Pragma("unroll")                                                    \
            for (int mt = 0; mt < 4; mt++)                                       \
                ldsm_x4(af[mt][0], af[mt][1], af[mt][2], af[mt][3],              \
                    aB + ((wm * 64 + mt * 16 + a_row) * SPITCH + kc + a_koff) * 4);\
            unsigned bf[4][2];                                                   \
            _Pragma("unroll")                                                    \
            for (int p = 0; p < 2; p++)                                          \
                ldsm_x4(bf[2 * p][0], bf[2 * p][1], bf[2 * p + 1][0],            \
                        bf[2 * p + 1][1],                                        \
                    bB + ((wnw * 32 + p * 16 + b_nr) * SPITCH + kc + b_koff) * 4);\
            _Pragma("unroll")                                                    \
            for (int mt = 0; mt < 4; mt++)                                       \
                _Pragma("unroll")                                                \
                for (int nt = 0; nt < 4; nt++)                                   \
                    mma_tf32(acc[mt][nt][0], acc[mt][nt][1],                     \
                             acc[mt][nt][2], acc[mt][nt][3],                     \
                             af[mt][0], af[mt][1], af[mt][2], af[mt][3],         \
                             bf[nt][0], bf[nt][1]);                              \
        }                                                                        \
        if (ch + 1 < (NCHUNK)) {                                                 \
            unsigned* As = buf ? As0 : As1;                                      \
            unsigned* Bs = buf ? Bs0 : Bs1;                                      \
            *(uint4*)&As[ar * SPITCH + ac] =                                     \
                make_uint4(f2tf32(pa0.x), f2tf32(pa0.y), f2tf32(pa0.z), f2tf32(pa0.w));\
            *(uint4*)&As[(ar + 64) * SPITCH + ac] =                              \
                make_uint4(f2tf32(pa1.x), f2tf32(pa1.y), f2tf32(pa1.z), f2tf32(pa1.w));\
            *(uint4*)&Bs[bn * SPITCH + bk0] =                                    \
                make_uint4(f2tf32(pb[0]), f2tf32(pb[1]), f2tf32(pb[2]), f2tf32(pb[3]));\
            *(uint4*)&Bs[bn * SPITCH + bk0 + 4] =                                \
                make_uint4(f2tf32(pb[4]), f2tf32(pb[5]), f2tf32(pb[6]), f2tf32(pb[7]));\
        }                                                                        \
        __syncthreads();                                                         \
    }

// ---------------- fused QKV projection ---------------------------------------
__global__ __launch_bounds__(256) void proj_kernel(
        const float* __restrict__ q, const float* __restrict__ k,
        const float* __restrict__ v,
        const float* __restrict__ Wq, const float* __restrict__ bq,
        const float* __restrict__ Wk, const float* __restrict__ bk,
        const float* __restrict__ Wv, const float* __restrict__ bv) {
    int which = blockIdx.z;
    const float* A    = (which == 0) ? q  : (which == 1) ? k  : v;
    const float* W    = (which == 0) ? Wq : (which == 1) ? Wk : Wv;
    const float* bias = (which == 0) ? bq : (which == 1) ? bk : bv;
    float*       out  = (which == 0) ? g_Q : (which == 1) ? g_K : g_V;

    __shared__ unsigned As0[128 * SPITCH], As1[128 * SPITCH];
    __shared__ unsigned Bs0[128 * SPITCH], Bs1[128 * SPITCH];
    int row0 = blockIdx.y * 128, col0 = blockIdx.x * 128;

#define LA0(kg) (*(const float4*)&A[(size_t)(row0 + ar) * DDIM + (kg) + ac])
#define LA1(kg) (*(const float4*)&A[(size_t)(row0 + 64 + ar) * DDIM + (kg) + ac])
#define LB(kg, j) (W[(size_t)((kg) + bk0 + (j)) * DDIM + col0 + bn])
    GEMM_BODY(LA0, LA1, LB, DDIM / 16)
#undef LA0
#undef LA1
#undef LB

    int g = lane >> 2, tg = lane & 3;
    #pragma unroll
    for (int mt = 0; mt < 4; mt++)
        #pragma unroll
        for (int nt = 0; nt < 4; nt++) {
            int gm = row0 + wm * 64 + mt * 16 + g;
            int gn = col0 + wnw * 32 + nt * 8 + tg * 2;
            #pragma unroll
            for (int hrow = 0; hrow < 2; hrow++) {
                int m = gm + hrow * 8;
                int b = m / SS, s = m % SS;
                #pragma unroll
                for (int j = 0; j < 2; j++) {
                    int n = gn + j;
                    int h = n >> 6, d = n & 63;
                    float val = acc[mt][nt][hrow * 2 + j] + bias[n];
                    if (which == 2)   // V transposed: [bh][d][s]
                        out[((size_t)(b * HH + h) * HDIM + d) * SS + s] = val;
                    else
                        out[((size_t)(b * HH + h) * SS + s) * HDIM + d] = val;
                }
            }
        }
}

// ---------------- out = attended @ Wo + bo -----------------------------------
__global__ __launch_bounds__(256) void outproj_kernel(const float* __restrict__ Wo,
                                                      const float* __restrict__ bo,
                                                      float* __restrict__ out) {
    __shared__ unsigned As0[128 * SPITCH], As1[128 * SPITCH];
    __shared__ unsigned Bs0[128 * SPITCH], Bs1[128 * SPITCH];
    int row0 = blockIdx.y * 128, col0 = blockIdx.x * 128;

#define LA0(kg) (*(const float4*)&g_att[(size_t)(row0 + ar) * DDIM + (kg) + ac])
#define LA1(kg) (*(const float4*)&g_att[(size_t)(row0 + 64 + ar) * DDIM + (kg) + ac])
#define LB(kg, j) (Wo[(size_t)((kg) + bk0 + (j)) * DDIM + col0 + bn])
    GEMM_BODY(LA0, LA1, LB, DDIM / 16)
#undef LA0
#undef LA1
#undef LB

    int g = lane >> 2, tg = lane & 3;
    #pragma unroll
    for (int mt = 0; mt < 4; mt++)
        #pragma unroll
        for (int nt = 0; nt < 4; nt++) {
            int gm = row0 + wm * 64 + mt * 16 + g;
            int gn = col0 + wnw * 32 + nt * 8 + tg * 2;
            #pragma unroll
            for (int hrow = 0; hrow < 2; hrow++) {
                int m = gm + hrow * 8;
                #pragma unroll
                for (int j = 0; j < 2; j++)
                    out[(size_t)m * DDIM + gn + j] =
                        acc[mt][nt][hrow * 2 + j] + bo[gn + j];
            }
        }
}

// ---------------- quantum features (warp-per-row) ---------------------------
__global__ __launch_bounds__(256) void qfeat_kernel(
        const float* __restrict__ qmapW, const float* __restrict__ qmapb,
        const float* __restrict__ qw, const float* __restrict__ ph,
        const float* __restrict__ es_ptr) {
    int gw   = (blockIdx.x * blockDim.x + threadIdx.x) >> 5;
    int lane = threadIdx.x & 31;
    if (gw >= 2 * BHn * SS) return;
    int side = gw / (BHn * SS);
    int r    = gw % (BHn * SS);
    int h    = (r / SS) % HH;
    const float* row = ((side == 0) ? g_Q : g_K) + (size_t)r * HDIM;
    float rv0 = row[lane], rv1 = row[lane + 32];

    float mydot = 0.f;
    #pragma unroll
    for (int n = 0; n < NQh; n++) {
        float p = rv0 * qmapW[lane * NQh + n] + rv1 * qmapW[(lane + 32) * NQh + n];
        #pragma unroll
        for (int o = 16; o; o >>= 1) p += __shfl_xor_sync(0xffffffffu, p, o);
        if (lane == n) mydot = p;
    }
    if (lane < NQh) {
        float a = tanhf(mydot + qmapb[lane]);
        float s, c;
        if (side == 0) {
            float mix = 1.f / (1.f + __expf(-*es_ptr));
            float w = (1.f / (1.f + __expf(-qw[h * NQh + lane]))) * (1.0f / NQh) * mix;
            sincosf(a + ph[h * NQh + lane], &s, &c);
            g_fQ[(size_t)r * NF + lane]       = w * c;
            g_fQ[(size_t)r * NF + NQh + lane] = w * s;
        } else {
            sincosf(a, &s, &c);
            g_fK[(size_t)r * NF + lane]       = c;
            g_fK[(size_t)r * NF + NQh + lane] = s;
        }
    }
}

// ---------------- fused attention: scores + softmax + AV --------------------
// smem: P[64][PROW] fp32/tf32 + Ks[64][KPITCH] (also reused as Vs[64][VPITCH])
__global__ __launch_bounds__(256) void attn_kernel(const float* __restrict__ es_ptr) {
    extern __shared__ float P[];                       // [64][PROW]
    unsigned* Ks = (unsigned*)(P + 64 * PROW);         // [64][KPITCH]

    int bh = blockIdx.y;
    int b = bh >> 4, h = bh & 15;
    int i0 = blockIdx.x * 64;
    const float* Qp  = g_Q  + (size_t)bh * SS * HDIM;
    const float* Kp  = g_K  + (size_t)bh * SS * HDIM;
    const float* Vtp = g_V  + (size_t)bh * HDIM * SS;  // [d][s]
    const float* Fqp = g_fQ + (size_t)bh * SS * NF;
    const float* Fkp = g_fK + (size_t)bh * SS * NF;
    float* scp = g_sc + (size_t)bh * SS * SS;

    int tid = threadIdx.x;
    int wid = tid >> 5, lane = tid & 31;
    int wm = wid & 3, wn = wid >> 2;
    int g = lane >> 2, tg = lane & 3;
    int a_row = lane & 15, a_koff = (lane >> 4) * 4;
    int b_nr  = (lane & 7) + ((lane >> 4) << 3);
    int b_koff = ((lane >> 3) & 1) * 4;
    unsigned PBase  = (unsigned)__cvta_generic_to_shared(P);
    unsigned KsBase = (unsigned)__cvta_generic_to_shared(Ks);

    float es  = *es_ptr;
    float mix = 1.f / (1.f + __expf(-es));
    float ca  = (1.f - mix) * 0.125f;

    // ---- stage Q(*ca)+Fq into Ks, preload persistent a-fragments -----------
    {
        #pragma unroll
        for (int it = 0; it < 4; it++) {
            int fid = tid + 256 * it;
            int r = fid >> 4, c4 = (fid & 15) * 4;
            float4 f = *(const float4*)&Qp[(size_t)(i0 + r) * HDIM + c4];
            *(uint4*)&Ks[r * KPITCH + c4] =
                make_uint4(f2tf32(ca * f.x), f2tf32(ca * f.y),
                           f2tf32(ca * f.z), f2tf32(ca * f.w));
        }
        int r = tid >> 2, c4 = (tid & 3) * 4;
        float4 f = *(const float4*)&Fqp[(size_t)(i0 + r) * NF + c4];
        *(uint4*)&Ks[r * KPITCH + 64 + c4] =
            make_uint4(f2tf32(f.x), f2tf32(f.y), f2tf32(f.z), f2tf32(f.w));
    }
    __syncthreads();
    unsigned afr[10][4];
    #pragma unroll
    for (int s = 0; s < 10; s++) {
        int r = wm * 16 + g, c = s * 8 + tg;
        afr[s][0] = Ks[r * KPITCH + c];
        afr[s][1] = Ks[(r + 8) * KPITCH + c];
        afr[s][2] = Ks[r * KPITCH + c + 4];
        afr[s][3] = Ks[(r + 8) * KPITCH + c + 4];
    }
    __syncthreads();

    // ---- phase 1: scores over 12 K-chunks (reg-prefetched) -----------------
    float4 rc[4], rq;
    {   // prologue: chunk 0 -> Ks
        #pragma unroll
        for (int it = 0; it < 4; it++) {
            int fid = tid + 256 * it;
            int r = fid >> 4, c4 = (fid & 15) * 4;
            rc[it] = *(const float4*)&Kp[(size_t)r * HDIM + c4];
        }
        { int r = tid >> 2, c4 = (tid & 3) * 4;
          rq = *(const float4*)&Fkp[(size_t)r * NF + c4]; }
        #pragma unroll
        for (int it = 0; it < 4; it++) {
            int fid = tid + 256 * it;
            int r = fid >> 4, c4 = (fid & 15) * 4;
            *(uint4*)&Ks[r * KPITCH + c4] =
                make_uint4(f2tf32(rc[it].x), f2tf32(rc[it].y),
                           f2tf32(rc[it].z), f2tf32(rc[it].w));
        }
        { int r = tid >> 2, c4 = (tid & 3) * 4;
          *(uint4*)&Ks[r * KPITCH + 64 + c4] =
              make_uint4(f2tf32(rq.x), f2tf32(rq.y), f2tf32(rq.z), f2tf32(rq.w)); }
        __syncthreads();
    }
    for (int jc = 0; jc < 12; jc++) {
        int j0 = jc * 64;
        if (jc + 1 < 12) {
            int jn = j0 + 64;
            #pragma unroll
            for (int it = 0; it < 4; it++) {
                int fid = tid + 256 * it;
                int r = fid >> 4, c4 = (fid & 15) * 4;
                rc[it] = *(const float4*)&Kp[(size_t)(jn + r) * HDIM + c4];
            }
            { int r = tid >> 2, c4 = (tid & 3) * 4;
              rq = *(const float4*)&Fkp[(size_t)(jn + r) * NF + c4]; }
        }
        float accC[4][4] = {}, accQ[4][4] = {};
        #pragma unroll
        for (int s = 0; s < 10; s++) {
            int kc = s * 8;
            unsigned bf[4][2];
            #pragma unroll
            for (int p = 0; p < 2; p++)
                ldsm_x4(bf[2 * p][0], bf[2 * p][1], bf[2 * p + 1][0], bf[2 * p + 1][1],
                        KsBase + ((wn * 32 + p * 16 + b_nr) * KPITCH + kc + b_koff) * 4);
            #pragma unroll
            for (int nt = 0; nt < 4; nt++) {
                if (s < 8)
                    mma_tf32(accC[nt][0], accC[nt][1], accC[nt][2], accC[nt][3],
                             afr[s][0], afr[s][1], afr[s][2], afr[s][3],
                             bf[nt][0], bf[nt][1]);
                else
                    mma_tf32(accQ[nt][0], accQ[nt][1], accQ[nt][2], accQ[nt][3],
                             afr[s][0], afr[s][1], afr[s][2], afr[s][3],
                             bf[nt][0], bf[nt][1]);
            }
        }
        // epilogue into P
        #pragma unroll
        for (int nt = 0; nt < 4; nt++) {
            int r  = wm * 16 + g;
            int cl = wn * 32 + nt * 8 + tg * 2;
            #pragma unroll
            for (int hrow = 0; hrow < 2; hrow++) {
                int rr = r + hrow * 8;
                #pragma unroll
                for (int j = 0; j < 2; j++) {
                    int cc = cl + j;
                    float ent = __expf(-0.1f * fabsf((float)((i0 + rr) - (j0 + cc))));
                    P[rr * PROW + j0 + cc] =
                        accC[nt][hrow * 2 + j] + ent * accQ[nt][hrow * 2 + j];
                }
            }
        }
        __syncthreads();
        if (jc + 1 < 12) {
            #pragma unroll
            for (int it = 0; it < 4; it++) {
                int fid = tid + 256 * it;
                int r = fid >> 4, c4 = (fid & 15) * 4;
                *(uint4*)&Ks[r * KPITCH + c4] =
                    make_uint4(f2tf32(rc[it].x), f2tf32(rc[it].y),
                               f2tf32(rc[it].z), f2tf32(rc[it].w));
            }
            { int r = tid >> 2, c4 = (tid & 3) * 4;
              *(uint4*)&Ks[r * KPITCH + 64 + c4] =
                  make_uint4(f2tf32(rq.x), f2tf32(rq.y), f2tf32(rq.z), f2tf32(rq.w)); }
        }
        __syncthreads();
    }

    // ---- phase 2: softmax; write tf32-rounded probs back into P ------------
    for (int rr = wid; rr < 64; rr += 8) {
        float* row = P + rr * PROW;
        float v[24];
        float m = -1e30f;
        #pragma unroll
        for (int u = 0; u < 24; u++) { v[u] = row[lane + u * 32]; m = fmaxf(m, v[u]); }
        #pragma unroll
        for (int o = 16; o; o >>= 1) m = fmaxf(m, __shfl_xor_sync(0xffffffffu, m, o));
        float ssum = 0.f;
        #pragma unroll
        for (int u = 0; u < 24; u++) { v[u] = __expf(v[u] - m); ssum += v[u]; }
        #pragma unroll
        for (int o = 16; o; o >>= 1) ssum += __shfl_xor_sync(0xffffffffu, ssum, o);
        float inv = __frcp_rn(ssum);
        #pragma unroll
        for (int u = 0; u < 24; u++)
            row[lane + u * 32] = __uint_as_float(f2tf32(v[u] * inv));
    }
    __syncthreads();

    // ---- phase 2.5: write attn (tf32-valued floats) to g_sc ----------------
    for (int fid = tid; fid < 64 * 192; fid += 256) {
        int r = fid / 192, c4 = fid % 192;
        *(float4*)&scp[(size_t)(i0 + r) * SS + c4 * 4] = *(float4*)&P[r * PROW + c4 * 4];
    }

    // ---- phase 3: AV via ldmatrix on P and Vs (12 chunks of k=64) ----------
    unsigned* Vs = Ks;          // [64 d][VPITCH]
    float acc[4][4] = {};
    float4 vreg[4];
    {   // prologue: stage chunk 0
        #pragma unroll
        for (int it = 0; it < 4; it++) {
            int q4 = tid + it * 256;
            int d = q4 >> 4, c4 = (q4 & 15) * 4;
            vreg[it] = *(const float4*)&Vtp[(size_t)d * SS + c4];
        }
        __syncthreads();        // Ks free (phase1 done), P ready
        #pragma unroll
        for (int it = 0; it < 4; it++) {
            int q4 = tid + it * 256;
            int d = q4 >> 4, c4 = (q4 & 15) * 4;
            *(uint4*)&Vs[d * VPITCH + c4] =
                make_uint4(f2tf32(vreg[it].x), f2tf32(vreg[it].y),
                           f2tf32(vreg[it].z), f2tf32(vreg[it].w));
        }
        __syncthreads();
    }
    for (int c = 0; c < 12; c++) {
        int k0 = c * 64;
        if (c + 1 < 12) {
            int kn = k0 + 64;
            #pragma unroll
            for (int it = 0; it < 4; it++) {
                int q4 = tid + it * 256;
                int d = q4 >> 4, c4 = (q4 & 15) * 4;
                vreg[it] = *(const float4*)&Vtp[(size_t)d * SS + kn + c4];
            }
        }
        #pragma unroll
        for (int s = 0; s < 8; s++) {
            int kc = s * 8;
            unsigned af[4];
            ldsm_x4(af[0], af[1], af[2], af[3],
                    PBase + ((wm * 16 + a_row) * PROW + k0 + kc + a_koff) * 4);
            unsigned bf[4][2];
            #pragma unroll
            for (int p = 0; p < 2; p++)
                ldsm_x4(bf[2 * p][0], bf[2 * p][1], bf[2 * p + 1][0], bf[2 * p + 1][1],
                        KsBase + ((wn * 32 + p * 16 + b_nr) * VPITCH + kc + b_koff) * 4);
            #pragma unroll
            for (int nt = 0; nt < 4; nt++)
                mma_tf32(acc[nt][0], acc[nt][1], acc[nt][2], acc[nt][3],
                         af[0], af[1], af[2], af[3], bf[nt][0], bf[nt][1]);
        }
        __syncthreads();
        if (c + 1 < 12) {
            #pragma unroll
            for (int it = 0; it < 4; it++) {
                int q4 = tid + it * 256;
                int d = q4 >> 4, c4 = (q4 & 15) * 4;
                *(uint4*)&Vs[d * VPITCH + c4] =
                    make_uint4(f2tf32(vreg[it].x), f2tf32(vreg[it].y),
                               f2tf32(vreg[it].z), f2tf32(vreg[it].w));
            }
        }
        __syncthreads();
    }
    // epilogue -> g_att
    #pragma unroll
    for (int nt = 0; nt < 4; nt++) {
        int r = wm * 16 + g;
        int d0 = wn * 32 + nt * 8 + tg * 2;
        #pragma unroll
        for (int hrow = 0; hrow < 2; hrow++) {
            int s_ = i0 + r + hrow * 8;
            #pragma unroll
            for (int j = 0; j < 2; j++)
                g_att[(size_t)(b * SS + s_) * DDIM + h * HDIM + d0 + j] =
                    acc[nt][hrow * 2 + j];
        }
    }
}

// ---------------- head-mean of attn -> second output ------------------------
__global__ void amean_kernel(float* __restrict__ out2) {
    int idx = blockIdx.x * blockDim.x + threadIdx.x;
    if (idx >= BB * SS * SS / 4) return;
    int b  = idx / (SS * SS / 4);
    int qk = idx % (SS * SS / 4);
    float4 s = make_float4(0.f, 0.f, 0.f, 0.f);
    #pragma unroll
    for (int h = 0; h < HH; h++) {
        const float4* src = (const float4*)(g_sc + (size_t)(b * HH + h) * SS * SS);
        float4 v = src[qk];
        s.x += v.x; s.y += v.y; s.z += v.z; s.w += v.w;
    }
    s.x *= (1.0f / HH); s.y *= (1.0f / HH); s.z *= (1.0f / HH); s.w *= (1.0f / HH);
    ((float4*)out2)[idx] = s;
}

// ---------------- launch -----------------------------------------------------
extern "C" void kernel_launch(void* const* d_in, const int* in_sizes, int n_in,
                              void* d_out, int out_size) {
    const float* query = (const float*)d_in[0];
    const float* key   = (const float*)d_in[1];
    const float* value = (const float*)d_in[2];
    const float* Wq = (const float*)d_in[3];
    const float* bq = (const float*)d_in[4];
    const float* Wk = (const float*)d_in[5];
    const float* bk = (const float*)d_in[6];
    const float* Wv = (const float*)d_in[7];
    const float* bv = (const float*)d_in[8];
    const float* Wo = (const float*)d_in[9];
    const float* bo = (const float*)d_in[10];
    const float* qmapW = (const float*)d_in[11];
    const float* qmapb = (const float*)d_in[12];
    const float* qw    = (const float*)d_in[13];
    const float* ph    = (const float*)d_in[14];
    const float* es    = (const float*)d_in[15];

    float* out  = (float*)d_out;
    float* out2 = out + (size_t)MM * DDIM;

    proj_kernel<<<dim3(DDIM / 128, MM / 128, 3), 256>>>(query, key, value,
                                                        Wq, bq, Wk, bk, Wv, bv);
    {
        int nrows = 2 * BHn * SS;
        qfeat_kernel<<<nrows / 8, 256>>>(qmapW, qmapb, qw, ph, es);
    }
    {
        size_t smem = (size_t)64 * PROW * 4 + (size_t)64 * KPITCH * 4;  // 219136
        cudaFuncSetAttribute(attn_kernel,
                             cudaFuncAttributeMaxDynamicSharedMemorySize, (int)smem);
        attn_kernel<<<dim3(SS / 64, BHn), 256, smem>>>(es);
    }
    {
        int n = BB * SS * SS / 4;
        amean_kernel<<<(n + 255) / 256, 256>>>(out2);
    }
    outproj_kernel<<<dim3(DDIM / 128, MM / 128), 256>>>(Wo, bo, out);
}

// round 6
// speedup vs baseline: 2.9852x; 1.0076x over previous
#include <cuda_runtime.h>
#include <math.h>

#define BB   2
#define SS   768
#define DDIM 1024
#define HH   16
#define HDIM 64
#define NQh  8
#define NF   16
#define BHn  (BB*HH)     // 32
#define MM   (BB*SS)     // 1536
#define PROW 772         // 772 % 32 == 4 -> conflict-free ldmatrix rows
#define SPITCH 20
#define KPITCH 84        // 84 % 32 == 20 -> conflict-free
#define VPITCH 68        // 68 % 32 == 4  -> conflict-free
#define ENTN 831         // LUT entries: (i0-767 .. i0+63) span

// ---------------- scratch ----------------------------------------------------
__device__ float g_Q[BHn*SS*HDIM];      // [bh][s][d]
__device__ float g_K[BHn*SS*HDIM];      // [bh][s][d]
__device__ float g_V[BHn*SS*HDIM];      // [bh][d][s]  (TRANSPOSED)
__device__ float g_fQ[BHn*SS*NF];
__device__ float g_fK[BHn*SS*NF];
__device__ float g_sc[(size_t)BHn*SS*SS];
__device__ float g_att[MM*DDIM];

// ---------------- helpers ----------------------------------------------------
__device__ __forceinline__ unsigned f2tf32(float f) {
    unsigned u;
    asm("cvt.rna.tf32.f32 %0, %1;" : "=r"(u) : "f"(f));
    return u;
}

__device__ __forceinline__ void mma_tf32(float& c0, float& c1, float& c2, float& c3,
                                         unsigned a0, unsigned a1, unsigned a2, unsigned a3,
                                         unsigned b0, unsigned b1) {
    asm volatile("mma.sync.aligned.m16n8k8.row.col.f32.tf32.tf32.f32 "
                 "{%0,%1,%2,%3}, {%4,%5,%6,%7}, {%8,%9}, {%0,%1,%2,%3};\n"
                 : "+f"(c0), "+f"(c1), "+f"(c2), "+f"(c3)
                 : "r"(a0), "r"(a1), "r"(a2), "r"(a3), "r"(b0), "r"(b1));
}

__device__ __forceinline__ void ldsm_x4(unsigned& r0, unsigned& r1,
                                        unsigned& r2, unsigned& r3, unsigned addr) {
    asm volatile("ldmatrix.sync.aligned.m8n8.x4.shared.b16 {%0,%1,%2,%3}, [%4];"
                 : "=r"(r0), "=r"(r1), "=r"(r2), "=r"(r3) : "r"(addr));
}

// ============================================================================
// tf32 GEMM core for proj/outproj
// ============================================================================
#define GEMM_BODY(LOAD_A0, LOAD_A1, LOAD_B, NCHUNK)                              \
    float acc[4][4][4] = {};                                                     \
    int tid = threadIdx.x;                                                       \
    int wid = tid >> 5, lane = tid & 31;                                         \
    int wm = wid & 1, wnw = wid >> 1;                                            \
    int ar = tid >> 2, ac = (tid & 3) * 4;                                       \
    int bn = tid & 127, bk0 = (tid >> 7) * 8;                                    \
    int a_row = lane & 15, a_koff = (lane >> 4) * 4;                             \
    int b_nr  = (lane & 7) + ((lane >> 4) << 3);                                 \
    int b_koff = ((lane >> 3) & 1) * 4;                                          \
    unsigned aBase0 = (unsigned)__cvta_generic_to_shared(As0);                   \
    unsigned aBase1 = (unsigned)__cvta_generic_to_shared(As1);                   \
    unsigned bBase0 = (unsigned)__cvta_generic_to_shared(Bs0);                   \
    unsigned bBase1 = (unsigned)__cvta_generic_to_shared(Bs1);                   \
    float4 pa0, pa1; float pb[8];                                                \
    { int kg = 0;                                                                \
      pa0 = LOAD_A0(kg); pa1 = LOAD_A1(kg);                                      \
      _Pragma("unroll") for (int j = 0; j < 8; j++) pb[j] = LOAD_B(kg, j); }     \
    { unsigned* As = As0; unsigned* Bs = Bs0;                                    \
      *(uint4*)&As[ar * SPITCH + ac] =                                           \
          make_uint4(f2tf32(pa0.x), f2tf32(pa0.y), f2tf32(pa0.z), f2tf32(pa0.w));\
      *(uint4*)&As[(ar + 64) * SPITCH + ac] =                                    \
          make_uint4(f2tf32(pa1.x), f2tf32(pa1.y), f2tf32(pa1.z), f2tf32(pa1.w));\
      *(uint4*)&Bs[bn * SPITCH + bk0] =                                          \
          make_uint4(f2tf32(pb[0]), f2tf32(pb[1]), f2tf32(pb[2]), f2tf32(pb[3]));\
      *(uint4*)&Bs[bn * SPITCH + bk0 + 4] =                                      \
          make_uint4(f2tf32(pb[4]), f2tf32(pb[5]), f2tf32(pb[6]), f2tf32(pb[7]));}\
    __syncthreads();                                                             \
    for (int ch = 0; ch < (NCHUNK); ch++) {                                      \
        int buf = ch & 1;                                                        \
        if (ch + 1 < (NCHUNK)) {                                                 \
            int kg = (ch + 1) * 16;                                              \
            pa0 = LOAD_A0(kg); pa1 = LOAD_A1(kg);                                \
            _Pragma("unroll") for (int j = 0; j < 8; j++) pb[j] = LOAD_B(kg, j); \
        }                                                                        \
        unsigned aB = buf ? aBase1 : aBase0;                                     \
        unsigned bB = buf ? bBase1 : bBase0;                                     \
        _Pragma("unroll")                                                        \
        for (int ks = 0; ks < 2; ks++) {                                         \
            int kc = ks * 8;                                                     \
            unsigned af[4][4];                                                   \
            _Pragma("unroll")                                                    \
            for (int mt = 0; mt < 4; mt++)                                       \
                ldsm_x4(af[mt][0], af[mt][1], af[mt][2], af[mt][3],              \
                    aB + ((wm * 64 + mt * 16 + a_row) * SPITCH + kc + a_koff) * 4);\
            unsigned bf[4][2];                                                   \
            _Pragma("unroll")                                                    \
            for (int p = 0; p < 2; p++)                                          \
                ldsm_x4(bf[2 * p][0], bf[2 * p][1], bf[2 * p + 1][0],            \
                        bf[2 * p + 1][1],                                        \
                    bB + ((wnw * 32 + p * 16 + b_nr) * SPITCH + kc + b_koff) * 4);\
            _Pragma("unroll")                                                    \
            for (int mt = 0; mt < 4; mt++)                                       \
                _Pragma("unroll")                                                \
                for (int nt = 0; nt < 4; nt++)                                   \
                    mma_tf32(acc[mt][nt][0], acc[mt][nt][1],                     \
                             acc[mt][nt][2], acc[mt][nt][3],                     \
                             af[mt][0], af[mt][1], af[mt][2], af[mt][3],         \
                             bf[nt][0], bf[nt][1]);                              \
        }                                                                        \
        if (ch + 1 < (NCHUNK)) {                                                 \
            unsigned* As = buf ? As0 : As1;                                      \
            unsigned* Bs = buf ? Bs0 : Bs1;                                      \
            *(uint4*)&As[ar * SPITCH + ac] =                                     \
                make_uint4(f2tf32(pa0.x), f2tf32(pa0.y), f2tf32(pa0.z), f2tf32(pa0.w));\
            *(uint4*)&As[(ar + 64) * SPITCH + ac] =                              \
                make_uint4(f2tf32(pa1.x), f2tf32(pa1.y), f2tf32(pa1.z), f2tf32(pa1.w));\
            *(uint4*)&Bs[bn * SPITCH + bk0] =                                    \
                make_uint4(f2tf32(pb[0]), f2tf32(pb[1]), f2tf32(pb[2]), f2tf32(pb[3]));\
            *(uint4*)&Bs[bn * SPITCH + bk0 + 4] =                                \
                make_uint4(f2tf32(pb[4]), f2tf32(pb[5]), f2tf32(pb[6]), f2tf32(pb[7]));\
        }                                                                        \
        __syncthreads();                                                         \
    }

// ---------------- fused QKV projection ---------------------------------------
__global__ __launch_bounds__(256) void proj_kernel(
        const float* __restrict__ q, const float* __restrict__ k,
        const float* __restrict__ v,
        const float* __restrict__ Wq, const float* __restrict__ bq,
        const float* __restrict__ Wk, const float* __restrict__ bk,
        const float* __restrict__ Wv, const float* __restrict__ bv) {
    int which = blockIdx.z;
    const float* A    = (which == 0) ? q  : (which == 1) ? k  : v;
    const float* W    = (which == 0) ? Wq : (which == 1) ? Wk : Wv;
    const float* bias = (which == 0) ? bq : (which == 1) ? bk : bv;
    float*       out  = (which == 0) ? g_Q : (which == 1) ? g_K : g_V;

    __shared__ unsigned As0[128 * SPITCH], As1[128 * SPITCH];
    __shared__ unsigned Bs0[128 * SPITCH], Bs1[128 * SPITCH];
    int row0 = blockIdx.y * 128, col0 = blockIdx.x * 128;

#define LA0(kg) (*(const float4*)&A[(size_t)(row0 + ar) * DDIM + (kg) + ac])
#define LA1(kg) (*(const float4*)&A[(size_t)(row0 + 64 + ar) * DDIM + (kg) + ac])
#define LB(kg, j) (W[(size_t)((kg) + bk0 + (j)) * DDIM + col0 + bn])
    GEMM_BODY(LA0, LA1, LB, DDIM / 16)
#undef LA0
#undef LA1
#undef LB

    int g = lane >> 2, tg = lane & 3;
    #pragma unroll
    for (int mt = 0; mt < 4; mt++)
        #pragma unroll
        for (int nt = 0; nt < 4; nt++) {
            int gm = row0 + wm * 64 + mt * 16 + g;
            int gn = col0 + wnw * 32 + nt * 8 + tg * 2;
            #pragma unroll
            for (int hrow = 0; hrow < 2; hrow++) {
                int m = gm + hrow * 8;
                int b = m / SS, s = m % SS;
                #pragma unroll
                for (int j = 0; j < 2; j++) {
                    int n = gn + j;
                    int h = n >> 6, d = n & 63;
                    float val = acc[mt][nt][hrow * 2 + j] + bias[n];
                    if (which == 2)
                        out[((size_t)(b * HH + h) * HDIM + d) * SS + s] = val;
                    else
                        out[((size_t)(b * HH + h) * SS + s) * HDIM + d] = val;
                }
            }
        }
}

// ---------------- out = attended @ Wo + bo -----------------------------------
__global__ __launch_bounds__(256) void outproj_kernel(const float* __restrict__ Wo,
                                                      const float* __restrict__ bo,
                                                      float* __restrict__ out) {
    __shared__ unsigned As0[128 * SPITCH], As1[128 * SPITCH];
    __shared__ unsigned Bs0[128 * SPITCH], Bs1[128 * SPITCH];
    int row0 = blockIdx.y * 128, col0 = blockIdx.x * 128;

#define LA0(kg) (*(const float4*)&g_att[(size_t)(row0 + ar) * DDIM + (kg) + ac])
#define LA1(kg) (*(const float4*)&g_att[(size_t)(row0 + 64 + ar) * DDIM + (kg) + ac])
#define LB(kg, j) (Wo[(size_t)((kg) + bk0 + (j)) * DDIM + col0 + bn])
    GEMM_BODY(LA0, LA1, LB, DDIM / 16)
#undef LA0
#undef LA1
#undef LB

    int g = lane >> 2, tg = lane & 3;
    #pragma unroll
    for (int mt = 0; mt < 4; mt++)
        #pragma unroll
        for (int nt = 0; nt < 4; nt++) {
            int gm = row0 + wm * 64 + mt * 16 + g;
            int gn = col0 + wnw * 32 + nt * 8 + tg * 2;
            #pragma unroll
            for (int hrow = 0; hrow < 2; hrow++) {
                int m = gm + hrow * 8;
                #pragma unroll
                for (int j = 0; j < 2; j++)
                    out[(size_t)m * DDIM + gn + j] =
                        acc[mt][nt][hrow * 2 + j] + bo[gn + j];
            }
        }
}

// ---------------- quantum features (warp-per-row) ---------------------------
__global__ __launch_bounds__(256) void qfeat_kernel(
        const float* __restrict__ qmapW, const float* __restrict__ qmapb,
        const float* __restrict__ qw, const float* __restrict__ ph,
        const float* __restrict__ es_ptr) {
    int gw   = (blockIdx.x * blockDim.x + threadIdx.x) >> 5;
    int lane = threadIdx.x & 31;
    if (gw >= 2 * BHn * SS) return;
    int side = gw / (BHn * SS);
    int r    = gw % (BHn * SS);
    int h    = (r / SS) % HH;
    const float* row = ((side == 0) ? g_Q : g_K) + (size_t)r * HDIM;
    float rv0 = row[lane], rv1 = row[lane + 32];

    float mydot = 0.f;
    #pragma unroll
    for (int n = 0; n < NQh; n++) {
        float p = rv0 * qmapW[lane * NQh + n] + rv1 * qmapW[(lane + 32) * NQh + n];
        #pragma unroll
        for (int o = 16; o; o >>= 1) p += __shfl_xor_sync(0xffffffffu, p, o);
        if (lane == n) mydot = p;
    }
    if (lane < NQh) {
        float a = tanhf(mydot + qmapb[lane]);
        float s, c;
        if (side == 0) {
            float mix = 1.f / (1.f + __expf(-*es_ptr));
            float w = (1.f / (1.f + __expf(-qw[h * NQh + lane]))) * (1.0f / NQh) * mix;
            sincosf(a + ph[h * NQh + lane], &s, &c);
            g_fQ[(size_t)r * NF + lane]       = w * c;
            g_fQ[(size_t)r * NF + NQh + lane] = w * s;
        } else {
            sincosf(a, &s, &c);
            g_fK[(size_t)r * NF + lane]       = c;
            g_fK[(size_t)r * NF + NQh + lane] = s;
        }
    }
}

// ---------------- fused attention: scores + softmax + AV --------------------
// smem layout (floats): P[64*PROW] | region[8704]
//   phase 1: region = Ks[64*KPITCH] (5376 u32) + entLUT[831]
//   phase 3: region = Vs0[64*VPITCH] + Vs1[64*VPITCH] (4352 u32 each)
__global__ __launch_bounds__(256) void attn_kernel(const float* __restrict__ es_ptr) {
    extern __shared__ float P[];                       // [64][PROW]
    unsigned* Ks   = (unsigned*)(P + 64 * PROW);       // phase 1
    float*    entT = (float*)(Ks + 64 * KPITCH);       // phase 1 LUT
    unsigned* Vs0  = (unsigned*)(P + 64 * PROW);       // phase 3
    unsigned* Vs1  = Vs0 + 64 * VPITCH;

    int bh = blockIdx.y;
    int b = bh >> 4, h = bh & 15;
    int i0 = blockIdx.x * 64;
    const float* Qp  = g_Q  + (size_t)bh * SS * HDIM;
    const float* Kp  = g_K  + (size_t)bh * SS * HDIM;
    const float* Vtp = g_V  + (size_t)bh * HDIM * SS;  // [d][s]
    const float* Fqp = g_fQ + (size_t)bh * SS * NF;
    const float* Fkp = g_fK + (size_t)bh * SS * NF;
    float* scp = g_sc + (size_t)bh * SS * SS;

    int tid = threadIdx.x;
    int wid = tid >> 5, lane = tid & 31;
    int wm = wid & 3, wn = wid >> 2;
    int g = lane >> 2, tg = lane & 3;
    int a_row = lane & 15, a_koff = (lane >> 4) * 4;
    int b_nr  = (lane & 7) + ((lane >> 4) << 3);
    int b_koff = ((lane >> 3) & 1) * 4;
    unsigned PBase   = (unsigned)__cvta_generic_to_shared(P);
    unsigned KsBase  = (unsigned)__cvta_generic_to_shared(Ks);
    unsigned VsBase0 = (unsigned)__cvta_generic_to_shared(Vs0);
    unsigned VsBase1 = (unsigned)__cvta_generic_to_shared(Vs1);

    float es  = *es_ptr;
    float mix = 1.f / (1.f + __expf(-es));
    float ca  = (1.f - mix) * 0.125f;

    // ---- ent LUT: entT[t] = exp(-0.1*|i0 - 767 + t|), t in [0, ENTN) ------
    for (int t = tid; t < ENTN; t += 256)
        entT[t] = __expf(-0.1f * fabsf((float)(i0 - 767 + t)));

    // ---- stage Q(*ca)+Fq into Ks, preload persistent a-fragments -----------
    {
        #pragma unroll
        for (int it = 0; it < 4; it++) {
            int fid = tid + 256 * it;
            int r = fid >> 4, c4 = (fid & 15) * 4;
            float4 f = *(const float4*)&Qp[(size_t)(i0 + r) * HDIM + c4];
            *(uint4*)&Ks[r * KPITCH + c4] =
                make_uint4(f2tf32(ca * f.x), f2tf32(ca * f.y),
                           f2tf32(ca * f.z), f2tf32(ca * f.w));
        }
        int r = tid >> 2, c4 = (tid & 3) * 4;
        float4 f = *(const float4*)&Fqp[(size_t)(i0 + r) * NF + c4];
        *(uint4*)&Ks[r * KPITCH + 64 + c4] =
            make_uint4(f2tf32(f.x), f2tf32(f.y), f2tf32(f.z), f2tf32(f.w));
    }
    __syncthreads();
    unsigned afr[10][4];
    #pragma unroll
    for (int s = 0; s < 10; s++) {
        int r = wm * 16 + g, c = s * 8 + tg;
        afr[s][0] = Ks[r * KPITCH + c];
        afr[s][1] = Ks[(r + 8) * KPITCH + c];
        afr[s][2] = Ks[r * KPITCH + c + 4];
        afr[s][3] = Ks[(r + 8) * KPITCH + c + 4];
    }
    __syncthreads();

    // ---- phase 1: scores over 12 K-chunks (reg-prefetched) -----------------
    float4 rc[4], rq;
    {   // prologue: chunk 0 -> Ks
        #pragma unroll
        for (int it = 0; it < 4; it++) {
            int fid = tid + 256 * it;
            int r = fid >> 4, c4 = (fid & 15) * 4;
            rc[it] = *(const float4*)&Kp[(size_t)r * HDIM + c4];
        }
        { int r = tid >> 2, c4 = (tid & 3) * 4;
          rq = *(const float4*)&Fkp[(size_t)r * NF + c4]; }
        #pragma unroll
        for (int it = 0; it < 4; it++) {
            int fid = tid + 256 * it;
            int r = fid >> 4, c4 = (fid & 15) * 4;
            *(uint4*)&Ks[r * KPITCH + c4] =
                make_uint4(f2tf32(rc[it].x), f2tf32(rc[it].y),
                           f2tf32(rc[it].z), f2tf32(rc[it].w));
        }
        { int r = tid >> 2, c4 = (tid & 3) * 4;
          *(uint4*)&Ks[r * KPITCH + 64 + c4] =
              make_uint4(f2tf32(rq.x), f2tf32(rq.y), f2tf32(rq.z), f2tf32(rq.w)); }
        __syncthreads();
    }
    for (int jc = 0; jc < 12; jc++) {
        int j0 = jc * 64;
        if (jc + 1 < 12) {
            int jn = j0 + 64;
            #pragma unroll
            for (int it = 0; it < 4; it++) {
                int fid = tid + 256 * it;
                int r = fid >> 4, c4 = (fid & 15) * 4;
                rc[it] = *(const float4*)&Kp[(size_t)(jn + r) * HDIM + c4];
            }
            { int r = tid >> 2, c4 = (tid & 3) * 4;
              rq = *(const float4*)&Fkp[(size_t)(jn + r) * NF + c4]; }
        }
        float accC[4][4] = {}, accQ[4][4] = {};
        #pragma unroll
        for (int s = 0; s < 10; s++) {
            int kc = s * 8;
            unsigned bf[4][2];
            #pragma unroll
            for (int p = 0; p < 2; p++)
                ldsm_x4(bf[2 * p][0], bf[2 * p][1], bf[2 * p + 1][0], bf[2 * p + 1][1],
                        KsBase + ((wn * 32 + p * 16 + b_nr) * KPITCH + kc + b_koff) * 4);
            #pragma unroll
            for (int nt = 0; nt < 4; nt++) {
                if (s < 8)
                    mma_tf32(accC[nt][0], accC[nt][1], accC[nt][2], accC[nt][3],
                             afr[s][0], afr[s][1], afr[s][2], afr[s][3],
                             bf[nt][0], bf[nt][1]);
                else
                    mma_tf32(accQ[nt][0], accQ[nt][1], accQ[nt][2], accQ[nt][3],
                             afr[s][0], afr[s][1], afr[s][2], afr[s][3],
                             bf[nt][0], bf[nt][1]);
            }
        }
        // epilogue into P (ent via LUT; float2 stores)
        #pragma unroll
        for (int nt = 0; nt < 4; nt++) {
            int r  = wm * 16 + g;
            int cl = wn * 32 + nt * 8 + tg * 2;
            #pragma unroll
            for (int hrow = 0; hrow < 2; hrow++) {
                int rr = r + hrow * 8;
                int base = rr + 767 - j0 - cl;     // LUT idx for j=0
                float e0 = entT[base];
                float e1 = entT[base - 1];
                float2 st;
                st.x = accC[nt][hrow * 2]     + e0 * accQ[nt][hrow * 2];
                st.y = accC[nt][hrow * 2 + 1] + e1 * accQ[nt][hrow * 2 + 1];
                *(float2*)&P[rr * PROW + j0 + cl] = st;
            }
        }
        __syncthreads();
        if (jc + 1 < 12) {
            #pragma unroll
            for (int it = 0; it < 4; it++) {
                int fid = tid + 256 * it;
                int r = fid >> 4, c4 = (fid & 15) * 4;
                *(uint4*)&Ks[r * KPITCH + c4] =
                    make_uint4(f2tf32(rc[it].x), f2tf32(rc[it].y),
                               f2tf32(rc[it].z), f2tf32(rc[it].w));
            }
            { int r = tid >> 2, c4 = (tid & 3) * 4;
              *(uint4*)&Ks[r * KPITCH + 64 + c4] =
                  make_uint4(f2tf32(rq.x), f2tf32(rq.y), f2tf32(rq.z), f2tf32(rq.w)); }
        }
        __syncthreads();
    }

    // ---- phase 2: softmax (float4) + fused g_sc writeback ------------------
    for (int rr = wid; rr < 64; rr += 8) {
        float4* row4 = (float4*)(P + rr * PROW);
        float4 v[6];
        float m = -1e30f;
        #pragma unroll
        for (int u = 0; u < 6; u++) {
            v[u] = row4[lane + u * 32];
            m = fmaxf(m, fmaxf(fmaxf(v[u].x, v[u].y), fmaxf(v[u].z, v[u].w)));
        }
        #pragma unroll
        for (int o = 16; o; o >>= 1) m = fmaxf(m, __shfl_xor_sync(0xffffffffu, m, o));
        float ssum = 0.f;
        #pragma unroll
        for (int u = 0; u < 6; u++) {
            v[u].x = __expf(v[u].x - m); v[u].y = __expf(v[u].y - m);
            v[u].z = __expf(v[u].z - m); v[u].w = __expf(v[u].w - m);
            ssum += (v[u].x + v[u].y) + (v[u].z + v[u].w);
        }
        #pragma unroll
        for (int o = 16; o; o >>= 1) ssum += __shfl_xor_sync(0xffffffffu, ssum, o);
        float inv = __frcp_rn(ssum);
        float4* out4 = (float4*)(scp + (size_t)(i0 + rr) * SS);
        #pragma unroll
        for (int u = 0; u < 6; u++) {
            float4 t;
            t.x = __uint_as_float(f2tf32(v[u].x * inv));
            t.y = __uint_as_float(f2tf32(v[u].y * inv));
            t.z = __uint_as_float(f2tf32(v[u].z * inv));
            t.w = __uint_as_float(f2tf32(v[u].w * inv));
            row4[lane + u * 32] = t;
            out4[lane + u * 32] = t;
        }
    }

    // ---- phase 3: AV via ldmatrix on P and double-buffered Vs --------------
    float acc[4][4] = {};
    float4 vreg[4];
    {   // prologue: stage chunk 0 into Vs0
        #pragma unroll
        for (int it = 0; it < 4; it++) {
            int q4 = tid + it * 256;
            int d = q4 >> 4, c4 = (q4 & 15) * 4;
            vreg[it] = *(const float4*)&Vtp[(size_t)d * SS + c4];
        }
        __syncthreads();        // phase-1/2 use of region + P writes complete
        #pragma unroll
        for (int it = 0; it < 4; it++) {
            int q4 = tid + it * 256;
            int d = q4 >> 4, c4 = (q4 & 15) * 4;
            *(uint4*)&Vs0[d * VPITCH + c4] =
                make_uint4(f2tf32(vreg[it].x), f2tf32(vreg[it].y),
                           f2tf32(vreg[it].z), f2tf32(vreg[it].w));
        }
        __syncthreads();
    }
    for (int c = 0; c < 12; c++) {
        int k0 = c * 64;
        unsigned curB = (c & 1) ? VsBase1 : VsBase0;
        unsigned* nxt = (c & 1) ? Vs0 : Vs1;
        if (c + 1 < 12) {
            int kn = k0 + 64;
            #pragma unroll
            for (int it = 0; it < 4; it++) {
                int q4 = tid + it * 256;
                int d = q4 >> 4, c4 = (q4 & 15) * 4;
                vreg[it] = *(const float4*)&Vtp[(size_t)d * SS + kn + c4];
            }
        }
        #pragma unroll
        for (int s = 0; s < 8; s++) {
            int kc = s * 8;
            unsigned af[4];
            ldsm_x4(af[0], af[1], af[2], af[3],
                    PBase + ((wm * 16 + a_row) * PROW + k0 + kc + a_koff) * 4);
            unsigned bf[4][2];
            #pragma unroll
            for (int p = 0; p < 2; p++)
                ldsm_x4(bf[2 * p][0], bf[2 * p][1], bf[2 * p + 1][0], bf[2 * p + 1][1],
                        curB + ((wn * 32 + p * 16 + b_nr) * VPITCH + kc + b_koff) * 4);
            #pragma unroll
            for (int nt = 0; nt < 4; nt++)
                mma_tf32(acc[nt][0], acc[nt][1], acc[nt][2], acc[nt][3],
                         af[0], af[1], af[2], af[3], bf[nt][0], bf[nt][1]);
        }
        if (c + 1 < 12) {   // store next buffer (no hazard with current readers)
            #pragma unroll
            for (int it = 0; it < 4; it++) {
                int q4 = tid + it * 256;
                int d = q4 >> 4, c4 = (q4 & 15) * 4;
                *(uint4*)&nxt[d * VPITCH + c4] =
                    make_uint4(f2tf32(vreg[it].x), f2tf32(vreg[it].y),
                               f2tf32(vreg[it].z), f2tf32(vreg[it].w));
            }
        }
        __syncthreads();
    }
    // epilogue -> g_att
    #pragma unroll
    for (int nt = 0; nt < 4; nt++) {
        int r = wm * 16 + g;
        int d0 = wn * 32 + nt * 8 + tg * 2;
        #pragma unroll
        for (int hrow = 0; hrow < 2; hrow++) {
            int s_ = i0 + r + hrow * 8;
            *(float2*)&g_att[(size_t)(b * SS + s_) * DDIM + h * HDIM + d0] =
                make_float2(acc[nt][hrow * 2], acc[nt][hrow * 2 + 1]);
        }
    }
}

// ---------------- head-mean of attn -> second output ------------------------
__global__ void amean_kernel(float* __restrict__ out2) {
    int idx = blockIdx.x * blockDim.x + threadIdx.x;
    if (idx >= BB * SS * SS / 4) return;
    int b  = idx / (SS * SS / 4);
    int qk = idx % (SS * SS / 4);
    float4 s = make_float4(0.f, 0.f, 0.f, 0.f);
    #pragma unroll
    for (int h = 0; h < HH; h++) {
        const float4* src = (const float4*)(g_sc + (size_t)(b * HH + h) * SS * SS);
        float4 v = src[qk];
        s.x += v.x; s.y += v.y; s.z += v.z; s.w += v.w;
    }
    s.x *= (1.0f / HH); s.y *= (1.0f / HH); s.z *= (1.0f / HH); s.w *= (1.0f / HH);
    ((float4*)out2)[idx] = s;
}

// ---------------- launch -----------------------------------------------------
extern "C" void kernel_launch(void* const* d_in, const int* in_sizes, int n_in,
                              void* d_out, int out_size) {
    const float* query = (const float*)d_in[0];
    const float* key   = (const float*)d_in[1];
    const float* value = (const float*)d_in[2];
    const float* Wq = (const float*)d_in[3];
    const float* bq = (const float*)d_in[4];
    const float* Wk = (const float*)d_in[5];
    const float* bk = (const float*)d_in[6];
    const float* Wv = (const float*)d_in[7];
    const float* bv = (const float*)d_in[8];
    const float* Wo = (const float*)d_in[9];
    const float* bo = (const float*)d_in[10];
    const float* qmapW = (const float*)d_in[11];
    const float* qmapb = (const float*)d_in[12];
    const float* qw    = (const float*)d_in[13];
    const float* ph    = (const float*)d_in[14];
    const float* es    = (const float*)d_in[15];

    float* out  = (float*)d_out;
    float* out2 = out + (size_t)MM * DDIM;

    proj_kernel<<<dim3(DDIM / 128, MM / 128, 3), 256>>>(query, key, value,
                                                        Wq, bq, Wk, bk, Wv, bv);
    {
        int nrows = 2 * BHn * SS;
        qfeat_kernel<<<nrows / 8, 256>>>(qmapW, qmapb, qw, ph, es);
    }
    {
        // P (64*PROW floats) + phase-3 region (2 * 64*VPITCH u32) = 227 KB
        size_t smem = (size_t)64 * PROW * 4 + (size_t)2 * 64 * VPITCH * 4; // 232448
        cudaFuncSetAttribute(attn_kernel,
                             cudaFuncAttributeMaxDynamicSharedMemorySize, (int)smem);
        attn_kernel<<<dim3(SS / 64, BHn), 256, smem>>>(es);
    }
    {
        int n = BB * SS * SS / 4;
        amean_kernel<<<(n + 255) / 256, 256>>>(out2);
    }
    outproj_kernel<<<dim3(DDIM / 128, MM / 128), 256>>>(Wo, bo, out);
}

// round 7
// speedup vs baseline: 3.1774x; 1.0644x over previous
#include <cuda_runtime.h>
#include <math.h>

#define BB   2
#define SS   768
#define DDIM 1024
#define HH   16
#define HDIM 64
#define NQh  8
#define NF   16
#define BHn  (BB*HH)     // 32
#define MM   (BB*SS)     // 1536
#define PROW 772         // 772 % 32 == 4 -> conflict-free ldmatrix rows
#define SPITCH 20
#define KPITCH 84        // 84 % 32 == 20 -> conflict-free
#define VPITCH 68        // 68 % 32 == 4  -> conflict-free
#define ENTN 831

// ---------------- scratch ----------------------------------------------------
__device__ float g_Q[BHn*SS*HDIM];      // [bh][s][d]
__device__ float g_K[BHn*SS*HDIM];      // [bh][s][d]
__device__ float g_V[BHn*SS*HDIM];      // [bh][d][s]  (TRANSPOSED)
__device__ float g_fQ[BHn*SS*NF];
__device__ float g_fK[BHn*SS*NF];
__device__ float g_att[MM*DDIM];

// ---------------- helpers ----------------------------------------------------
__device__ __forceinline__ unsigned f2tf32(float f) {
    unsigned u;
    asm("cvt.rna.tf32.f32 %0, %1;" : "=r"(u) : "f"(f));
    return u;
}

__device__ __forceinline__ void mma_tf32(float& c0, float& c1, float& c2, float& c3,
                                         unsigned a0, unsigned a1, unsigned a2, unsigned a3,
                                         unsigned b0, unsigned b1) {
    asm volatile("mma.sync.aligned.m16n8k8.row.col.f32.tf32.tf32.f32 "
                 "{%0,%1,%2,%3}, {%4,%5,%6,%7}, {%8,%9}, {%0,%1,%2,%3};\n"
                 : "+f"(c0), "+f"(c1), "+f"(c2), "+f"(c3)
                 : "r"(a0), "r"(a1), "r"(a2), "r"(a3), "r"(b0), "r"(b1));
}

__device__ __forceinline__ void ldsm_x4(unsigned& r0, unsigned& r1,
                                        unsigned& r2, unsigned& r3, unsigned addr) {
    asm volatile("ldmatrix.sync.aligned.m8n8.x4.shared.b16 {%0,%1,%2,%3}, [%4];"
                 : "=r"(r0), "=r"(r1), "=r"(r2), "=r"(r3) : "r"(addr));
}

__device__ __forceinline__ void red_add_v4(float* p, float x, float y, float z, float w) {
    asm volatile("red.global.add.v4.f32 [%0], {%1,%2,%3,%4};"
                 :: "l"(p), "f"(x), "f"(y), "f"(z), "f"(w) : "memory");
}

// ============================================================================
// tf32 GEMM core for proj/outproj
// ============================================================================
#define GEMM_BODY(LOAD_A0, LOAD_A1, LOAD_B, NCHUNK)                              \
    float acc[4][4][4] = {};                                                     \
    int tid = threadIdx.x;                                                       \
    int wid = tid >> 5, lane = tid & 31;                                         \
    int wm = wid & 1, wnw = wid >> 1;                                            \
    int ar = tid >> 2, ac = (tid & 3) * 4;                                       \
    int bn = tid & 127, bk0 = (tid >> 7) * 8;                                    \
    int a_row = lane & 15, a_koff = (lane >> 4) * 4;                             \
    int b_nr  = (lane & 7) + ((lane >> 4) << 3);                                 \
    int b_koff = ((lane >> 3) & 1) * 4;                                          \
    unsigned aBase0 = (unsigned)__cvta_generic_to_shared(As0);                   \
    unsigned aBase1 = (unsigned)__cvta_generic_to_shared(As1);                   \
    unsigned bBase0 = (unsigned)__cvta_generic_to_shared(Bs0);                   \
    unsigned bBase1 = (unsigned)__cvta_generic_to_shared(Bs1);                   \
    float4 pa0, pa1; float pb[8];                                                \
    { int kg = 0;                                                                \
      pa0 = LOAD_A0(kg); pa1 = LOAD_A1(kg);                                      \
      _Pragma("unroll") for (int j = 0; j < 8; j++) pb[j] = LOAD_B(kg, j); }     \
    { unsigned* As = As0; unsigned* Bs = Bs0;                                    \
      *(uint4*)&As[ar * SPITCH + ac] =                                           \
          make_uint4(f2tf32(pa0.x), f2tf32(pa0.y), f2tf32(pa0.z), f2tf32(pa0.w));\
      *(uint4*)&As[(ar + 64) * SPITCH + ac] =                                    \
          make_uint4(f2tf32(pa1.x), f2tf32(pa1.y), f2tf32(pa1.z), f2tf32(pa1.w));\
      *(uint4*)&Bs[bn * SPITCH + bk0] =                                          \
          make_uint4(f2tf32(pb[0]), f2tf32(pb[1]), f2tf32(pb[2]), f2tf32(pb[3]));\
      *(uint4*)&Bs[bn * SPITCH + bk0 + 4] =                                      \
          make_uint4(f2tf32(pb[4]), f2tf32(pb[5]), f2tf32(pb[6]), f2tf32(pb[7]));}\
    __syncthreads();                                                             \
    for (int ch = 0; ch < (NCHUNK); ch++) {                                      \
        int buf = ch & 1;                                                        \
        if (ch + 1 < (NCHUNK)) {                                                 \
            int kg = (ch + 1) * 16;                                              \
            pa0 = LOAD_A0(kg); pa1 = LOAD_A1(kg);                                \
            _Pragma("unroll") for (int j = 0; j < 8; j++) pb[j] = LOAD_B(kg, j); \
        }                                                                        \
        unsigned aB = buf ? aBase1 : aBase0;                                     \
        unsigned bB = buf ? bBase1 : bBase0;                                     \
        _Pragma("unroll")                                                        \
        for (int ks = 0; ks < 2; ks++) {                                         \
            int kc = ks * 8;                                                     \
            unsigned af[4][4];                                                   \
            _Pragma("unroll")                                                    \
            for (int mt = 0; mt < 4; mt++)                                       \
                ldsm_x4(af[mt][0], af[mt][1], af[mt][2], af[mt][3],              \
                    aB + ((wm * 64 + mt * 16 + a_row) * SPITCH + kc + a_koff) * 4);\
            unsigned bf[4][2];                                                   \
            _Pragma("unroll")                                                    \
            for (int p = 0; p < 2; p++)                                          \
                ldsm_x4(bf[2 * p][0], bf[2 * p][1], bf[2 * p + 1][0],            \
                        bf[2 * p + 1][1],                                        \
                    bB + ((wnw * 32 + p * 16 + b_nr) * SPITCH + kc + b_koff) * 4);\
            _Pragma("unroll")                                                    \
            for (int mt = 0; mt < 4; mt++)                                       \
                _Pragma("unroll")                                                \
                for (int nt = 0; nt < 4; nt++)                                   \
                    mma_tf32(acc[mt][nt][0], acc[mt][nt][1],                     \
                             acc[mt][nt][2], acc[mt][nt][3],                     \
                             af[mt][0], af[mt][1], af[mt][2], af[mt][3],         \
                             bf[nt][0], bf[nt][1]);                              \
        }                                                                        \
        if (ch + 1 < (NCHUNK)) {                                                 \
            unsigned* As = buf ? As0 : As1;                                      \
            unsigned* Bs = buf ? Bs0 : Bs1;                                      \
            *(uint4*)&As[ar * SPITCH + ac] =                                     \
                make_uint4(f2tf32(pa0.x), f2tf32(pa0.y), f2tf32(pa0.z), f2tf32(pa0.w));\
            *(uint4*)&As[(ar + 64) * SPITCH + ac] =                              \
                make_uint4(f2tf32(pa1.x), f2tf32(pa1.y), f2tf32(pa1.z), f2tf32(pa1.w));\
            *(uint4*)&Bs[bn * SPITCH + bk0] =                                    \
                make_uint4(f2tf32(pb[0]), f2tf32(pb[1]), f2tf32(pb[2]), f2tf32(pb[3]));\
            *(uint4*)&Bs[bn * SPITCH + bk0 + 4] =                                \
                make_uint4(f2tf32(pb[4]), f2tf32(pb[5]), f2tf32(pb[6]), f2tf32(pb[7]));\
        }                                                                        \
        __syncthreads();                                                         \
    }

// ---------------- fused QKV projection ---------------------------------------
__global__ __launch_bounds__(256) void proj_kernel(
        const float* __restrict__ q, const float* __restrict__ k,
        const float* __restrict__ v,
        const float* __restrict__ Wq, const float* __restrict__ bq,
        const float* __restrict__ Wk, const float* __restrict__ bk,
        const float* __restrict__ Wv, const float* __restrict__ bv) {
    int which = blockIdx.z;
    const float* A    = (which == 0) ? q  : (which == 1) ? k  : v;
    const float* W    = (which == 0) ? Wq : (which == 1) ? Wk : Wv;
    const float* bias = (which == 0) ? bq : (which == 1) ? bk : bv;
    float*       out  = (which == 0) ? g_Q : (which == 1) ? g_K : g_V;

    __shared__ unsigned As0[128 * SPITCH], As1[128 * SPITCH];
    __shared__ unsigned Bs0[128 * SPITCH], Bs1[128 * SPITCH];
    int row0 = blockIdx.y * 128, col0 = blockIdx.x * 128;

#define LA0(kg) (*(const float4*)&A[(size_t)(row0 + ar) * DDIM + (kg) + ac])
#define LA1(kg) (*(const float4*)&A[(size_t)(row0 + 64 + ar) * DDIM + (kg) + ac])
#define LB(kg, j) (W[(size_t)((kg) + bk0 + (j)) * DDIM + col0 + bn])
    GEMM_BODY(LA0, LA1, LB, DDIM / 16)
#undef LA0
#undef LA1
#undef LB

    int g = lane >> 2, tg = lane & 3;
    #pragma unroll
    for (int mt = 0; mt < 4; mt++)
        #pragma unroll
        for (int nt = 0; nt < 4; nt++) {
            int gm = row0 + wm * 64 + mt * 16 + g;
            int gn = col0 + wnw * 32 + nt * 8 + tg * 2;
            #pragma unroll
            for (int hrow = 0; hrow < 2; hrow++) {
                int m = gm + hrow * 8;
                int b = m / SS, s = m % SS;
                int h = gn >> 6, d = gn & 63;
                if (which == 2) {   // V transposed: [bh][d][s]
                    #pragma unroll
                    for (int j = 0; j < 2; j++)
                        out[((size_t)(b * HH + h) * HDIM + d + j) * SS + s] =
                            acc[mt][nt][hrow * 2 + j] + bias[gn + j];
                } else {            // Q/K: [bh][s][d], d,d+1 contiguous
                    float2 st;
                    st.x = acc[mt][nt][hrow * 2]     + bias[gn];
                    st.y = acc[mt][nt][hrow * 2 + 1] + bias[gn + 1];
                    *(float2*)&out[((size_t)(b * HH + h) * SS + s) * HDIM + d] = st;
                }
            }
        }
}

// ---------------- out = attended @ Wo + bo -----------------------------------
__global__ __launch_bounds__(256) void outproj_kernel(const float* __restrict__ Wo,
                                                      const float* __restrict__ bo,
                                                      float* __restrict__ out) {
    __shared__ unsigned As0[128 * SPITCH], As1[128 * SPITCH];
    __shared__ unsigned Bs0[128 * SPITCH], Bs1[128 * SPITCH];
    int row0 = blockIdx.y * 128, col0 = blockIdx.x * 128;

#define LA0(kg) (*(const float4*)&g_att[(size_t)(row0 + ar) * DDIM + (kg) + ac])
#define LA1(kg) (*(const float4*)&g_att[(size_t)(row0 + 64 + ar) * DDIM + (kg) + ac])
#define LB(kg, j) (Wo[(size_t)((kg) + bk0 + (j)) * DDIM + col0 + bn])
    GEMM_BODY(LA0, LA1, LB, DDIM / 16)
#undef LA0
#undef LA1
#undef LB

    int g = lane >> 2, tg = lane & 3;
    #pragma unroll
    for (int mt = 0; mt < 4; mt++)
        #pragma unroll
        for (int nt = 0; nt < 4; nt++) {
            int gm = row0 + wm * 64 + mt * 16 + g;
            int gn = col0 + wnw * 32 + nt * 8 + tg * 2;
            #pragma unroll
            for (int hrow = 0; hrow < 2; hrow++) {
                int m = gm + hrow * 8;
                float2 st;
                st.x = acc[mt][nt][hrow * 2]     + bo[gn];
                st.y = acc[mt][nt][hrow * 2 + 1] + bo[gn + 1];
                *(float2*)&out[(size_t)m * DDIM + gn] = st;
            }
        }
}

// ---------------- quantum features (warp-per-row) ---------------------------
__global__ __launch_bounds__(256) void qfeat_kernel(
        const float* __restrict__ qmapW, const float* __restrict__ qmapb,
        const float* __restrict__ qw, const float* __restrict__ ph,
        const float* __restrict__ es_ptr) {
    int gw   = (blockIdx.x * blockDim.x + threadIdx.x) >> 5;
    int lane = threadIdx.x & 31;
    if (gw >= 2 * BHn * SS) return;
    int side = gw / (BHn * SS);
    int r    = gw % (BHn * SS);
    int h    = (r / SS) % HH;
    const float* row = ((side == 0) ? g_Q : g_K) + (size_t)r * HDIM;
    float rv0 = row[lane], rv1 = row[lane + 32];

    float mydot = 0.f;
    #pragma unroll
    for (int n = 0; n < NQh; n++) {
        float p = rv0 * qmapW[lane * NQh + n] + rv1 * qmapW[(lane + 32) * NQh + n];
        #pragma unroll
        for (int o = 16; o; o >>= 1) p += __shfl_xor_sync(0xffffffffu, p, o);
        if (lane == n) mydot = p;
    }
    if (lane < NQh) {
        float a = tanhf(mydot + qmapb[lane]);
        float s, c;
        if (side == 0) {
            float mix = 1.f / (1.f + __expf(-*es_ptr));
            float w = (1.f / (1.f + __expf(-qw[h * NQh + lane]))) * (1.0f / NQh) * mix;
            sincosf(a + ph[h * NQh + lane], &s, &c);
            g_fQ[(size_t)r * NF + lane]       = w * c;
            g_fQ[(size_t)r * NF + NQh + lane] = w * s;
        } else {
            sincosf(a, &s, &c);
            g_fK[(size_t)r * NF + lane]       = c;
            g_fK[(size_t)r * NF + NQh + lane] = s;
        }
    }
}

// ---------------- zero out2 --------------------------------------------------
__global__ void zero_out2_kernel(float* __restrict__ out2) {
    int idx = blockIdx.x * blockDim.x + threadIdx.x;
    if (idx < BB * SS * SS / 4)
        ((float4*)out2)[idx] = make_float4(0.f, 0.f, 0.f, 0.f);
}

// ---------------- fused attention: scores + softmax(+head-mean red) + AV ----
__global__ __launch_bounds__(256) void attn_kernel(const float* __restrict__ es_ptr,
                                                   float* __restrict__ out2) {
    extern __shared__ float P[];                       // [64][PROW]
    unsigned* Ks   = (unsigned*)(P + 64 * PROW);       // phase 1
    float*    entT = (float*)(Ks + 64 * KPITCH);       // phase 1 LUT
    unsigned* Vs0  = (unsigned*)(P + 64 * PROW);       // phase 3
    unsigned* Vs1  = Vs0 + 64 * VPITCH;

    int bh = blockIdx.y;
    int b = bh >> 4, h = bh & 15;
    int i0 = blockIdx.x * 64;
    const float* Qp  = g_Q  + (size_t)bh * SS * HDIM;
    const float* Kp  = g_K  + (size_t)bh * SS * HDIM;
    const float* Vtp = g_V  + (size_t)bh * HDIM * SS;  // [d][s]
    const float* Fqp = g_fQ + (size_t)bh * SS * NF;
    const float* Fkp = g_fK + (size_t)bh * SS * NF;
    float* o2p = out2 + (size_t)b * SS * SS;

    int tid = threadIdx.x;
    int wid = tid >> 5, lane = tid & 31;
    int wm = wid & 3, wn = wid >> 2;
    int g = lane >> 2, tg = lane & 3;
    int a_row = lane & 15, a_koff = (lane >> 4) * 4;
    int b_nr  = (lane & 7) + ((lane >> 4) << 3);
    int b_koff = ((lane >> 3) & 1) * 4;
    unsigned PBase   = (unsigned)__cvta_generic_to_shared(P);
    unsigned KsBase  = (unsigned)__cvta_generic_to_shared(Ks);
    unsigned VsBase0 = (unsigned)__cvta_generic_to_shared(Vs0);
    unsigned VsBase1 = (unsigned)__cvta_generic_to_shared(Vs1);

    float es  = *es_ptr;
    float mix = 1.f / (1.f + __expf(-es));
    float ca  = (1.f - mix) * 0.125f;

    for (int t = tid; t < ENTN; t += 256)
        entT[t] = __expf(-0.1f * fabsf((float)(i0 - 767 + t)));

    // ---- stage Q(*ca)+Fq into Ks, preload persistent a-fragments -----------
    {
        #pragma unroll
        for (int it = 0; it < 4; it++) {
            int fid = tid + 256 * it;
            int r = fid >> 4, c4 = (fid & 15) * 4;
            float4 f = *(const float4*)&Qp[(size_t)(i0 + r) * HDIM + c4];
            *(uint4*)&Ks[r * KPITCH + c4] =
                make_uint4(f2tf32(ca * f.x), f2tf32(ca * f.y),
                           f2tf32(ca * f.z), f2tf32(ca * f.w));
        }
        int r = tid >> 2, c4 = (tid & 3) * 4;
        float4 f = *(const float4*)&Fqp[(size_t)(i0 + r) * NF + c4];
        *(uint4*)&Ks[r * KPITCH + 64 + c4] =
            make_uint4(f2tf32(f.x), f2tf32(f.y), f2tf32(f.z), f2tf32(f.w));
    }
    __syncthreads();
    unsigned afr[10][4];
    #pragma unroll
    for (int s = 0; s < 10; s++) {
        int r = wm * 16 + g, c = s * 8 + tg;
        afr[s][0] = Ks[r * KPITCH + c];
        afr[s][1] = Ks[(r + 8) * KPITCH + c];
        afr[s][2] = Ks[r * KPITCH + c + 4];
        afr[s][3] = Ks[(r + 8) * KPITCH + c + 4];
    }
    __syncthreads();

    // ---- phase 1: scores over 12 K-chunks (reg-prefetched) -----------------
    float4 rc[4], rq;
    {
        #pragma unroll
        for (int it = 0; it < 4; it++) {
            int fid = tid + 256 * it;
            int r = fid >> 4, c4 = (fid & 15) * 4;
            rc[it] = *(const float4*)&Kp[(size_t)r * HDIM + c4];
        }
        { int r = tid >> 2, c4 = (tid & 3) * 4;
          rq = *(const float4*)&Fkp[(size_t)r * NF + c4]; }
        #pragma unroll
        for (int it = 0; it < 4; it++) {
            int fid = tid + 256 * it;
            int r = fid >> 4, c4 = (fid & 15) * 4;
            *(uint4*)&Ks[r * KPITCH + c4] =
                make_uint4(f2tf32(rc[it].x), f2tf32(rc[it].y),
                           f2tf32(rc[it].z), f2tf32(rc[it].w));
        }
        { int r = tid >> 2, c4 = (tid & 3) * 4;
          *(uint4*)&Ks[r * KPITCH + 64 + c4] =
              make_uint4(f2tf32(rq.x), f2tf32(rq.y), f2tf32(rq.z), f2tf32(rq.w)); }
        __syncthreads();
    }
    for (int jc = 0; jc < 12; jc++) {
        int j0 = jc * 64;
        if (jc + 1 < 12) {
            int jn = j0 + 64;
            #pragma unroll
            for (int it = 0; it < 4; it++) {
                int fid = tid + 256 * it;
                int r = fid >> 4, c4 = (fid & 15) * 4;
                rc[it] = *(const float4*)&Kp[(size_t)(jn + r) * HDIM + c4];
            }
            { int r = tid >> 2, c4 = (tid & 3) * 4;
              rq = *(const float4*)&Fkp[(size_t)(jn + r) * NF + c4]; }
        }
        float accC[4][4] = {}, accQ[4][4] = {};
        #pragma unroll
        for (int s = 0; s < 10; s++) {
            int kc = s * 8;
            unsigned bf[4][2];
            #pragma unroll
            for (int p = 0; p < 2; p++)
                ldsm_x4(bf[2 * p][0], bf[2 * p][1], bf[2 * p + 1][0], bf[2 * p + 1][1],
                        KsBase + ((wn * 32 + p * 16 + b_nr) * KPITCH + kc + b_koff) * 4);
            #pragma unroll
            for (int nt = 0; nt < 4; nt++) {
                if (s < 8)
                    mma_tf32(accC[nt][0], accC[nt][1], accC[nt][2], accC[nt][3],
                             afr[s][0], afr[s][1], afr[s][2], afr[s][3],
                             bf[nt][0], bf[nt][1]);
                else
                    mma_tf32(accQ[nt][0], accQ[nt][1], accQ[nt][2], accQ[nt][3],
                             afr[s][0], afr[s][1], afr[s][2], afr[s][3],
                             bf[nt][0], bf[nt][1]);
            }
        }
        #pragma unroll
        for (int nt = 0; nt < 4; nt++) {
            int r  = wm * 16 + g;
            int cl = wn * 32 + nt * 8 + tg * 2;
            #pragma unroll
            for (int hrow = 0; hrow < 2; hrow++) {
                int rr = r + hrow * 8;
                int base = rr + 767 - j0 - cl;
                float e0 = entT[base];
                float e1 = entT[base - 1];
                float2 st;
                st.x = accC[nt][hrow * 2]     + e0 * accQ[nt][hrow * 2];
                st.y = accC[nt][hrow * 2 + 1] + e1 * accQ[nt][hrow * 2 + 1];
                *(float2*)&P[rr * PROW + j0 + cl] = st;
            }
        }
        __syncthreads();
        if (jc + 1 < 12) {
            #pragma unroll
            for (int it = 0; it < 4; it++) {
                int fid = tid + 256 * it;
                int r = fid >> 4, c4 = (fid & 15) * 4;
                *(uint4*)&Ks[r * KPITCH + c4] =
                    make_uint4(f2tf32(rc[it].x), f2tf32(rc[it].y),
                               f2tf32(rc[it].z), f2tf32(rc[it].w));
            }
            { int r = tid >> 2, c4 = (tid & 3) * 4;
              *(uint4*)&Ks[r * KPITCH + 64 + c4] =
                  make_uint4(f2tf32(rq.x), f2tf32(rq.y), f2tf32(rq.z), f2tf32(rq.w)); }
        }
        __syncthreads();
    }

    // ---- phase 2: softmax + head-mean reduction into out2 ------------------
    for (int rr = wid; rr < 64; rr += 8) {
        float4* row4 = (float4*)(P + rr * PROW);
        float4 v[6];
        float m = -1e30f;
        #pragma unroll
        for (int u = 0; u < 6; u++) {
            v[u] = row4[lane + u * 32];
            m = fmaxf(m, fmaxf(fmaxf(v[u].x, v[u].y), fmaxf(v[u].z, v[u].w)));
        }
        #pragma unroll
        for (int o = 16; o; o >>= 1) m = fmaxf(m, __shfl_xor_sync(0xffffffffu, m, o));
        float ssum = 0.f;
        #pragma unroll
        for (int u = 0; u < 6; u++) {
            v[u].x = __expf(v[u].x - m); v[u].y = __expf(v[u].y - m);
            v[u].z = __expf(v[u].z - m); v[u].w = __expf(v[u].w - m);
            ssum += (v[u].x + v[u].y) + (v[u].z + v[u].w);
        }
        #pragma unroll
        for (int o = 16; o; o >>= 1) ssum += __shfl_xor_sync(0xffffffffu, ssum, o);
        float inv = __frcp_rn(ssum);
        float* o2row = o2p + (size_t)(i0 + rr) * SS;
        #pragma unroll
        for (int u = 0; u < 6; u++) {
            float4 t;
            t.x = __uint_as_float(f2tf32(v[u].x * inv));
            t.y = __uint_as_float(f2tf32(v[u].y * inv));
            t.z = __uint_as_float(f2tf32(v[u].z * inv));
            t.w = __uint_as_float(f2tf32(v[u].w * inv));
            row4[lane + u * 32] = t;
            red_add_v4(o2row + (lane + u * 32) * 4,
                       t.x * (1.0f / HH), t.y * (1.0f / HH),
                       t.z * (1.0f / HH), t.w * (1.0f / HH));
        }
    }

    // ---- phase 3: AV via ldmatrix on P and double-buffered Vs --------------
    float acc[4][4] = {};
    float4 vreg[4];
    {
        #pragma unroll
        for (int it = 0; it < 4; it++) {
            int q4 = tid + it * 256;
            int d = q4 >> 4, c4 = (q4 & 15) * 4;
            vreg[it] = *(const float4*)&Vtp[(size_t)d * SS + c4];
        }
        __syncthreads();
        #pragma unroll
        for (int it = 0; it < 4; it++) {
            int q4 = tid + it * 256;
            int d = q4 >> 4, c4 = (q4 & 15) * 4;
            *(uint4*)&Vs0[d * VPITCH + c4] =
                make_uint4(f2tf32(vreg[it].x), f2tf32(vreg[it].y),
                           f2tf32(vreg[it].z), f2tf32(vreg[it].w));
        }
        __syncthreads();
    }
    for (int c = 0; c < 12; c++) {
        int k0 = c * 64;
        unsigned curB = (c & 1) ? VsBase1 : VsBase0;
        unsigned* nxt = (c & 1) ? Vs0 : Vs1;
        if (c + 1 < 12) {
            int kn = k0 + 64;
            #pragma unroll
            for (int it = 0; it < 4; it++) {
                int q4 = tid + it * 256;
                int d = q4 >> 4, c4 = (q4 & 15) * 4;
                vreg[it] = *(const float4*)&Vtp[(size_t)d * SS + kn + c4];
            }
        }
        #pragma unroll
        for (int s = 0; s < 8; s++) {
            int kc = s * 8;
            unsigned af[4];
            ldsm_x4(af[0], af[1], af[2], af[3],
                    PBase + ((wm * 16 + a_row) * PROW + k0 + kc + a_koff) * 4);
            unsigned bf[4][2];
            #pragma unroll
            for (int p = 0; p < 2; p++)
                ldsm_x4(bf[2 * p][0], bf[2 * p][1], bf[2 * p + 1][0], bf[2 * p + 1][1],
                        curB + ((wn * 32 + p * 16 + b_nr) * VPITCH + kc + b_koff) * 4);
            #pragma unroll
            for (int nt = 0; nt < 4; nt++)
                mma_tf32(acc[nt][0], acc[nt][1], acc[nt][2], acc[nt][3],
                         af[0], af[1], af[2], af[3], bf[nt][0], bf[nt][1]);
        }
        if (c + 1 < 12) {
            #pragma unroll
            for (int it = 0; it < 4; it++) {
                int q4 = tid + it * 256;
                int d = q4 >> 4, c4 = (q4 & 15) * 4;
                *(uint4*)&nxt[d * VPITCH + c4] =
                    make_uint4(f2tf32(vreg[it].x), f2tf32(vreg[it].y),
                               f2tf32(vreg[it].z), f2tf32(vreg[it].w));
            }
        }
        __syncthreads();
    }
    #pragma unroll
    for (int nt = 0; nt < 4; nt++) {
        int r = wm * 16 + g;
        int d0 = wn * 32 + nt * 8 + tg * 2;
        #pragma unroll
        for (int hrow = 0; hrow < 2; hrow++) {
            int s_ = i0 + r + hrow * 8;
            *(float2*)&g_att[(size_t)(b * SS + s_) * DDIM + h * HDIM + d0] =
                make_float2(acc[nt][hrow * 2], acc[nt][hrow * 2 + 1]);
        }
    }
}

// ---------------- launch -----------------------------------------------------
extern "C" void kernel_launch(void* const* d_in, const int* in_sizes, int n_in,
                              void* d_out, int out_size) {
    const float* query = (const float*)d_in[0];
    const float* key   = (const float*)d_in[1];
    const float* value = (const float*)d_in[2];
    const float* Wq = (const float*)d_in[3];
    const float* bq = (const float*)d_in[4];
    const float* Wk = (const float*)d_in[5];
    const float* bk = (const float*)d_in[6];
    const float* Wv = (const float*)d_in[7];
    const float* bv = (const float*)d_in[8];
    const float* Wo = (const float*)d_in[9];
    const float* bo = (const float*)d_in[10];
    const float* qmapW = (const float*)d_in[11];
    const float* qmapb = (const float*)d_in[12];
    const float* qw    = (const float*)d_in[13];
    const float* ph    = (const float*)d_in[14];
    const float* es    = (const float*)d_in[15];

    float* out  = (float*)d_out;
    float* out2 = out + (size_t)MM * DDIM;

    {
        int n = BB * SS * SS / 4;
        zero_out2_kernel<<<(n + 255) / 256, 256>>>(out2);
    }
    proj_kernel<<<dim3(DDIM / 128, MM / 128, 3), 256>>>(query, key, value,
                                                        Wq, bq, Wk, bk, Wv, bv);
    {
        int nrows = 2 * BHn * SS;
        qfeat_kernel<<<nrows / 8, 256>>>(qmapW, qmapb, qw, ph, es);
    }
    {
        size_t smem = (size_t)64 * PROW * 4 + (size_t)2 * 64 * VPITCH * 4; // 232448
        cudaFuncSetAttribute(attn_kernel,
                             cudaFuncAttributeMaxDynamicSharedMemorySize, (int)smem);
        attn_kernel<<<dim3(SS / 64, BHn), 256, smem>>>(es, out2);
    }
    outproj_kernel<<<dim3(DDIM / 128, MM / 128), 256>>>(Wo, bo, out);
}

// round 8
// speedup vs baseline: 3.2180x; 1.0128x over previous
#include <cuda_runtime.h>
#include <math.h>

#define BB   2
#define SS   768
#define DDIM 1024
#define HH   16
#define HDIM 64
#define NQh  8
#define NF   16
#define BHn  (BB*HH)     // 32
#define MM   (BB*SS)     // 1536
#define PROW 772         // 772 % 32 == 4 -> conflict-free ldmatrix rows
#define SPITCH 20
#define KPITCH 84        // 84 % 32 == 20 -> conflict-free
#define VPITCH 68        // 68 % 32 == 4  -> conflict-free
#define ENTN 831
#define ATHREADS 512

// ---------------- scratch ----------------------------------------------------
__device__ float g_Q[BHn*SS*HDIM];      // [bh][s][d]
__device__ float g_K[BHn*SS*HDIM];      // [bh][s][d]
__device__ float g_V[BHn*SS*HDIM];      // [bh][d][s]  (TRANSPOSED)
__device__ float g_fQ[BHn*SS*NF];
__device__ float g_fK[BHn*SS*NF];
__device__ float g_att[MM*DDIM];

// ---------------- helpers ----------------------------------------------------
__device__ __forceinline__ unsigned f2tf32(float f) {
    unsigned u;
    asm("cvt.rna.tf32.f32 %0, %1;" : "=r"(u) : "f"(f));
    return u;
}

__device__ __forceinline__ void mma_tf32(float& c0, float& c1, float& c2, float& c3,
                                         unsigned a0, unsigned a1, unsigned a2, unsigned a3,
                                         unsigned b0, unsigned b1) {
    asm volatile("mma.sync.aligned.m16n8k8.row.col.f32.tf32.tf32.f32 "
                 "{%0,%1,%2,%3}, {%4,%5,%6,%7}, {%8,%9}, {%0,%1,%2,%3};\n"
                 : "+f"(c0), "+f"(c1), "+f"(c2), "+f"(c3)
                 : "r"(a0), "r"(a1), "r"(a2), "r"(a3), "r"(b0), "r"(b1));
}

__device__ __forceinline__ void ldsm_x4(unsigned& r0, unsigned& r1,
                                        unsigned& r2, unsigned& r3, unsigned addr) {
    asm volatile("ldmatrix.sync.aligned.m8n8.x4.shared.b16 {%0,%1,%2,%3}, [%4];"
                 : "=r"(r0), "=r"(r1), "=r"(r2), "=r"(r3) : "r"(addr));
}

__device__ __forceinline__ void red_add_v4(float* p, float x, float y, float z, float w) {
    asm volatile("red.global.add.v4.f32 [%0], {%1,%2,%3,%4};"
                 :: "l"(p), "f"(x), "f"(y), "f"(z), "f"(w) : "memory");
}

// ============================================================================
// tf32 GEMM core for proj/outproj (256 threads, 128x128 tile)
// ============================================================================
#define GEMM_BODY(LOAD_A0, LOAD_A1, LOAD_B, NCHUNK)                              \
    float acc[4][4][4] = {};                                                     \
    int tid = threadIdx.x;                                                       \
    int wid = tid >> 5, lane = tid & 31;                                         \
    int wm = wid & 1, wnw = wid >> 1;                                            \
    int ar = tid >> 2, ac = (tid & 3) * 4;                                       \
    int bn = tid & 127, bk0 = (tid >> 7) * 8;                                    \
    int a_row = lane & 15, a_koff = (lane >> 4) * 4;                             \
    int b_nr  = (lane & 7) + ((lane >> 4) << 3);                                 \
    int b_koff = ((lane >> 3) & 1) * 4;                                          \
    unsigned aBase0 = (unsigned)__cvta_generic_to_shared(As0);                   \
    unsigned aBase1 = (unsigned)__cvta_generic_to_shared(As1);                   \
    unsigned bBase0 = (unsigned)__cvta_generic_to_shared(Bs0);                   \
    unsigned bBase1 = (unsigned)__cvta_generic_to_shared(Bs1);                   \
    float4 pa0, pa1; float pb[8];                                                \
    { int kg = 0;                                                                \
      pa0 = LOAD_A0(kg); pa1 = LOAD_A1(kg);                                      \
      _Pragma("unroll") for (int j = 0; j < 8; j++) pb[j] = LOAD_B(kg, j); }     \
    { unsigned* As = As0; unsigned* Bs = Bs0;                                    \
      *(uint4*)&As[ar * SPITCH + ac] =                                           \
          make_uint4(f2tf32(pa0.x), f2tf32(pa0.y), f2tf32(pa0.z), f2tf32(pa0.w));\
      *(uint4*)&As[(ar + 64) * SPITCH + ac] =                                    \
          make_uint4(f2tf32(pa1.x), f2tf32(pa1.y), f2tf32(pa1.z), f2tf32(pa1.w));\
      *(uint4*)&Bs[bn * SPITCH + bk0] =                                          \
          make_uint4(f2tf32(pb[0]), f2tf32(pb[1]), f2tf32(pb[2]), f2tf32(pb[3]));\
      *(uint4*)&Bs[bn * SPITCH + bk0 + 4] =                                      \
          make_uint4(f2tf32(pb[4]), f2tf32(pb[5]), f2tf32(pb[6]), f2tf32(pb[7]));}\
    __syncthreads();                                                             \
    for (int ch = 0; ch < (NCHUNK); ch++) {                                      \
        int buf = ch & 1;                                                        \
        if (ch + 1 < (NCHUNK)) {                                                 \
            int kg = (ch + 1) * 16;                                              \
            pa0 = LOAD_A0(kg); pa1 = LOAD_A1(kg);                                \
            _Pragma("unroll") for (int j = 0; j < 8; j++) pb[j] = LOAD_B(kg, j); \
        }                                                                        \
        unsigned aB = buf ? aBase1 : aBase0;                                     \
        unsigned bB = buf ? bBase1 : bBase0;                                     \
        _Pragma("unroll")                                                        \
        for (int ks = 0; ks < 2; ks++) {                                         \
            int kc = ks * 8;                                                     \
            unsigned af[4][4];                                                   \
            _Pragma("unroll")                                                    \
            for (int mt = 0; mt < 4; mt++)                                       \
                ldsm_x4(af[mt][0], af[mt][1], af[mt][2], af[mt][3],              \
                    aB + ((wm * 64 + mt * 16 + a_row) * SPITCH + kc + a_koff) * 4);\
            unsigned bf[4][2];                                                   \
            _Pragma("unroll")                                                    \
            for (int p = 0; p < 2; p++)                                          \
                ldsm_x4(bf[2 * p][0], bf[2 * p][1], bf[2 * p + 1][0],            \
                        bf[2 * p + 1][1],                                        \
                    bB + ((wnw * 32 + p * 16 + b_nr) * SPITCH + kc + b_koff) * 4);\
            _Pragma("unroll")                                                    \
            for (int mt = 0; mt < 4; mt++)                                       \
                _Pragma("unroll")                                                \
                for (int nt = 0; nt < 4; nt++)                                   \
                    mma_tf32(acc[mt][nt][0], acc[mt][nt][1],                     \
                             acc[mt][nt][2], acc[mt][nt][3],                     \
                             af[mt][0], af[mt][1], af[mt][2], af[mt][3],         \
                             bf[nt][0], bf[nt][1]);                              \
        }                                                                        \
        if (ch + 1 < (NCHUNK)) {                                                 \
            unsigned* As = buf ? As0 : As1;                                      \
            unsigned* Bs = buf ? Bs0 : Bs1;                                      \
            *(uint4*)&As[ar * SPITCH + ac] =                                     \
                make_uint4(f2tf32(pa0.x), f2tf32(pa0.y), f2tf32(pa0.z), f2tf32(pa0.w));\
            *(uint4*)&As[(ar + 64) * SPITCH + ac] =                              \
                make_uint4(f2tf32(pa1.x), f2tf32(pa1.y), f2tf32(pa1.z), f2tf32(pa1.w));\
            *(uint4*)&Bs[bn * SPITCH + bk0] =                                    \
                make_uint4(f2tf32(pb[0]), f2tf32(pb[1]), f2tf32(pb[2]), f2tf32(pb[3]));\
            *(uint4*)&Bs[bn * SPITCH + bk0 + 4] =                                \
                make_uint4(f2tf32(pb[4]), f2tf32(pb[5]), f2tf32(pb[6]), f2tf32(pb[7]));\
        }                                                                        \
        __syncthreads();                                                         \
    }

// ---------------- fused QKV projection ---------------------------------------
__global__ __launch_bounds__(256) void proj_kernel(
        const float* __restrict__ q, const float* __restrict__ k,
        const float* __restrict__ v,
        const float* __restrict__ Wq, const float* __restrict__ bq,
        const float* __restrict__ Wk, const float* __restrict__ bk,
        const float* __restrict__ Wv, const float* __restrict__ bv) {
    int which = blockIdx.z;
    const float* A    = (which == 0) ? q  : (which == 1) ? k  : v;
    const float* W    = (which == 0) ? Wq : (which == 1) ? Wk : Wv;
    const float* bias = (which == 0) ? bq : (which == 1) ? bk : bv;
    float*       out  = (which == 0) ? g_Q : (which == 1) ? g_K : g_V;

    __shared__ unsigned As0[128 * SPITCH], As1[128 * SPITCH];
    __shared__ unsigned Bs0[128 * SPITCH], Bs1[128 * SPITCH];
    int row0 = blockIdx.y * 128, col0 = blockIdx.x * 128;

#define LA0(kg) (*(const float4*)&A[(size_t)(row0 + ar) * DDIM + (kg) + ac])
#define LA1(kg) (*(const float4*)&A[(size_t)(row0 + 64 + ar) * DDIM + (kg) + ac])
#define LB(kg, j) (W[(size_t)((kg) + bk0 + (j)) * DDIM + col0 + bn])
    GEMM_BODY(LA0, LA1, LB, DDIM / 16)
#undef LA0
#undef LA1
#undef LB

    int g = lane >> 2, tg = lane & 3;
    #pragma unroll
    for (int mt = 0; mt < 4; mt++)
        #pragma unroll
        for (int nt = 0; nt < 4; nt++) {
            int gm = row0 + wm * 64 + mt * 16 + g;
            int gn = col0 + wnw * 32 + nt * 8 + tg * 2;
            #pragma unroll
            for (int hrow = 0; hrow < 2; hrow++) {
                int m = gm + hrow * 8;
                int b = m / SS, s = m % SS;
                int h = gn >> 6, d = gn & 63;
                if (which == 2) {
                    #pragma unroll
                    for (int j = 0; j < 2; j++)
                        out[((size_t)(b * HH + h) * HDIM + d + j) * SS + s] =
                            acc[mt][nt][hrow * 2 + j] + bias[gn + j];
                } else {
                    float2 st;
                    st.x = acc[mt][nt][hrow * 2]     + bias[gn];
                    st.y = acc[mt][nt][hrow * 2 + 1] + bias[gn + 1];
                    *(float2*)&out[((size_t)(b * HH + h) * SS + s) * HDIM + d] = st;
                }
            }
        }
}

// ---------------- out = attended @ Wo + bo -----------------------------------
__global__ __launch_bounds__(256) void outproj_kernel(const float* __restrict__ Wo,
                                                      const float* __restrict__ bo,
                                                      float* __restrict__ out) {
    __shared__ unsigned As0[128 * SPITCH], As1[128 * SPITCH];
    __shared__ unsigned Bs0[128 * SPITCH], Bs1[128 * SPITCH];
    int row0 = blockIdx.y * 128, col0 = blockIdx.x * 128;

#define LA0(kg) (*(const float4*)&g_att[(size_t)(row0 + ar) * DDIM + (kg) + ac])
#define LA1(kg) (*(const float4*)&g_att[(size_t)(row0 + 64 + ar) * DDIM + (kg) + ac])
#define LB(kg, j) (Wo[(size_t)((kg) + bk0 + (j)) * DDIM + col0 + bn])
    GEMM_BODY(LA0, LA1, LB, DDIM / 16)
#undef LA0
#undef LA1
#undef LB

    int g = lane >> 2, tg = lane & 3;
    #pragma unroll
    for (int mt = 0; mt < 4; mt++)
        #pragma unroll
        for (int nt = 0; nt < 4; nt++) {
            int gm = row0 + wm * 64 + mt * 16 + g;
            int gn = col0 + wnw * 32 + nt * 8 + tg * 2;
            #pragma unroll
            for (int hrow = 0; hrow < 2; hrow++) {
                int m = gm + hrow * 8;
                float2 st;
                st.x = acc[mt][nt][hrow * 2]     + bo[gn];
                st.y = acc[mt][nt][hrow * 2 + 1] + bo[gn + 1];
                *(float2*)&out[(size_t)m * DDIM + gn] = st;
            }
        }
}

// ---------------- quantum features (warp-per-row) ---------------------------
__global__ __launch_bounds__(256) void qfeat_kernel(
        const float* __restrict__ qmapW, const float* __restrict__ qmapb,
        const float* __restrict__ qw, const float* __restrict__ ph,
        const float* __restrict__ es_ptr) {
    int gw   = (blockIdx.x * blockDim.x + threadIdx.x) >> 5;
    int lane = threadIdx.x & 31;
    if (gw >= 2 * BHn * SS) return;
    int side = gw / (BHn * SS);
    int r    = gw % (BHn * SS);
    int h    = (r / SS) % HH;
    const float* row = ((side == 0) ? g_Q : g_K) + (size_t)r * HDIM;
    float rv0 = row[lane], rv1 = row[lane + 32];

    float mydot = 0.f;
    #pragma unroll
    for (int n = 0; n < NQh; n++) {
        float p = rv0 * qmapW[lane * NQh + n] + rv1 * qmapW[(lane + 32) * NQh + n];
        #pragma unroll
        for (int o = 16; o; o >>= 1) p += __shfl_xor_sync(0xffffffffu, p, o);
        if (lane == n) mydot = p;
    }
    if (lane < NQh) {
        float a = tanhf(mydot + qmapb[lane]);
        float s, c;
        if (side == 0) {
            float mix = 1.f / (1.f + __expf(-*es_ptr));
            float w = (1.f / (1.f + __expf(-qw[h * NQh + lane]))) * (1.0f / NQh) * mix;
            sincosf(a + ph[h * NQh + lane], &s, &c);
            g_fQ[(size_t)r * NF + lane]       = w * c;
            g_fQ[(size_t)r * NF + NQh + lane] = w * s;
        } else {
            sincosf(a, &s, &c);
            g_fK[(size_t)r * NF + lane]       = c;
            g_fK[(size_t)r * NF + NQh + lane] = s;
        }
    }
}

// ---------------- zero out2 --------------------------------------------------
__global__ void zero_out2_kernel(float* __restrict__ out2) {
    int idx = blockIdx.x * blockDim.x + threadIdx.x;
    if (idx < BB * SS * SS / 4)
        ((float4*)out2)[idx] = make_float4(0.f, 0.f, 0.f, 0.f);
}

// ---------------- fused attention (512 threads, 16 warps: 4m x 4n) ----------
__global__ __launch_bounds__(ATHREADS) void attn_kernel(const float* __restrict__ es_ptr,
                                                        float* __restrict__ out2) {
    extern __shared__ float P[];                       // [64][PROW]
    unsigned* Ks   = (unsigned*)(P + 64 * PROW);       // phase 1
    float*    entT = (float*)(Ks + 64 * KPITCH);       // phase 1 LUT
    unsigned* Vs0  = (unsigned*)(P + 64 * PROW);       // phase 3
    unsigned* Vs1  = Vs0 + 64 * VPITCH;

    int bh = blockIdx.y;
    int b = bh >> 4, h = bh & 15;
    int i0 = blockIdx.x * 64;
    const float* Qp  = g_Q  + (size_t)bh * SS * HDIM;
    const float* Kp  = g_K  + (size_t)bh * SS * HDIM;
    const float* Vtp = g_V  + (size_t)bh * HDIM * SS;  // [d][s]
    const float* Fqp = g_fQ + (size_t)bh * SS * NF;
    const float* Fkp = g_fK + (size_t)bh * SS * NF;
    float* o2p = out2 + (size_t)b * SS * SS;

    int tid = threadIdx.x;
    int wid = tid >> 5, lane = tid & 31;
    int wm = wid & 3, wn = wid >> 2;                   // 4m x 4n
    int g = lane >> 2, tg = lane & 3;
    int a_row = lane & 15, a_koff = (lane >> 4) * 4;
    int b_nr  = (lane & 7) + ((lane >> 4) << 3);
    int b_koff = ((lane >> 3) & 1) * 4;
    unsigned PBase   = (unsigned)__cvta_generic_to_shared(P);
    unsigned KsBase  = (unsigned)__cvta_generic_to_shared(Ks);
    unsigned VsBase0 = (unsigned)__cvta_generic_to_shared(Vs0);
    unsigned VsBase1 = (unsigned)__cvta_generic_to_shared(Vs1);

    float es  = *es_ptr;
    float mix = 1.f / (1.f + __expf(-es));
    float ca  = (1.f - mix) * 0.125f;

    for (int t = tid; t < ENTN; t += ATHREADS)
        entT[t] = __expf(-0.1f * fabsf((float)(i0 - 767 + t)));

    // ---- stage Q(*ca)+Fq into Ks, preload persistent a-fragments -----------
    {
        #pragma unroll
        for (int it = 0; it < 2; it++) {
            int fid = tid + ATHREADS * it;
            int r = fid >> 4, c4 = (fid & 15) * 4;
            float4 f = *(const float4*)&Qp[(size_t)(i0 + r) * HDIM + c4];
            *(uint4*)&Ks[r * KPITCH + c4] =
                make_uint4(f2tf32(ca * f.x), f2tf32(ca * f.y),
                           f2tf32(ca * f.z), f2tf32(ca * f.w));
        }
        if (tid < 256) {
            int r = tid >> 2, c4 = (tid & 3) * 4;
            float4 f = *(const float4*)&Fqp[(size_t)(i0 + r) * NF + c4];
            *(uint4*)&Ks[r * KPITCH + 64 + c4] =
                make_uint4(f2tf32(f.x), f2tf32(f.y), f2tf32(f.z), f2tf32(f.w));
        }
    }
    __syncthreads();
    unsigned afr[10][4];
    #pragma unroll
    for (int s = 0; s < 10; s++) {
        int r = wm * 16 + g, c = s * 8 + tg;
        afr[s][0] = Ks[r * KPITCH + c];
        afr[s][1] = Ks[(r + 8) * KPITCH + c];
        afr[s][2] = Ks[r * KPITCH + c + 4];
        afr[s][3] = Ks[(r + 8) * KPITCH + c + 4];
    }
    __syncthreads();

    // ---- phase 1: scores over 12 K-chunks (reg-prefetched) -----------------
    float4 rc[2], rq;
    {
        #pragma unroll
        for (int it = 0; it < 2; it++) {
            int fid = tid + ATHREADS * it;
            int r = fid >> 4, c4 = (fid & 15) * 4;
            rc[it] = *(const float4*)&Kp[(size_t)r * HDIM + c4];
        }
        if (tid < 256) {
            int r = tid >> 2, c4 = (tid & 3) * 4;
            rq = *(const float4*)&Fkp[(size_t)r * NF + c4];
        }
        #pragma unroll
        for (int it = 0; it < 2; it++) {
            int fid = tid + ATHREADS * it;
            int r = fid >> 4, c4 = (fid & 15) * 4;
            *(uint4*)&Ks[r * KPITCH + c4] =
                make_uint4(f2tf32(rc[it].x), f2tf32(rc[it].y),
                           f2tf32(rc[it].z), f2tf32(rc[it].w));
        }
        if (tid < 256) {
            int r = tid >> 2, c4 = (tid & 3) * 4;
            *(uint4*)&Ks[r * KPITCH + 64 + c4] =
                make_uint4(f2tf32(rq.x), f2tf32(rq.y), f2tf32(rq.z), f2tf32(rq.w));
        }
        __syncthreads();
    }
    for (int jc = 0; jc < 12; jc++) {
        int j0 = jc * 64;
        if (jc + 1 < 12) {
            int jn = j0 + 64;
            #pragma unroll
            for (int it = 0; it < 2; it++) {
                int fid = tid + ATHREADS * it;
                int r = fid >> 4, c4 = (fid & 15) * 4;
                rc[it] = *(const float4*)&Kp[(size_t)(jn + r) * HDIM + c4];
            }
            if (tid < 256) {
                int r = tid >> 2, c4 = (tid & 3) * 4;
                rq = *(const float4*)&Fkp[(size_t)(jn + r) * NF + c4];
            }
        }
        float accC[2][4] = {}, accQ[2][4] = {};
        #pragma unroll
        for (int s = 0; s < 10; s++) {
            int kc = s * 8;
            unsigned bf[2][2];
            ldsm_x4(bf[0][0], bf[0][1], bf[1][0], bf[1][1],
                    KsBase + ((wn * 16 + b_nr) * KPITCH + kc + b_koff) * 4);
            #pragma unroll
            for (int nt = 0; nt < 2; nt++) {
                if (s < 8)
                    mma_tf32(accC[nt][0], accC[nt][1], accC[nt][2], accC[nt][3],
                             afr[s][0], afr[s][1], afr[s][2], afr[s][3],
                             bf[nt][0], bf[nt][1]);
                else
                    mma_tf32(accQ[nt][0], accQ[nt][1], accQ[nt][2], accQ[nt][3],
                             afr[s][0], afr[s][1], afr[s][2], afr[s][3],
                             bf[nt][0], bf[nt][1]);
            }
        }
        #pragma unroll
        for (int nt = 0; nt < 2; nt++) {
            int r  = wm * 16 + g;
            int cl = wn * 16 + nt * 8 + tg * 2;
            #pragma unroll
            for (int hrow = 0; hrow < 2; hrow++) {
                int rr = r + hrow * 8;
                int base = rr + 767 - j0 - cl;
                float e0 = entT[base];
                float e1 = entT[base - 1];
                float2 st;
                st.x = accC[nt][hrow * 2]     + e0 * accQ[nt][hrow * 2];
                st.y = accC[nt][hrow * 2 + 1] + e1 * accQ[nt][hrow * 2 + 1];
                *(float2*)&P[rr * PROW + j0 + cl] = st;
            }
        }
        __syncthreads();
        if (jc + 1 < 12) {
            #pragma unroll
            for (int it = 0; it < 2; it++) {
                int fid = tid + ATHREADS * it;
                int r = fid >> 4, c4 = (fid & 15) * 4;
                *(uint4*)&Ks[r * KPITCH + c4] =
                    make_uint4(f2tf32(rc[it].x), f2tf32(rc[it].y),
                               f2tf32(rc[it].z), f2tf32(rc[it].w));
            }
            if (tid < 256) {
                int r = tid >> 2, c4 = (tid & 3) * 4;
                *(uint4*)&Ks[r * KPITCH + 64 + c4] =
                    make_uint4(f2tf32(rq.x), f2tf32(rq.y), f2tf32(rq.z), f2tf32(rq.w));
            }
        }
        __syncthreads();
    }

    // ---- phase 2: softmax + head-mean reduction into out2 (4 rows/warp) ----
    for (int rr = wid; rr < 64; rr += 16) {
        float4* row4 = (float4*)(P + rr * PROW);
        float4 v[6];
        float m = -1e30f;
        #pragma unroll
        for (int u = 0; u < 6; u++) {
            v[u] = row4[lane + u * 32];
            m = fmaxf(m, fmaxf(fmaxf(v[u].x, v[u].y), fmaxf(v[u].z, v[u].w)));
        }
        #pragma unroll
        for (int o = 16; o; o >>= 1) m = fmaxf(m, __shfl_xor_sync(0xffffffffu, m, o));
        float ssum = 0.f;
        #pragma unroll
        for (int u = 0; u < 6; u++) {
            v[u].x = __expf(v[u].x - m); v[u].y = __expf(v[u].y - m);
            v[u].z = __expf(v[u].z - m); v[u].w = __expf(v[u].w - m);
            ssum += (v[u].x + v[u].y) + (v[u].z + v[u].w);
        }
        #pragma unroll
        for (int o = 16; o; o >>= 1) ssum += __shfl_xor_sync(0xffffffffu, ssum, o);
        float inv = __frcp_rn(ssum);
        float* o2row = o2p + (size_t)(i0 + rr) * SS;
        #pragma unroll
        for (int u = 0; u < 6; u++) {
            float4 t;
            t.x = __uint_as_float(f2tf32(v[u].x * inv));
            t.y = __uint_as_float(f2tf32(v[u].y * inv));
            t.z = __uint_as_float(f2tf32(v[u].z * inv));
            t.w = __uint_as_float(f2tf32(v[u].w * inv));
            row4[lane + u * 32] = t;
            red_add_v4(o2row + (lane + u * 32) * 4,
                       t.x * (1.0f / HH), t.y * (1.0f / HH),
                       t.z * (1.0f / HH), t.w * (1.0f / HH));
        }
    }

    // ---- phase 3: AV via ldmatrix on P and double-buffered Vs --------------
    float acc[2][4] = {};
    float4 vreg[2];
    {
        #pragma unroll
        for (int it = 0; it < 2; it++) {
            int fid = tid + ATHREADS * it;
            int d = fid >> 4, c4 = (fid & 15) * 4;
            vreg[it] = *(const float4*)&Vtp[(size_t)d * SS + c4];
        }
        __syncthreads();
        #pragma unroll
        for (int it = 0; it < 2; it++) {
            int fid = tid + ATHREADS * it;
            int d = fid >> 4, c4 = (fid & 15) * 4;
            *(uint4*)&Vs0[d * VPITCH + c4] =
                make_uint4(f2tf32(vreg[it].x), f2tf32(vreg[it].y),
                           f2tf32(vreg[it].z), f2tf32(vreg[it].w));
        }
        __syncthreads();
    }
    for (int c = 0; c < 12; c++) {
        int k0 = c * 64;
        unsigned curB = (c & 1) ? VsBase1 : VsBase0;
        unsigned* nxt = (c & 1) ? Vs0 : Vs1;
        if (c + 1 < 12) {
            int kn = k0 + 64;
            #pragma unroll
            for (int it = 0; it < 2; it++) {
                int fid = tid + ATHREADS * it;
                int d = fid >> 4, c4 = (fid & 15) * 4;
                vreg[it] = *(const float4*)&Vtp[(size_t)d * SS + kn + c4];
            }
        }
        #pragma unroll
        for (int s = 0; s < 8; s++) {
            int kc = s * 8;
            unsigned af[4];
            ldsm_x4(af[0], af[1], af[2], af[3],
                    PBase + ((wm * 16 + a_row) * PROW + k0 + kc + a_koff) * 4);
            unsigned bf[2][2];
            ldsm_x4(bf[0][0], bf[0][1], bf[1][0], bf[1][1],
                    curB + ((wn * 16 + b_nr) * VPITCH + kc + b_koff) * 4);
            #pragma unroll
            for (int nt = 0; nt < 2; nt++)
                mma_tf32(acc[nt][0], acc[nt][1], acc[nt][2], acc[nt][3],
                         af[0], af[1], af[2], af[3], bf[nt][0], bf[nt][1]);
        }
        if (c + 1 < 12) {
            #pragma unroll
            for (int it = 0; it < 2; it++) {
                int fid = tid + ATHREADS * it;
                int d = fid >> 4, c4 = (fid & 15) * 4;
                *(uint4*)&nxt[d * VPITCH + c4] =
                    make_uint4(f2tf32(vreg[it].x), f2tf32(vreg[it].y),
                               f2tf32(vreg[it].z), f2tf32(vreg[it].w));
            }
        }
        __syncthreads();
    }
    #pragma unroll
    for (int nt = 0; nt < 2; nt++) {
        int r = wm * 16 + g;
        int d0 = wn * 16 + nt * 8 + tg * 2;
        #pragma unroll
        for (int hrow = 0; hrow < 2; hrow++) {
            int s_ = i0 + r + hrow * 8;
            *(float2*)&g_att[(size_t)(b * SS + s_) * DDIM + h * HDIM + d0] =
                make_float2(acc[nt][hrow * 2], acc[nt][hrow * 2 + 1]);
        }
    }
}

// ---------------- launch -----------------------------------------------------
extern "C" void kernel_launch(void* const* d_in, const int* in_sizes, int n_in,
                              void* d_out, int out_size) {
    const float* query = (const float*)d_in[0];
    const float* key   = (const float*)d_in[1];
    const float* value = (const float*)d_in[2];
    const float* Wq = (const float*)d_in[3];
    const float* bq = (const float*)d_in[4];
    const float* Wk = (const float*)d_in[5];
    const float* bk = (const float*)d_in[6];
    const float* Wv = (const float*)d_in[7];
    const float* bv = (const float*)d_in[8];
    const float* Wo = (const float*)d_in[9];
    const float* bo = (const float*)d_in[10];
    const float* qmapW = (const float*)d_in[11];
    const float* qmapb = (const float*)d_in[12];
    const float* qw    = (const float*)d_in[13];
    const float* ph    = (const float*)d_in[14];
    const float* es    = (const float*)d_in[15];

    float* out  = (float*)d_out;
    float* out2 = out + (size_t)MM * DDIM;

    {
        int n = BB * SS * SS / 4;
        zero_out2_kernel<<<(n + 255) / 256, 256>>>(out2);
    }
    proj_kernel<<<dim3(DDIM / 128, MM / 128, 3), 256>>>(query, key, value,
                                                        Wq, bq, Wk, bk, Wv, bv);
    {
        int nrows = 2 * BHn * SS;
        qfeat_kernel<<<nrows / 8, 256>>>(qmapW, qmapb, qw, ph, es);
    }
    {
        size_t smem = (size_t)64 * PROW * 4 + (size_t)2 * 64 * VPITCH * 4; // 232448
        cudaFuncSetAttribute(attn_kernel,
                             cudaFuncAttributeMaxDynamicSharedMemorySize, (int)smem);
        attn_kernel<<<dim3(SS / 64, BHn), ATHREADS, smem>>>(es, out2);
    }
    outproj_kernel<<<dim3(DDIM / 128, MM / 128), 256>>>(Wo, bo, out);
}